// round 1
// baseline (speedup 1.0000x reference)
#include <cuda_runtime.h>
#include <cstdint>

// Problem constants (fixed by the reference: B=1, T=2048, E=1024, H=16, D=64)
#define TT 2048
#define EE 1024
#define HH 16
#define DD 64
#define HD 1024   // H*D

// ---------------- scratch (device globals: allocation-free) ----------------
__device__ float g_q[TT * HD];
__device__ float g_k[TT * HD];
__device__ float g_v[TT * HD];
__device__ float g_rv[TT * HD];
__device__ float g_echo[TT * EE];
__device__ float g_eb[TT * EE];
__device__ float g_r[HH * TT];
__device__ float g_sc[TT];
__device__ float g_o1[TT * HD];
__device__ float g_o2[TT * HD];
__device__ float g_o3[TT * EE];
__device__ float g_comb[TT * HD];

// ---------------- GEMM: C(2048x1024) = A(2048x1024) @ B, TB? B^T : B -------
// TB=true : C[m,n] = sum_k A[m,k] * B[n,k]   (B row-major N x K)
// TB=false: C[m,n] = sum_k A[m,k] * B[k,n]   (B row-major K x N)
template<bool TB>
__global__ void __launch_bounds__(256, 2) gemm_k(const float* __restrict__ A,
                                                 const float* __restrict__ B,
                                                 float* __restrict__ C) {
    __shared__ float As[128][17];
    __shared__ float Bs[128][17];
    const int tid = threadIdx.x;
    const int tx = tid & 15;
    const int ty = tid >> 4;
    const int m0 = blockIdx.y * 128;
    const int n0 = blockIdx.x * 128;

    float acc[8][8];
#pragma unroll
    for (int i = 0; i < 8; i++)
#pragma unroll
        for (int j = 0; j < 8; j++) acc[i][j] = 0.f;

    for (int k0 = 0; k0 < 1024; k0 += 16) {
#pragma unroll
        for (int i = 0; i < 8; i++) {
            int idx = tid + i * 256;
            int m = idx >> 4, kk = idx & 15;
            As[m][kk] = A[(size_t)(m0 + m) * 1024 + k0 + kk];
        }
        if (TB) {
#pragma unroll
            for (int i = 0; i < 8; i++) {
                int idx = tid + i * 256;
                int n = idx >> 4, kk = idx & 15;
                Bs[n][kk] = B[(size_t)(n0 + n) * 1024 + k0 + kk];
            }
        } else {
#pragma unroll
            for (int i = 0; i < 8; i++) {
                int idx = tid + i * 256;
                int kk = idx >> 7, n = idx & 127;
                Bs[n][kk] = B[(size_t)(k0 + kk) * 1024 + n0 + n];
            }
        }
        __syncthreads();
#pragma unroll
        for (int kk = 0; kk < 16; kk++) {
            float a[8], b[8];
#pragma unroll
            for (int i = 0; i < 8; i++) a[i] = As[i * 16 + ty][kk];
#pragma unroll
            for (int j = 0; j < 8; j++) b[j] = Bs[j * 16 + tx][kk];
#pragma unroll
            for (int i = 0; i < 8; i++)
#pragma unroll
                for (int j = 0; j < 8; j++) acc[i][j] += a[i] * b[j];
        }
        __syncthreads();
    }
#pragma unroll
    for (int i = 0; i < 8; i++) {
        float* Cp = C + (size_t)(m0 + i * 16 + ty) * 1024 + n0;
#pragma unroll
        for (int j = 0; j < 8; j++) Cp[j * 16 + tx] = acc[i][j];
    }
}

// ---------------- r[h,t] = sum_e x[t,e] * wr[h,e,t] ------------------------
__global__ void kr(const float* __restrict__ x, const float* __restrict__ wr,
                   float* __restrict__ r) {
    const int h = blockIdx.y;
    const int t = blockIdx.x * 128 + threadIdx.x;
    const float* wp = wr + (size_t)h * EE * TT + t;  // stride TT over e, coalesced over t
    const float* xp = x + (size_t)t * EE;            // per-thread streaming (L1-friendly)
    float acc = 0.f;
#pragma unroll 8
    for (int e = 0; e < EE; e++) acc += xp[e] * wp[(size_t)e * TT];
    r[h * TT + t] = acc;
}

// ---------------- scores[t] = dot(x[t], echo_back[t]) / 32 -----------------
__global__ void kscores(const float* __restrict__ x, const float* __restrict__ eb,
                        float* __restrict__ sc) {
    const int t = blockIdx.x;
    const float* xp = x + (size_t)t * EE;
    const float* ep = eb + (size_t)t * EE;
    float a = 0.f;
    for (int e = threadIdx.x; e < EE; e += 256) a += xp[e] * ep[e];
#pragma unroll
    for (int o = 16; o > 0; o >>= 1) a += __shfl_xor_sync(0xffffffffu, a, o);
    __shared__ float red[8];
    if ((threadIdx.x & 31) == 0) red[threadIdx.x >> 5] = a;
    __syncthreads();
    if (threadIdx.x == 0) {
        float s = 0.f;
#pragma unroll
        for (int w = 0; w < 8; w++) s += red[w];
        sc[t] = s * (1.f / 32.f);
    }
}

// ---------------- branch 1: causal flash attention -------------------------
__global__ void __launch_bounds__(64) flash_qkv(const float* __restrict__ q,
                                                const float* __restrict__ k,
                                                const float* __restrict__ v,
                                                float* __restrict__ out) {
    __shared__ __align__(16) float Ks[64][68];
    __shared__ __align__(16) float Vs[64][68];
    const int h = blockIdx.y;
    const int m0 = blockIdx.x * 64;
    const int tid = threadIdx.x;
    const int qrow = m0 + tid;

    float qr[64];
    const float* qp = q + (size_t)qrow * HD + h * DD;
#pragma unroll
    for (int d = 0; d < 64; d++) qr[d] = qp[d] * 0.125f;

    float mi = -1e30f, li = 0.f;
    float acc[64];
#pragma unroll
    for (int d = 0; d < 64; d++) acc[d] = 0.f;

    for (int n0 = 0; n0 <= m0; n0 += 64) {
        __syncthreads();
        const float* kp = k + (size_t)n0 * HD + h * DD + tid;
        const float* vp = v + (size_t)n0 * HD + h * DD + tid;
#pragma unroll 4
        for (int j = 0; j < 64; j++) {
            Ks[j][tid] = kp[(size_t)j * HD];
            Vs[j][tid] = vp[(size_t)j * HD];
        }
        __syncthreads();
        int jmax = qrow - n0 + 1;
        if (jmax > 64) jmax = 64;
        for (int j = 0; j < jmax; j++) {
            const float4* Kr = (const float4*)Ks[j];
            float s = 0.f;
#pragma unroll
            for (int dd = 0; dd < 16; dd++) {
                float4 kv = Kr[dd];
                s += qr[dd * 4 + 0] * kv.x + qr[dd * 4 + 1] * kv.y +
                     qr[dd * 4 + 2] * kv.z + qr[dd * 4 + 3] * kv.w;
            }
            float mnew = fmaxf(mi, s);
            float corr = __expf(mi - mnew);
            float p = __expf(s - mnew);
            li = li * corr + p;
            mi = mnew;
            const float4* Vr = (const float4*)Vs[j];
#pragma unroll
            for (int dd = 0; dd < 16; dd++) {
                float4 vv = Vr[dd];
                acc[dd * 4 + 0] = acc[dd * 4 + 0] * corr + p * vv.x;
                acc[dd * 4 + 1] = acc[dd * 4 + 1] * corr + p * vv.y;
                acc[dd * 4 + 2] = acc[dd * 4 + 2] * corr + p * vv.z;
                acc[dd * 4 + 3] = acc[dd * 4 + 3] * corr + p * vv.w;
            }
        }
    }
    float inv = 1.f / li;
    float* op = out + (size_t)qrow * HD + h * DD;
#pragma unroll
    for (int d = 0; d < 64; d++) op[d] = acc[d] * inv;
}

// ---------------- branch 2: scores depend only on k (r[h,k]) ---------------
__global__ void __launch_bounds__(64) flash_rrp(const float* __restrict__ r,
                                                const float* __restrict__ rv,
                                                float* __restrict__ out) {
    __shared__ __align__(16) float Vs[64][68];
    __shared__ float rs[64];
    const int h = blockIdx.y;
    const int m0 = blockIdx.x * 64;
    const int tid = threadIdx.x;
    const int qrow = m0 + tid;

    float mi = -1e30f, li = 0.f;
    float acc[64];
#pragma unroll
    for (int d = 0; d < 64; d++) acc[d] = 0.f;

    for (int n0 = 0; n0 <= m0; n0 += 64) {
        __syncthreads();
        const float* vp = rv + (size_t)n0 * HD + h * DD + tid;
#pragma unroll 4
        for (int j = 0; j < 64; j++) Vs[j][tid] = vp[(size_t)j * HD];
        rs[tid] = r[h * TT + n0 + tid] * 0.125f;
        __syncthreads();
        int jmax = qrow - n0 + 1;
        if (jmax > 64) jmax = 64;
        for (int j = 0; j < jmax; j++) {
            float s = rs[j];
            float mnew = fmaxf(mi, s);
            float corr = __expf(mi - mnew);
            float p = __expf(s - mnew);
            li = li * corr + p;
            mi = mnew;
            const float4* Vr = (const float4*)Vs[j];
#pragma unroll
            for (int dd = 0; dd < 16; dd++) {
                float4 vv = Vr[dd];
                acc[dd * 4 + 0] = acc[dd * 4 + 0] * corr + p * vv.x;
                acc[dd * 4 + 1] = acc[dd * 4 + 1] * corr + p * vv.y;
                acc[dd * 4 + 2] = acc[dd * 4 + 2] * corr + p * vv.z;
                acc[dd * 4 + 3] = acc[dd * 4 + 3] * corr + p * vv.w;
            }
        }
    }
    float inv = 1.f / li;
    float* op = out + (size_t)qrow * HD + h * DD;
#pragma unroll
    for (int d = 0; d < 64; d++) op[d] = acc[d] * inv;
}

// ---------------- branch 3: s = scores[q]*scores[k], values = echo ---------
__global__ void __launch_bounds__(64) flash_jan(const float* __restrict__ sc,
                                                const float* __restrict__ echo,
                                                float* __restrict__ out) {
    __shared__ __align__(16) float Es[64][68];
    __shared__ float sk[64];
    const int e0 = blockIdx.y * 64;
    const int m0 = blockIdx.x * 64;
    const int tid = threadIdx.x;
    const int qrow = m0 + tid;
    const float sq = sc[qrow];

    float mi = -1e30f, li = 0.f;
    float acc[64];
#pragma unroll
    for (int d = 0; d < 64; d++) acc[d] = 0.f;

    for (int n0 = 0; n0 <= m0; n0 += 64) {
        __syncthreads();
        const float* ep = echo + (size_t)n0 * EE + e0 + tid;
#pragma unroll 4
        for (int j = 0; j < 64; j++) Es[j][tid] = ep[(size_t)j * EE];
        sk[tid] = sc[n0 + tid];
        __syncthreads();
        int jmax = qrow - n0 + 1;
        if (jmax > 64) jmax = 64;
        for (int j = 0; j < jmax; j++) {
            float s = sq * sk[j];
            float mnew = fmaxf(mi, s);
            float corr = __expf(mi - mnew);
            float p = __expf(s - mnew);
            li = li * corr + p;
            mi = mnew;
            const float4* Er = (const float4*)Es[j];
#pragma unroll
            for (int dd = 0; dd < 16; dd++) {
                float4 vv = Er[dd];
                acc[dd * 4 + 0] = acc[dd * 4 + 0] * corr + p * vv.x;
                acc[dd * 4 + 1] = acc[dd * 4 + 1] * corr + p * vv.y;
                acc[dd * 4 + 2] = acc[dd * 4 + 2] * corr + p * vv.z;
                acc[dd * 4 + 3] = acc[dd * 4 + 3] * corr + p * vv.w;
            }
        }
    }
    float inv = 1.f / li;
    float* op = out + (size_t)qrow * EE + e0;
#pragma unroll
    for (int d = 0; d < 64; d++) op[d] = acc[d] * inv;
}

// ---------------- gated combine (gate softmax inline) ----------------------
__global__ void kcombine(const float* __restrict__ o1, const float* __restrict__ o2,
                         const float* __restrict__ o3, const float* __restrict__ gate,
                         float* __restrict__ comb) {
    const int idx = blockIdx.x * 256 + threadIdx.x;
    const int c = idx & (HD - 1);
    const int h = c >> 6;
    float g0 = gate[h * 3 + 0], g1 = gate[h * 3 + 1], g2 = gate[h * 3 + 2];
    float mx = fmaxf(g0, fmaxf(g1, g2));
    float e0 = __expf(g0 - mx), e1 = __expf(g1 - mx), e2 = __expf(g2 - mx);
    float inv = 1.f / (e0 + e1 + e2);
    comb[idx] = (e0 * o1[idx] + e1 * o2[idx] + e2 * o3[idx]) * inv;
}

// ---------------- launch ----------------------------------------------------
extern "C" void kernel_launch(void* const* d_in, const int* in_sizes, int n_in,
                              void* d_out, int out_size) {
    const float* x    = (const float*)d_in[0];
    const float* wq   = (const float*)d_in[1];
    const float* wk   = (const float*)d_in[2];
    const float* wv   = (const float*)d_in[3];
    const float* wr   = (const float*)d_in[4];
    const float* wvr  = (const float*)d_in[5];
    const float* wj   = (const float*)d_in[6];
    const float* gate = (const float*)d_in[7];
    const float* wo   = (const float*)d_in[8];
    float* out = (float*)d_out;

    float *q, *k, *v, *rv, *echo, *eb, *r, *sc, *o1, *o2, *o3, *comb;
    cudaGetSymbolAddress((void**)&q, g_q);
    cudaGetSymbolAddress((void**)&k, g_k);
    cudaGetSymbolAddress((void**)&v, g_v);
    cudaGetSymbolAddress((void**)&rv, g_rv);
    cudaGetSymbolAddress((void**)&echo, g_echo);
    cudaGetSymbolAddress((void**)&eb, g_eb);
    cudaGetSymbolAddress((void**)&r, g_r);
    cudaGetSymbolAddress((void**)&sc, g_sc);
    cudaGetSymbolAddress((void**)&o1, g_o1);
    cudaGetSymbolAddress((void**)&o2, g_o2);
    cudaGetSymbolAddress((void**)&o3, g_o3);
    cudaGetSymbolAddress((void**)&comb, g_comb);

    dim3 ggrid(8, 16);      // N/128, M/128
    dim3 fgrid(32, 16);     // T/64,  H (or E/64 for jan)

    // projections (C = x @ W^T)
    gemm_k<true><<<ggrid, 256>>>(x, wq, q);
    gemm_k<true><<<ggrid, 256>>>(x, wk, k);
    gemm_k<true><<<ggrid, 256>>>(x, wv, v);
    gemm_k<true><<<ggrid, 256>>>(x, wvr, rv);
    gemm_k<true><<<ggrid, 256>>>(x, wj, echo);

    // echo_back = echo @ wj
    gemm_k<false><<<ggrid, 256>>>(echo, wj, eb);

    // scalar scores
    kscores<<<TT, 256>>>(x, eb, sc);
    kr<<<dim3(16, 16), 128>>>(x, wr, r);

    // three attention branches
    flash_qkv<<<fgrid, 64>>>(q, k, v, o1);
    flash_rrp<<<fgrid, 64>>>(r, rv, o2);
    flash_jan<<<fgrid, 64>>>(sc, echo, o3);

    // gated combine + output projection
    kcombine<<<(TT * HD) / 256, 256>>>(o1, o2, o3, gate, comb);
    gemm_k<true><<<ggrid, 256>>>(comb, wo, out);
}

// round 3
// speedup vs baseline: 2.0640x; 2.0640x over previous
#include <cuda_runtime.h>
#include <cstdint>

#define TT 2048
#define EE 1024
#define HH 16
#define DD 64
#define HD 1024

#define LOG2E 1.4426950408889634f

// ---------------- scratch ----------------
__device__ float g_q[TT * HD];
__device__ float g_k[TT * HD];
__device__ float g_v[TT * HD];
__device__ float g_rv[TT * HD];
__device__ float g_echo[TT * EE];
__device__ float g_eb[TT * EE];
__device__ float g_r[HH * TT];
__device__ float g_sc[TT];
__device__ float g_o1[TT * HD];
__device__ float g_o2[TT * HD];
__device__ float g_o3[TT * EE];
__device__ float g_comb[TT * HD];
__device__ float g_P[TT * TT];   // jan probabilities (16MB)

// =====================================================================
// GEMM v2: C(Mx1024) = A(MxK) @ (TB ? B^T : B).  128x128 tile, 8x8 micro,
// k-major smem + float4 LDS, double-buffered, 1 sync/chunk.
// CAUSAL: A[m][k]==0 for k>m  ->  loop k only to m0+128.
// =====================================================================
template<bool TB, bool CAUSAL>
__global__ void __launch_bounds__(256, 2) gemm2(const float* __restrict__ A,
                                                const float* __restrict__ B,
                                                float* __restrict__ C, int K) {
    __shared__ float As[2][16][132];
    __shared__ float Bs[2][16][132];
    const int tid = threadIdx.x;
    const int tx = tid & 15, ty = tid >> 4;
    const int m0 = blockIdx.y * 128, n0 = blockIdx.x * 128;
    const int kend = CAUSAL ? (m0 + 128 < K ? m0 + 128 : K) : K;
    const int nchunk = kend >> 4;

    // A loader: thread covers (m=tid>>1, k4 = tid&1 and tid&1+2)
    const int am = tid >> 1;
    const int ak = (tid & 1) * 4;            // word offset; second at ak+8
    const float* Ab = A + (size_t)(m0 + am) * K;

    // B loaders
    const int bn  = tid >> 1;                 // TB=true
    const int bk  = (tid & 1) * 4;
    const float* Bb_t = B + (size_t)(n0 + bn) * K;
    const int bkk = tid >> 5;                 // TB=false
    const int bng = tid & 31;
    const float* Bb_f = B + (size_t)bkk * 1024 + n0 + bng * 4;

    float4 pa0, pa1, pb0, pb1;

    // prologue: chunk 0
    pa0 = *(const float4*)(Ab + ak);
    pa1 = *(const float4*)(Ab + ak + 8);
    if (TB) {
        pb0 = *(const float4*)(Bb_t + bk);
        pb1 = *(const float4*)(Bb_t + bk + 8);
    } else {
        pb0 = *(const float4*)(Bb_f);
        pb1 = *(const float4*)(Bb_f + (size_t)8 * 1024);
    }
    {
        float* as = &As[0][0][0];
        as[(ak + 0) * 132 + am] = pa0.x; as[(ak + 1) * 132 + am] = pa0.y;
        as[(ak + 2) * 132 + am] = pa0.z; as[(ak + 3) * 132 + am] = pa0.w;
        as[(ak + 8) * 132 + am] = pa1.x; as[(ak + 9) * 132 + am] = pa1.y;
        as[(ak + 10) * 132 + am] = pa1.z; as[(ak + 11) * 132 + am] = pa1.w;
        float* bs = &Bs[0][0][0];
        if (TB) {
            bs[(bk + 0) * 132 + bn] = pb0.x; bs[(bk + 1) * 132 + bn] = pb0.y;
            bs[(bk + 2) * 132 + bn] = pb0.z; bs[(bk + 3) * 132 + bn] = pb0.w;
            bs[(bk + 8) * 132 + bn] = pb1.x; bs[(bk + 9) * 132 + bn] = pb1.y;
            bs[(bk + 10) * 132 + bn] = pb1.z; bs[(bk + 11) * 132 + bn] = pb1.w;
        } else {
            *(float4*)(bs + bkk * 132 + bng * 4) = pb0;
            *(float4*)(bs + (bkk + 8) * 132 + bng * 4) = pb1;
        }
    }
    __syncthreads();

    float acc[8][8];
#pragma unroll
    for (int i = 0; i < 8; i++)
#pragma unroll
        for (int j = 0; j < 8; j++) acc[i][j] = 0.f;

    for (int c = 0; c < nchunk; c++) {
        const int buf = c & 1;
        const bool more = (c + 1 < nchunk);
        if (more) {
            const int k0 = (c + 1) * 16;
            pa0 = *(const float4*)(Ab + k0 + ak);
            pa1 = *(const float4*)(Ab + k0 + ak + 8);
            if (TB) {
                pb0 = *(const float4*)(Bb_t + k0 + bk);
                pb1 = *(const float4*)(Bb_t + k0 + bk + 8);
            } else {
                pb0 = *(const float4*)(Bb_f + (size_t)k0 * 1024);
                pb1 = *(const float4*)(Bb_f + (size_t)(k0 + 8) * 1024);
            }
        }
#pragma unroll
        for (int kk = 0; kk < 16; kk++) {
            float4 a0 = *(const float4*)&As[buf][kk][ty * 8];
            float4 a1 = *(const float4*)&As[buf][kk][ty * 8 + 4];
            float4 b0 = *(const float4*)&Bs[buf][kk][tx * 8];
            float4 b1 = *(const float4*)&Bs[buf][kk][tx * 8 + 4];
            float av[8] = {a0.x, a0.y, a0.z, a0.w, a1.x, a1.y, a1.z, a1.w};
            float bv[8] = {b0.x, b0.y, b0.z, b0.w, b1.x, b1.y, b1.z, b1.w};
#pragma unroll
            for (int i = 0; i < 8; i++)
#pragma unroll
                for (int j = 0; j < 8; j++) acc[i][j] += av[i] * bv[j];
        }
        if (more) {
            const int nb = buf ^ 1;
            float* as = &As[nb][0][0];
            as[(ak + 0) * 132 + am] = pa0.x; as[(ak + 1) * 132 + am] = pa0.y;
            as[(ak + 2) * 132 + am] = pa0.z; as[(ak + 3) * 132 + am] = pa0.w;
            as[(ak + 8) * 132 + am] = pa1.x; as[(ak + 9) * 132 + am] = pa1.y;
            as[(ak + 10) * 132 + am] = pa1.z; as[(ak + 11) * 132 + am] = pa1.w;
            float* bs = &Bs[nb][0][0];
            if (TB) {
                bs[(bk + 0) * 132 + bn] = pb0.x; bs[(bk + 1) * 132 + bn] = pb0.y;
                bs[(bk + 2) * 132 + bn] = pb0.z; bs[(bk + 3) * 132 + bn] = pb0.w;
                bs[(bk + 8) * 132 + bn] = pb1.x; bs[(bk + 9) * 132 + bn] = pb1.y;
                bs[(bk + 10) * 132 + bn] = pb1.z; bs[(bk + 11) * 132 + bn] = pb1.w;
            } else {
                *(float4*)(bs + bkk * 132 + bng * 4) = pb0;
                *(float4*)(bs + (bkk + 8) * 132 + bng * 4) = pb1;
            }
        }
        __syncthreads();
    }

#pragma unroll
    for (int i = 0; i < 8; i++) {
        float* Cp = C + (size_t)(m0 + ty * 8 + i) * 1024 + n0 + tx * 8;
        *(float4*)Cp = make_float4(acc[i][0], acc[i][1], acc[i][2], acc[i][3]);
        *(float4*)(Cp + 4) = make_float4(acc[i][4], acc[i][5], acc[i][6], acc[i][7]);
    }
}

// =====================================================================
// branch 1: tiled causal flash attention. 64 q-rows x 64 k per tile,
// 256 threads, micro 4x4, exp2-domain (scale*log2e folded into Q).
// =====================================================================
__global__ void __launch_bounds__(256) flash_qkv2(const float* __restrict__ q,
                                                  const float* __restrict__ k,
                                                  const float* __restrict__ v,
                                                  float* __restrict__ out) {
    __shared__ float Qs[64][64];   // [d][r]
    __shared__ float KPs[64][64];  // K phase: [d][j]; P phase: [r][j]
    __shared__ float Vs[64][64];   // [j][d]
    const int h = blockIdx.y;
    const int m0 = blockIdx.x * 64;
    const int tid = threadIdx.x;
    const int tx = tid & 15, ty = tid >> 4;

    // load Q tile (d-major), fold scale*log2e
    const float QSCALE = 0.125f * LOG2E;
#pragma unroll
    for (int it = 0; it < 4; it++) {
        int idx = tid + it * 256;
        int r = idx >> 4, dg = idx & 15;
        float4 qv = *(const float4*)(q + (size_t)(m0 + r) * HD + h * DD + dg * 4);
        Qs[dg * 4 + 0][r] = qv.x * QSCALE;
        Qs[dg * 4 + 1][r] = qv.y * QSCALE;
        Qs[dg * 4 + 2][r] = qv.z * QSCALE;
        Qs[dg * 4 + 3][r] = qv.w * QSCALE;
    }

    float m_i[4], l_i[4], acc[4][4];
#pragma unroll
    for (int i = 0; i < 4; i++) {
        m_i[i] = -1e30f; l_i[i] = 0.f;
#pragma unroll
        for (int j = 0; j < 4; j++) acc[i][j] = 0.f;
    }

    for (int n0 = 0; n0 <= m0; n0 += 64) {
        __syncthreads();   // previous PV done
        // load K (d-major) and V (row-major)
#pragma unroll
        for (int it = 0; it < 4; it++) {
            int idx = tid + it * 256;
            int j = idx >> 4, dg = idx & 15;
            float4 kv = *(const float4*)(k + (size_t)(n0 + j) * HD + h * DD + dg * 4);
            KPs[dg * 4 + 0][j] = kv.x;
            KPs[dg * 4 + 1][j] = kv.y;
            KPs[dg * 4 + 2][j] = kv.z;
            KPs[dg * 4 + 3][j] = kv.w;
            float4 vv = *(const float4*)(v + (size_t)(n0 + j) * HD + h * DD + dg * 4);
            *(float4*)&Vs[j][dg * 4] = vv;
        }
        __syncthreads();

        // S = Q K^T (in exp2 domain units)
        float s[4][4];
#pragma unroll
        for (int i = 0; i < 4; i++)
#pragma unroll
            for (int j = 0; j < 4; j++) s[i][j] = 0.f;
        for (int d = 0; d < 64; d++) {
            float4 a = *(const float4*)&Qs[d][ty * 4];
            float4 b = *(const float4*)&KPs[d][tx * 4];
            float av[4] = {a.x, a.y, a.z, a.w};
            float bv[4] = {b.x, b.y, b.z, b.w};
#pragma unroll
            for (int i = 0; i < 4; i++)
#pragma unroll
                for (int j = 0; j < 4; j++) s[i][j] += av[i] * bv[j];
        }
        // causal mask on diagonal tile
        if (n0 == m0) {
#pragma unroll
            for (int i = 0; i < 4; i++)
#pragma unroll
                for (int j = 0; j < 4; j++)
                    if (tx * 4 + j > ty * 4 + i) s[i][j] = -1e30f;
        }
        // online softmax
        float p[4][4];
#pragma unroll
        for (int i = 0; i < 4; i++) {
            float rm = fmaxf(fmaxf(s[i][0], s[i][1]), fmaxf(s[i][2], s[i][3]));
#pragma unroll
            for (int o = 1; o < 16; o <<= 1)
                rm = fmaxf(rm, __shfl_xor_sync(0xffffffffu, rm, o));
            float mnew = fmaxf(m_i[i], rm);
            float corr = exp2f(m_i[i] - mnew);
            float rs = 0.f;
#pragma unroll
            for (int j = 0; j < 4; j++) { p[i][j] = exp2f(s[i][j] - mnew); rs += p[i][j]; }
#pragma unroll
            for (int o = 1; o < 16; o <<= 1)
                rs += __shfl_xor_sync(0xffffffffu, rs, o);
            l_i[i] = l_i[i] * corr + rs;
            m_i[i] = mnew;
#pragma unroll
            for (int j = 0; j < 4; j++) acc[i][j] *= corr;
        }
        __syncthreads();   // done reading K
        // store P into KPs as [r][j]
#pragma unroll
        for (int i = 0; i < 4; i++)
            *(float4*)&KPs[ty * 4 + i][tx * 4] = make_float4(p[i][0], p[i][1], p[i][2], p[i][3]);
        __syncthreads();
        // O += P V
        for (int j = 0; j < 64; j++) {
            float4 vv = *(const float4*)&Vs[j][tx * 4];
            float pv[4];
#pragma unroll
            for (int i = 0; i < 4; i++) pv[i] = KPs[ty * 4 + i][j];
#pragma unroll
            for (int i = 0; i < 4; i++) {
                acc[i][0] += pv[i] * vv.x;
                acc[i][1] += pv[i] * vv.y;
                acc[i][2] += pv[i] * vv.z;
                acc[i][3] += pv[i] * vv.w;
            }
        }
    }
#pragma unroll
    for (int i = 0; i < 4; i++) {
        float inv = 1.f / l_i[i];
        float* op = out + (size_t)(m0 + ty * 4 + i) * HD + h * DD + tx * 4;
        *(float4*)op = make_float4(acc[i][0] * inv, acc[i][1] * inv,
                                   acc[i][2] * inv, acc[i][3] * inv);
    }
}

// =====================================================================
// branch 2: prefix-scan (softmax weights depend only on k)
// =====================================================================
__global__ void __launch_bounds__(256) krrp(const float* __restrict__ r,
                                            const float* __restrict__ rv,
                                            float* __restrict__ out) {
    __shared__ float w[2048];
    __shared__ float rl[2048];
    __shared__ float red[256];
    const int h = blockIdx.x, tid = threadIdx.x;
    const float C = 0.125f * LOG2E;

    float vloc[8];
    float lm = -1e30f;
#pragma unroll
    for (int i = 0; i < 8; i++) {
        float vv = r[h * 2048 + tid * 8 + i] * C;
        vloc[i] = vv;
        lm = fmaxf(lm, vv);
    }
    red[tid] = lm; __syncthreads();
    for (int s = 128; s; s >>= 1) {
        if (tid < s) red[tid] = fmaxf(red[tid], red[tid + s]);
        __syncthreads();
    }
    float M = red[0];
    __syncthreads();

    float run = 0.f, pre[8];
#pragma unroll
    for (int i = 0; i < 8; i++) {
        float e = exp2f(vloc[i] - M);
        w[tid * 8 + i] = e;
        run += e;
        pre[i] = run;
    }
    red[tid] = run; __syncthreads();
    // Hillis-Steele inclusive scan over 256 partials
    for (int s = 1; s < 256; s <<= 1) {
        float t = (tid >= s) ? red[tid - s] : 0.f;
        __syncthreads();
        red[tid] += t;
        __syncthreads();
    }
    float excl = red[tid] - run;
#pragma unroll
    for (int i = 0; i < 8; i++) rl[tid * 8 + i] = 1.f / (excl + pre[i]);
    __syncthreads();

    if (tid < 64) {
        float acc = 0.f;
        const float* rp = rv + h * 64 + tid;
        float* op = out + h * 64 + tid;
#pragma unroll 4
        for (int t = 0; t < 2048; t++) {
            acc += w[t] * rp[(size_t)t * 1024];
            op[(size_t)t * 1024] = acc * rl[t];
        }
    }
}

// =====================================================================
// branch 3: probability rows (one block per q), then causal GEMM P@echo
// =====================================================================
__global__ void __launch_bounds__(256) kjp(const float* __restrict__ sc,
                                           float* __restrict__ P) {
    __shared__ float sk[2048];
    __shared__ float se[2048];
    __shared__ float red[256];
    const int qq = blockIdx.x, tid = threadIdx.x;
    for (int t = tid; t < 2048; t += 256) sk[t] = sc[t];
    __syncthreads();
    const float sq = sk[qq] * LOG2E;
    float lm = -1e30f;
    for (int t = tid; t <= qq; t += 256) lm = fmaxf(lm, sq * sk[t]);
    red[tid] = lm; __syncthreads();
    for (int s = 128; s; s >>= 1) {
        if (tid < s) red[tid] = fmaxf(red[tid], red[tid + s]);
        __syncthreads();
    }
    float M = red[0];
    __syncthreads();
    float ls = 0.f;
    for (int t = tid; t <= qq; t += 256) {
        float e = exp2f(sq * sk[t] - M);
        se[t] = e;
        ls += e;
    }
    red[tid] = ls; __syncthreads();
    for (int s = 128; s; s >>= 1) {
        if (tid < s) red[tid] += red[tid + s];
        __syncthreads();
    }
    const float rinv = 1.f / red[0];
    float* Prow = P + (size_t)qq * 2048;
    for (int t = tid; t < 2048; t += 256)
        Prow[t] = (t <= qq) ? se[t] * rinv : 0.f;
}

// ---------------- r[h,t] = sum_e x[t,e]*wr[h,e,t] --------------------
__global__ void kr(const float* __restrict__ x, const float* __restrict__ wr,
                   float* __restrict__ r) {
    const int h = blockIdx.y;
    const int t = blockIdx.x * 128 + threadIdx.x;
    const float* wp = wr + (size_t)h * EE * TT + t;
    const float* xp = x + (size_t)t * EE;
    float acc = 0.f;
#pragma unroll 8
    for (int e = 0; e < EE; e++) acc += xp[e] * wp[(size_t)e * TT];
    r[h * TT + t] = acc;
}

// ---------------- scores[t] = dot(x[t], eb[t]) / 32 ------------------
__global__ void kscores(const float* __restrict__ x, const float* __restrict__ eb,
                        float* __restrict__ sc) {
    const int t = blockIdx.x;
    const float* xp = x + (size_t)t * EE;
    const float* ep = eb + (size_t)t * EE;
    float a = 0.f;
    for (int e = threadIdx.x; e < EE; e += 256) a += xp[e] * ep[e];
#pragma unroll
    for (int o = 16; o > 0; o >>= 1) a += __shfl_xor_sync(0xffffffffu, a, o);
    __shared__ float red[8];
    if ((threadIdx.x & 31) == 0) red[threadIdx.x >> 5] = a;
    __syncthreads();
    if (threadIdx.x == 0) {
        float s = 0.f;
#pragma unroll
        for (int w = 0; w < 8; w++) s += red[w];
        sc[t] = s * (1.f / 32.f);
    }
}

// ---------------- gated combine --------------------------------------
__global__ void kcombine(const float* __restrict__ o1, const float* __restrict__ o2,
                         const float* __restrict__ o3, const float* __restrict__ gate,
                         float* __restrict__ comb) {
    const int idx = blockIdx.x * 256 + threadIdx.x;
    const int c = idx & (HD - 1);
    const int h = c >> 6;
    float g0 = gate[h * 3 + 0], g1 = gate[h * 3 + 1], g2 = gate[h * 3 + 2];
    float mx = fmaxf(g0, fmaxf(g1, g2));
    float e0 = __expf(g0 - mx), e1 = __expf(g1 - mx), e2 = __expf(g2 - mx);
    float inv = 1.f / (e0 + e1 + e2);
    comb[idx] = (e0 * o1[idx] + e1 * o2[idx] + e2 * o3[idx]) * inv;
}

// ---------------- launch ----------------------------------------------
extern "C" void kernel_launch(void* const* d_in, const int* in_sizes, int n_in,
                              void* d_out, int out_size) {
    const float* x    = (const float*)d_in[0];
    const float* wq   = (const float*)d_in[1];
    const float* wk   = (const float*)d_in[2];
    const float* wv   = (const float*)d_in[3];
    const float* wr   = (const float*)d_in[4];
    const float* wvr  = (const float*)d_in[5];
    const float* wj   = (const float*)d_in[6];
    const float* gate = (const float*)d_in[7];
    const float* wo   = (const float*)d_in[8];
    float* out = (float*)d_out;

    float *q, *k, *v, *rv, *echo, *eb, *r, *sc, *o1, *o2, *o3, *comb, *P;
    cudaGetSymbolAddress((void**)&q, g_q);
    cudaGetSymbolAddress((void**)&k, g_k);
    cudaGetSymbolAddress((void**)&v, g_v);
    cudaGetSymbolAddress((void**)&rv, g_rv);
    cudaGetSymbolAddress((void**)&echo, g_echo);
    cudaGetSymbolAddress((void**)&eb, g_eb);
    cudaGetSymbolAddress((void**)&r, g_r);
    cudaGetSymbolAddress((void**)&sc, g_sc);
    cudaGetSymbolAddress((void**)&o1, g_o1);
    cudaGetSymbolAddress((void**)&o2, g_o2);
    cudaGetSymbolAddress((void**)&o3, g_o3);
    cudaGetSymbolAddress((void**)&comb, g_comb);
    cudaGetSymbolAddress((void**)&P, g_P);

    dim3 ggrid(8, 16);   // N/128, M/128

    gemm2<true, false><<<ggrid, 256>>>(x, wq, q, 1024);
    gemm2<true, false><<<ggrid, 256>>>(x, wk, k, 1024);
    gemm2<true, false><<<ggrid, 256>>>(x, wv, v, 1024);
    gemm2<true, false><<<ggrid, 256>>>(x, wvr, rv, 1024);
    gemm2<true, false><<<ggrid, 256>>>(x, wj, echo, 1024);
    gemm2<false, false><<<ggrid, 256>>>(echo, wj, eb, 1024);

    kscores<<<TT, 256>>>(x, eb, sc);
    kr<<<dim3(16, 16), 128>>>(x, wr, r);

    kjp<<<TT, 256>>>(sc, P);
    flash_qkv2<<<dim3(32, 16), 256>>>(q, k, v, o1);
    krrp<<<16, 256>>>(r, rv, o2);
    gemm2<false, true><<<ggrid, 256>>>(P, echo, o3, 2048);

    kcombine<<<(TT * HD) / 256, 256>>>(o1, o2, o3, gate, comb);
    gemm2<true, false><<<ggrid, 256>>>(comb, wo, out, 1024);
}

// round 5
// speedup vs baseline: 2.4800x; 1.2015x over previous
#include <cuda_runtime.h>
#include <cuda_bf16.h>
#include <cstdint>

#define TT 2048
#define EE 1024
#define HH 16
#define DD 64
#define HD 1024
#define LOG2E 1.4426950408889634f

// ---------------- fp32 scratch ----------------
__device__ __align__(16) float g_q[TT * HD];
__device__ __align__(16) float g_k[TT * HD];
__device__ __align__(16) float g_v[TT * HD];
__device__ __align__(16) float g_rv[TT * HD];
__device__ __align__(16) float g_echo[TT * EE];
__device__ __align__(16) float g_eb[TT * EE];
__device__ __align__(16) float g_r[HH * TT];
__device__ __align__(16) float g_sc[TT];
__device__ __align__(16) float g_o1[TT * HD];
__device__ __align__(16) float g_o2[TT * HD];
__device__ __align__(16) float g_o3[TT * EE];

// ---------------- bf16 triple-split scratch ----------------
__device__ __align__(16) __nv_bfloat16 g_x3[TT * 3072];
__device__ __align__(16) __nv_bfloat16 g_wq3[1024 * 3072];
__device__ __align__(16) __nv_bfloat16 g_wk3[1024 * 3072];
__device__ __align__(16) __nv_bfloat16 g_wv3[1024 * 3072];
__device__ __align__(16) __nv_bfloat16 g_wvr3[1024 * 3072];
__device__ __align__(16) __nv_bfloat16 g_wj3[1024 * 3072];
__device__ __align__(16) __nv_bfloat16 g_wo3[1024 * 3072];
__device__ __align__(16) __nv_bfloat16 g_wjT3[1024 * 3072];
__device__ __align__(16) __nv_bfloat16 g_echoA3[TT * 3072];
__device__ __align__(16) __nv_bfloat16 g_echoT3[1024 * 6144];
__device__ __align__(16) __nv_bfloat16 g_P3[TT * 6144];
__device__ __align__(16) __nv_bfloat16 g_comb3[TT * 3072];

// ============================ PTX helpers ============================
__device__ __forceinline__ uint32_t smem_u32(const void* p) {
    uint32_t a;
    asm("{ .reg .u64 t; cvta.to.shared.u64 t, %1; cvt.u32.u64 %0, t; }" : "=r"(a) : "l"(p));
    return a;
}
__device__ __forceinline__ void cp_async16(uint32_t s, const void* g) {
    asm volatile("cp.async.cg.shared.global [%0], [%1], 16;" :: "r"(s), "l"(g));
}
__device__ __forceinline__ void cp_commit() { asm volatile("cp.async.commit_group;"); }
template<int N> __device__ __forceinline__ void cp_wait() {
    asm volatile("cp.async.wait_group %0;" :: "n"(N) : "memory");
}
__device__ __forceinline__ void ldmx4(uint32_t& r0, uint32_t& r1, uint32_t& r2, uint32_t& r3,
                                      uint32_t addr) {
    asm volatile("ldmatrix.sync.aligned.m8n8.x4.shared.b16 {%0,%1,%2,%3}, [%4];"
                 : "=r"(r0), "=r"(r1), "=r"(r2), "=r"(r3) : "r"(addr));
}
__device__ __forceinline__ void mma_bf16(float* d, const uint32_t* a, const uint32_t* b) {
    asm volatile("mma.sync.aligned.m16n8k16.row.col.f32.bf16.bf16.f32 "
                 "{%0,%1,%2,%3}, {%4,%5,%6,%7}, {%8,%9}, {%0,%1,%2,%3};"
                 : "+f"(d[0]), "+f"(d[1]), "+f"(d[2]), "+f"(d[3])
                 : "r"(a[0]), "r"(a[1]), "r"(a[2]), "r"(a[3]), "r"(b[0]), "r"(b[1]));
}

// =====================================================================
// HMMA bf16 GEMM: C(Mx1024) = A3(MxK3) @ B3(1024xK3)^T, fp32 accum/out.
// Tile 128x128, BK=32, 4-stage cp.async pipeline, 8 warps (4M x 2N).
// Smem rows padded to 40 bf16 (80B): ldmatrix phases conflict-free.
// =====================================================================
#define HSTAGE_ELE 10240            // elements per stage (A 5120 + B 5120)
#define HMMA_SMEM (4 * HSTAGE_ELE * 2)

__global__ void __launch_bounds__(256, 2) hmma_gemm(const __nv_bfloat16* __restrict__ A,
                                                    const __nv_bfloat16* __restrict__ B,
                                                    float* __restrict__ C, int K3) {
    extern __shared__ __nv_bfloat16 sm[];
    const int tid = threadIdx.x;
    const int m0 = blockIdx.y * 128, n0 = blockIdx.x * 128;
    const int nchunk = K3 >> 5;
    const int warp = tid >> 5, lane = tid & 31;
    const int wm = warp & 3, wn = warp >> 2;      // warp tile: (wm*32) x (wn*64)

    const uint32_t smb = smem_u32(sm);

    auto load_stage = [&](int cc, int s) {
        const uint32_t ab = smb + s * (HSTAGE_ELE * 2);
        const uint32_t bb = ab + 10240;
        const int k0 = cc * 32;
#pragma unroll
        for (int i = 0; i < 2; i++) {
            int c = tid * 2 + i;               // 0..511
            int row = c >> 2, cg = c & 3;
            cp_async16(ab + row * 80 + cg * 16, A + (size_t)(m0 + row) * K3 + k0 + cg * 8);
            cp_async16(bb + row * 80 + cg * 16, B + (size_t)(n0 + row) * K3 + k0 + cg * 8);
        }
        cp_commit();
    };

    load_stage(0, 0);
    load_stage(1, 1);
    load_stage(2, 2);

    float acc[2][8][4];
#pragma unroll
    for (int i = 0; i < 2; i++)
#pragma unroll
        for (int j = 0; j < 8; j++)
#pragma unroll
            for (int t = 0; t < 4; t++) acc[i][j][t] = 0.f;

    const int lrow = lane & 15;
    const int lcol = (lane >> 4) << 3;

    for (int c = 0; c < nchunk; c++) {
        cp_wait<2>();
        __syncthreads();
        if (c + 3 < nchunk) load_stage(c + 3, (c + 3) & 3);

        const uint32_t ab = smb + (c & 3) * (HSTAGE_ELE * 2);
        const uint32_t bb = ab + 10240;
#pragma unroll
        for (int ks = 0; ks < 2; ks++) {
            const uint32_t coff = (ks * 16 + lcol) * 2;
            uint32_t a[2][4], b[8][2];
#pragma unroll
            for (int mt = 0; mt < 2; mt++)
                ldmx4(a[mt][0], a[mt][1], a[mt][2], a[mt][3],
                      ab + (uint32_t)(wm * 32 + mt * 16 + lrow) * 80 + coff);
#pragma unroll
            for (int bp = 0; bp < 4; bp++) {
                uint32_t r0, r1, r2, r3;
                ldmx4(r0, r1, r2, r3,
                      bb + (uint32_t)(wn * 64 + bp * 16 + lrow) * 80 + coff);
                b[bp * 2][0] = r0; b[bp * 2][1] = r2;
                b[bp * 2 + 1][0] = r1; b[bp * 2 + 1][1] = r3;
            }
#pragma unroll
            for (int mt = 0; mt < 2; mt++)
#pragma unroll
                for (int nt = 0; nt < 8; nt++) mma_bf16(acc[mt][nt], a[mt], b[nt]);
        }
        __syncthreads();
    }

    // epilogue
    const int erow = lane >> 2;
    const int ecol = (lane & 3) * 2;
#pragma unroll
    for (int mt = 0; mt < 2; mt++) {
        const int r0 = m0 + wm * 32 + mt * 16 + erow;
#pragma unroll
        for (int nt = 0; nt < 8; nt++) {
            const int cc = n0 + wn * 64 + nt * 8 + ecol;
            *(float2*)&C[(size_t)r0 * 1024 + cc] = make_float2(acc[mt][nt][0], acc[mt][nt][1]);
            *(float2*)&C[(size_t)(r0 + 8) * 1024 + cc] = make_float2(acc[mt][nt][2], acc[mt][nt][3]);
        }
    }
}

// =====================================================================
// fp32 -> bf16 triple split.  APAT: [hi,lo,hi] (A operand); else [hi,hi,lo]
// =====================================================================
template<bool APAT>
__global__ void conv3(const float* __restrict__ S, __nv_bfloat16* __restrict__ D, int K) {
    const int idx = blockIdx.x * 256 + threadIdx.x;
    const int m = idx / K, k = idx - m * K;
    float x = S[idx];
    __nv_bfloat16 hi = __float2bfloat16(x);
    __nv_bfloat16 lo = __float2bfloat16(x - __bfloat162float(hi));
    const size_t ro = (size_t)m * 3 * K;
    D[ro + k] = hi;
    D[ro + K + k] = APAT ? lo : hi;
    D[ro + 2 * K + k] = APAT ? hi : lo;
}

// transpose + split (B pattern): S is KxN fp32, D is N x 3K bf16
__global__ void conv3T(const float* __restrict__ S, __nv_bfloat16* __restrict__ D,
                       int K, int N) {
    __shared__ float t[32][33];
    const int k0 = blockIdx.x * 32, n0 = blockIdx.y * 32;
    const int tx = threadIdx.x & 31, ty = threadIdx.x >> 5;
    for (int i = ty; i < 32; i += 8) t[i][tx] = S[(size_t)(k0 + i) * N + n0 + tx];
    __syncthreads();
    const int K3 = 3 * K;
    for (int i = ty; i < 32; i += 8) {
        const int n = n0 + i, k = k0 + tx;
        float x = t[tx][i];
        __nv_bfloat16 hi = __float2bfloat16(x);
        __nv_bfloat16 lo = __float2bfloat16(x - __bfloat162float(hi));
        D[(size_t)n * K3 + k] = hi;
        D[(size_t)n * K3 + K + k] = hi;
        D[(size_t)n * K3 + 2 * K + k] = lo;
    }
}

// =====================================================================
// branch 1: tiled causal flash attention (fp32 SIMT)
// =====================================================================
__global__ void __launch_bounds__(256) flash_qkv2(const float* __restrict__ q,
                                                  const float* __restrict__ k,
                                                  const float* __restrict__ v,
                                                  float* __restrict__ out) {
    __shared__ float Qs[64][64];
    __shared__ float KPs[64][64];
    __shared__ float Vs[64][64];
    const int h = blockIdx.y;
    const int m0 = blockIdx.x * 64;
    const int tid = threadIdx.x;
    const int tx = tid & 15, ty = tid >> 4;

    const float QSCALE = 0.125f * LOG2E;
#pragma unroll
    for (int it = 0; it < 4; it++) {
        int idx = tid + it * 256;
        int r = idx >> 4, dg = idx & 15;
        float4 qv = *(const float4*)(q + (size_t)(m0 + r) * HD + h * DD + dg * 4);
        Qs[dg * 4 + 0][r] = qv.x * QSCALE;
        Qs[dg * 4 + 1][r] = qv.y * QSCALE;
        Qs[dg * 4 + 2][r] = qv.z * QSCALE;
        Qs[dg * 4 + 3][r] = qv.w * QSCALE;
    }
    float m_i[4], l_i[4], acc[4][4];
#pragma unroll
    for (int i = 0; i < 4; i++) {
        m_i[i] = -1e30f; l_i[i] = 0.f;
#pragma unroll
        for (int j = 0; j < 4; j++) acc[i][j] = 0.f;
    }
    for (int n0 = 0; n0 <= m0; n0 += 64) {
        __syncthreads();
#pragma unroll
        for (int it = 0; it < 4; it++) {
            int idx = tid + it * 256;
            int j = idx >> 4, dg = idx & 15;
            float4 kv = *(const float4*)(k + (size_t)(n0 + j) * HD + h * DD + dg * 4);
            KPs[dg * 4 + 0][j] = kv.x;
            KPs[dg * 4 + 1][j] = kv.y;
            KPs[dg * 4 + 2][j] = kv.z;
            KPs[dg * 4 + 3][j] = kv.w;
            float4 vv = *(const float4*)(v + (size_t)(n0 + j) * HD + h * DD + dg * 4);
            *(float4*)&Vs[j][dg * 4] = vv;
        }
        __syncthreads();
        float s[4][4];
#pragma unroll
        for (int i = 0; i < 4; i++)
#pragma unroll
            for (int j = 0; j < 4; j++) s[i][j] = 0.f;
        for (int d = 0; d < 64; d++) {
            float4 a = *(const float4*)&Qs[d][ty * 4];
            float4 b = *(const float4*)&KPs[d][tx * 4];
            float av[4] = {a.x, a.y, a.z, a.w};
            float bv[4] = {b.x, b.y, b.z, b.w};
#pragma unroll
            for (int i = 0; i < 4; i++)
#pragma unroll
                for (int j = 0; j < 4; j++) s[i][j] += av[i] * bv[j];
        }
        if (n0 == m0) {
#pragma unroll
            for (int i = 0; i < 4; i++)
#pragma unroll
                for (int j = 0; j < 4; j++)
                    if (tx * 4 + j > ty * 4 + i) s[i][j] = -1e30f;
        }
        float p[4][4];
#pragma unroll
        for (int i = 0; i < 4; i++) {
            float rm = fmaxf(fmaxf(s[i][0], s[i][1]), fmaxf(s[i][2], s[i][3]));
#pragma unroll
            for (int o = 1; o < 16; o <<= 1) rm = fmaxf(rm, __shfl_xor_sync(0xffffffffu, rm, o));
            float mnew = fmaxf(m_i[i], rm);
            float corr = exp2f(m_i[i] - mnew);
            float rs = 0.f;
#pragma unroll
            for (int j = 0; j < 4; j++) { p[i][j] = exp2f(s[i][j] - mnew); rs += p[i][j]; }
#pragma unroll
            for (int o = 1; o < 16; o <<= 1) rs += __shfl_xor_sync(0xffffffffu, rs, o);
            l_i[i] = l_i[i] * corr + rs;
            m_i[i] = mnew;
#pragma unroll
            for (int j = 0; j < 4; j++) acc[i][j] *= corr;
        }
        __syncthreads();
#pragma unroll
        for (int i = 0; i < 4; i++)
            *(float4*)&KPs[ty * 4 + i][tx * 4] = make_float4(p[i][0], p[i][1], p[i][2], p[i][3]);
        __syncthreads();
        for (int j = 0; j < 64; j++) {
            float4 vv = *(const float4*)&Vs[j][tx * 4];
            float pv[4];
#pragma unroll
            for (int i = 0; i < 4; i++) pv[i] = KPs[ty * 4 + i][j];
#pragma unroll
            for (int i = 0; i < 4; i++) {
                acc[i][0] += pv[i] * vv.x;
                acc[i][1] += pv[i] * vv.y;
                acc[i][2] += pv[i] * vv.z;
                acc[i][3] += pv[i] * vv.w;
            }
        }
    }
#pragma unroll
    for (int i = 0; i < 4; i++) {
        float inv = 1.f / l_i[i];
        float* op = out + (size_t)(m0 + ty * 4 + i) * HD + h * DD + tx * 4;
        *(float4*)op = make_float4(acc[i][0] * inv, acc[i][1] * inv, acc[i][2] * inv,
                                   acc[i][3] * inv);
    }
}

// ---------------- branch 2: prefix scan ------------------------------
__global__ void __launch_bounds__(256) krrp(const float* __restrict__ r,
                                            const float* __restrict__ rv,
                                            float* __restrict__ out) {
    __shared__ float w[2048];
    __shared__ float rl[2048];
    __shared__ float red[256];
    const int h = blockIdx.x, tid = threadIdx.x;
    const float Cc = 0.125f * LOG2E;
    float vloc[8], lm = -1e30f;
#pragma unroll
    for (int i = 0; i < 8; i++) {
        float vv = r[h * 2048 + tid * 8 + i] * Cc;
        vloc[i] = vv;
        lm = fmaxf(lm, vv);
    }
    red[tid] = lm; __syncthreads();
    for (int s = 128; s; s >>= 1) { if (tid < s) red[tid] = fmaxf(red[tid], red[tid + s]); __syncthreads(); }
    float M = red[0];
    __syncthreads();
    float run = 0.f, pre[8];
#pragma unroll
    for (int i = 0; i < 8; i++) {
        float e = exp2f(vloc[i] - M);
        w[tid * 8 + i] = e;
        run += e;
        pre[i] = run;
    }
    red[tid] = run; __syncthreads();
    for (int s = 1; s < 256; s <<= 1) {
        float t = (tid >= s) ? red[tid - s] : 0.f;
        __syncthreads();
        red[tid] += t;
        __syncthreads();
    }
    float excl = red[tid] - run;
#pragma unroll
    for (int i = 0; i < 8; i++) rl[tid * 8 + i] = 1.f / (excl + pre[i]);
    __syncthreads();
    if (tid < 64) {
        float acc = 0.f;
        const float* rp = rv + h * 64 + tid;
        float* op = out + h * 64 + tid;
#pragma unroll 4
        for (int t = 0; t < 2048; t++) {
            acc += w[t] * rp[(size_t)t * 1024];
            op[(size_t)t * 1024] = acc * rl[t];
        }
    }
}

// ---------------- branch 3 probabilities, split bf16 directly --------
__global__ void __launch_bounds__(256) kjp3(const float* __restrict__ sc,
                                            __nv_bfloat16* __restrict__ P3) {
    __shared__ float sk[2048];
    __shared__ float se[2048];
    __shared__ float red[256];
    const int qq = blockIdx.x, tid = threadIdx.x;
    for (int t = tid; t < 2048; t += 256) sk[t] = sc[t];
    __syncthreads();
    const float sq = sk[qq] * LOG2E;
    float lm = -1e30f;
    for (int t = tid; t <= qq; t += 256) lm = fmaxf(lm, sq * sk[t]);
    red[tid] = lm; __syncthreads();
    for (int s = 128; s; s >>= 1) { if (tid < s) red[tid] = fmaxf(red[tid], red[tid + s]); __syncthreads(); }
    float M = red[0];
    __syncthreads();
    float ls = 0.f;
    for (int t = tid; t <= qq; t += 256) {
        float e = exp2f(sq * sk[t] - M);
        se[t] = e;
        ls += e;
    }
    red[tid] = ls; __syncthreads();
    for (int s = 128; s; s >>= 1) { if (tid < s) red[tid] += red[tid + s]; __syncthreads(); }
    const float rinv = 1.f / red[0];
    __nv_bfloat16* Prow = P3 + (size_t)qq * 6144;
    for (int t = tid; t < 2048; t += 256) {
        float p = (t <= qq) ? se[t] * rinv : 0.f;
        __nv_bfloat16 hi = __float2bfloat16(p);
        __nv_bfloat16 lo = __float2bfloat16(p - __bfloat162float(hi));
        Prow[t] = hi;
        Prow[2048 + t] = lo;
        Prow[4096 + t] = hi;
    }
}

// ---------------- r[h,t] ----------------------------------------------
__global__ void kr(const float* __restrict__ x, const float* __restrict__ wr,
                   float* __restrict__ r) {
    const int h = blockIdx.y;
    const int t = blockIdx.x * 128 + threadIdx.x;
    const float* wp = wr + (size_t)h * EE * TT + t;
    const float* xp = x + (size_t)t * EE;
    float acc = 0.f;
#pragma unroll 8
    for (int e = 0; e < EE; e++) acc += xp[e] * wp[(size_t)e * TT];
    r[h * TT + t] = acc;
}

// ---------------- scores ----------------------------------------------
__global__ void kscores(const float* __restrict__ x, const float* __restrict__ eb,
                        float* __restrict__ sc) {
    const int t = blockIdx.x;
    const float* xp = x + (size_t)t * EE;
    const float* ep = eb + (size_t)t * EE;
    float a = 0.f;
    for (int e = threadIdx.x; e < EE; e += 256) a += xp[e] * ep[e];
#pragma unroll
    for (int o = 16; o > 0; o >>= 1) a += __shfl_xor_sync(0xffffffffu, a, o);
    __shared__ float red[8];
    if ((threadIdx.x & 31) == 0) red[threadIdx.x >> 5] = a;
    __syncthreads();
    if (threadIdx.x == 0) {
        float s = 0.f;
#pragma unroll
        for (int w = 0; w < 8; w++) s += red[w];
        sc[t] = s * (1.f / 32.f);
    }
}

// ---------------- gated combine -> split bf16 (A pattern) -------------
__global__ void kcombine3(const float* __restrict__ o1, const float* __restrict__ o2,
                          const float* __restrict__ o3, const float* __restrict__ gate,
                          __nv_bfloat16* __restrict__ comb3) {
    const int idx = blockIdx.x * 256 + threadIdx.x;
    const int c = idx & (HD - 1);
    const int h = c >> 6;
    float g0 = gate[h * 3 + 0], g1 = gate[h * 3 + 1], g2 = gate[h * 3 + 2];
    float mx = fmaxf(g0, fmaxf(g1, g2));
    float e0 = __expf(g0 - mx), e1 = __expf(g1 - mx), e2 = __expf(g2 - mx);
    float inv = 1.f / (e0 + e1 + e2);
    float val = (e0 * o1[idx] + e1 * o2[idx] + e2 * o3[idx]) * inv;
    __nv_bfloat16 hi = __float2bfloat16(val);
    __nv_bfloat16 lo = __float2bfloat16(val - __bfloat162float(hi));
    const int m = idx >> 10, k = idx & 1023;
    __nv_bfloat16* row = comb3 + (size_t)m * 3072;
    row[k] = hi;
    row[1024 + k] = lo;
    row[2048 + k] = hi;
}

// ---------------- launch ------------------------------------------------
extern "C" void kernel_launch(void* const* d_in, const int* in_sizes, int n_in,
                              void* d_out, int out_size) {
    const float* x    = (const float*)d_in[0];
    const float* wq   = (const float*)d_in[1];
    const float* wk   = (const float*)d_in[2];
    const float* wv   = (const float*)d_in[3];
    const float* wr   = (const float*)d_in[4];
    const float* wvr  = (const float*)d_in[5];
    const float* wj   = (const float*)d_in[6];
    const float* gate = (const float*)d_in[7];
    const float* wo   = (const float*)d_in[8];
    float* out = (float*)d_out;

    float *q, *k, *v, *rv, *echo, *eb, *r, *sc, *o1, *o2, *o3;
    __nv_bfloat16 *x3, *wq3, *wk3, *wv3, *wvr3, *wj3, *wo3, *wjT3, *echoA3, *echoT3, *P3, *comb3;
    cudaGetSymbolAddress((void**)&q, g_q);
    cudaGetSymbolAddress((void**)&k, g_k);
    cudaGetSymbolAddress((void**)&v, g_v);
    cudaGetSymbolAddress((void**)&rv, g_rv);
    cudaGetSymbolAddress((void**)&echo, g_echo);
    cudaGetSymbolAddress((void**)&eb, g_eb);
    cudaGetSymbolAddress((void**)&r, g_r);
    cudaGetSymbolAddress((void**)&sc, g_sc);
    cudaGetSymbolAddress((void**)&o1, g_o1);
    cudaGetSymbolAddress((void**)&o2, g_o2);
    cudaGetSymbolAddress((void**)&o3, g_o3);
    cudaGetSymbolAddress((void**)&x3, g_x3);
    cudaGetSymbolAddress((void**)&wq3, g_wq3);
    cudaGetSymbolAddress((void**)&wk3, g_wk3);
    cudaGetSymbolAddress((void**)&wv3, g_wv3);
    cudaGetSymbolAddress((void**)&wvr3, g_wvr3);
    cudaGetSymbolAddress((void**)&wj3, g_wj3);
    cudaGetSymbolAddress((void**)&wo3, g_wo3);
    cudaGetSymbolAddress((void**)&wjT3, g_wjT3);
    cudaGetSymbolAddress((void**)&echoA3, g_echoA3);
    cudaGetSymbolAddress((void**)&echoT3, g_echoT3);
    cudaGetSymbolAddress((void**)&P3, g_P3);
    cudaGetSymbolAddress((void**)&comb3, g_comb3);

    cudaFuncSetAttribute(hmma_gemm, cudaFuncAttributeMaxDynamicSharedMemorySize, HMMA_SMEM);

    dim3 mgrid(8, 16);   // N/128, M/128
    const int W = 1024 * 1024 / 256;
    const int X = 2048 * 1024 / 256;

    // split conversions (weights + x)
    conv3<false><<<W, 256>>>(wq, wq3, 1024);
    conv3<false><<<W, 256>>>(wk, wk3, 1024);
    conv3<false><<<W, 256>>>(wv, wv3, 1024);
    conv3<false><<<W, 256>>>(wvr, wvr3, 1024);
    conv3<false><<<W, 256>>>(wj, wj3, 1024);
    conv3<false><<<W, 256>>>(wo, wo3, 1024);
    conv3T<<<dim3(32, 32), 256>>>(wj, wjT3, 1024, 1024);
    conv3<true><<<X, 256>>>(x, x3, 1024);

    // projections on tensor cores (HMMA)
    hmma_gemm<<<mgrid, 256, HMMA_SMEM>>>(x3, wq3, q, 3072);
    hmma_gemm<<<mgrid, 256, HMMA_SMEM>>>(x3, wk3, k, 3072);
    hmma_gemm<<<mgrid, 256, HMMA_SMEM>>>(x3, wv3, v, 3072);
    hmma_gemm<<<mgrid, 256, HMMA_SMEM>>>(x3, wvr3, rv, 3072);
    hmma_gemm<<<mgrid, 256, HMMA_SMEM>>>(x3, wj3, echo, 3072);

    // echo_back = echo @ wj
    conv3<true><<<X, 256>>>(echo, echoA3, 1024);
    conv3T<<<dim3(64, 32), 256>>>(echo, echoT3, 2048, 1024);
    hmma_gemm<<<mgrid, 256, HMMA_SMEM>>>(echoA3, wjT3, eb, 3072);

    kscores<<<TT, 256>>>(x, eb, sc);
    kr<<<dim3(16, 16), 128>>>(x, wr, r);

    kjp3<<<TT, 256>>>(sc, P3);
    flash_qkv2<<<dim3(32, 16), 256>>>(q, k, v, o1);
    krrp<<<16, 256>>>(r, rv, o2);
    hmma_gemm<<<mgrid, 256, HMMA_SMEM>>>(P3, echoT3, o3, 6144);

    kcombine3<<<(TT * HD) / 256, 256>>>(o1, o2, o3, gate, comb3);
    hmma_gemm<<<mgrid, 256, HMMA_SMEM>>>(comb3, wo3, out, 3072);
}

// round 6
// speedup vs baseline: 2.7682x; 1.1162x over previous
#include <cuda_runtime.h>
#include <cuda_bf16.h>
#include <cstdint>

#define TT 2048
#define EE 1024
#define HH 16
#define DD 64
#define HD 1024
#define LOG2E 1.4426950408889634f

// ---------------- fp32 scratch ----------------
__device__ __align__(16) float g_q[TT * HD];
__device__ __align__(16) float g_k[TT * HD];
__device__ __align__(16) float g_v[TT * HD];
__device__ __align__(16) float g_rv[TT * HD];
__device__ __align__(16) float g_echo[TT * EE];
__device__ __align__(16) float g_eb[TT * EE];
__device__ __align__(16) float g_r[HH * TT];
__device__ __align__(16) float g_sc[TT];
__device__ __align__(16) float g_o1[TT * HD];
__device__ __align__(16) float g_o2[TT * HD];
__device__ __align__(16) float g_o3[TT * EE];

// ---------------- bf16 triple-split scratch ----------------
__device__ __align__(16) __nv_bfloat16 g_x3[TT * 3072];
__device__ __align__(16) __nv_bfloat16 g_wq3[1024 * 3072];
__device__ __align__(16) __nv_bfloat16 g_wk3[1024 * 3072];
__device__ __align__(16) __nv_bfloat16 g_wv3[1024 * 3072];
__device__ __align__(16) __nv_bfloat16 g_wvr3[1024 * 3072];
__device__ __align__(16) __nv_bfloat16 g_wj3[1024 * 3072];
__device__ __align__(16) __nv_bfloat16 g_wo3[1024 * 3072];
__device__ __align__(16) __nv_bfloat16 g_wjT3[1024 * 3072];
__device__ __align__(16) __nv_bfloat16 g_echoA3[TT * 3072];
__device__ __align__(16) __nv_bfloat16 g_echoT3[1024 * 6144];   // grouped per 64-key
__device__ __align__(16) __nv_bfloat16 g_P3[TT * 6144];         // grouped per 64-key
__device__ __align__(16) __nv_bfloat16 g_comb3[TT * 3072];

// ============================ PTX helpers ============================
__device__ __forceinline__ uint32_t smem_u32(const void* p) {
    uint32_t a;
    asm("{ .reg .u64 t; cvta.to.shared.u64 t, %1; cvt.u32.u64 %0, t; }" : "=r"(a) : "l"(p));
    return a;
}
__device__ __forceinline__ void cp_async16(uint32_t s, const void* g) {
    asm volatile("cp.async.cg.shared.global [%0], [%1], 16;" :: "r"(s), "l"(g));
}
__device__ __forceinline__ void cp_commit() { asm volatile("cp.async.commit_group;"); }
template<int N> __device__ __forceinline__ void cp_wait() {
    asm volatile("cp.async.wait_group %0;" :: "n"(N) : "memory");
}
__device__ __forceinline__ void ldmx4(uint32_t& r0, uint32_t& r1, uint32_t& r2, uint32_t& r3,
                                      uint32_t addr) {
    asm volatile("ldmatrix.sync.aligned.m8n8.x4.shared.b16 {%0,%1,%2,%3}, [%4];"
                 : "=r"(r0), "=r"(r1), "=r"(r2), "=r"(r3) : "r"(addr));
}
__device__ __forceinline__ void mma_bf16(float* d, const uint32_t* a, const uint32_t* b) {
    asm volatile("mma.sync.aligned.m16n8k16.row.col.f32.bf16.bf16.f32 "
                 "{%0,%1,%2,%3}, {%4,%5,%6,%7}, {%8,%9}, {%0,%1,%2,%3};"
                 : "+f"(d[0]), "+f"(d[1]), "+f"(d[2]), "+f"(d[3])
                 : "r"(a[0]), "r"(a[1]), "r"(a[2]), "r"(a[3]), "r"(b[0]), "r"(b[1]));
}
__device__ __forceinline__ uint32_t pack2(__nv_bfloat16 a, __nv_bfloat16 b) {
    __nv_bfloat162 t(a, b);
    return *reinterpret_cast<uint32_t*>(&t);
}

// =====================================================================
// HMMA bf16 GEMM: C(Mx1024) = A3(MxK3) @ B3(1024xK3)^T, fp32 accum/out.
// Tile 128x128, BK=32, 4-stage cp.async pipeline, 8 warps (4M x 2N).
// CAUSAL (grouped split layout, 192 cols / 64 keys): stop at (m0+128)*3.
// =====================================================================
#define HSTAGE_ELE 10240
#define HMMA_SMEM (4 * HSTAGE_ELE * 2)

template<bool CAUSAL>
__global__ void __launch_bounds__(256, 2) hmma_gemm(const __nv_bfloat16* __restrict__ A,
                                                    const __nv_bfloat16* __restrict__ B,
                                                    float* __restrict__ C, int K3) {
    extern __shared__ __nv_bfloat16 sm[];
    const int tid = threadIdx.x;
    const int m0 = blockIdx.y * 128, n0 = blockIdx.x * 128;
    const int kcols = CAUSAL ? ((m0 + 128) * 3 < K3 ? (m0 + 128) * 3 : K3) : K3;
    const int nchunk = kcols >> 5;
    const int warp = tid >> 5, lane = tid & 31;
    const int wm = warp & 3, wn = warp >> 2;

    const uint32_t smb = smem_u32(sm);

    auto load_stage = [&](int cc, int s) {
        const uint32_t ab = smb + s * (HSTAGE_ELE * 2);
        const uint32_t bb = ab + 10240;
        const int k0 = cc * 32;
#pragma unroll
        for (int i = 0; i < 2; i++) {
            int c = tid * 2 + i;
            int row = c >> 2, cg = c & 3;
            cp_async16(ab + row * 80 + cg * 16, A + (size_t)(m0 + row) * K3 + k0 + cg * 8);
            cp_async16(bb + row * 80 + cg * 16, B + (size_t)(n0 + row) * K3 + k0 + cg * 8);
        }
        cp_commit();
    };

    load_stage(0, 0);
    if (1 < nchunk) load_stage(1, 1); else cp_commit();
    if (2 < nchunk) load_stage(2, 2); else cp_commit();

    float acc[2][8][4];
#pragma unroll
    for (int i = 0; i < 2; i++)
#pragma unroll
        for (int j = 0; j < 8; j++)
#pragma unroll
            for (int t = 0; t < 4; t++) acc[i][j][t] = 0.f;

    const int lrow = lane & 15;
    const int lcol = (lane >> 4) << 3;

    for (int c = 0; c < nchunk; c++) {
        cp_wait<2>();
        __syncthreads();
        if (c + 3 < nchunk) load_stage(c + 3, (c + 3) & 3); else cp_commit();

        const uint32_t ab = smb + (c & 3) * (HSTAGE_ELE * 2);
        const uint32_t bb = ab + 10240;
#pragma unroll
        for (int ks = 0; ks < 2; ks++) {
            const uint32_t coff = (ks * 16 + lcol) * 2;
            uint32_t a[2][4], b[8][2];
#pragma unroll
            for (int mt = 0; mt < 2; mt++)
                ldmx4(a[mt][0], a[mt][1], a[mt][2], a[mt][3],
                      ab + (uint32_t)(wm * 32 + mt * 16 + lrow) * 80 + coff);
#pragma unroll
            for (int bp = 0; bp < 4; bp++) {
                uint32_t r0, r1, r2, r3;
                ldmx4(r0, r1, r2, r3,
                      bb + (uint32_t)(wn * 64 + bp * 16 + lrow) * 80 + coff);
                b[bp * 2][0] = r0; b[bp * 2][1] = r2;
                b[bp * 2 + 1][0] = r1; b[bp * 2 + 1][1] = r3;
            }
#pragma unroll
            for (int mt = 0; mt < 2; mt++)
#pragma unroll
                for (int nt = 0; nt < 8; nt++) mma_bf16(acc[mt][nt], a[mt], b[nt]);
        }
        __syncthreads();
    }

    const int erow = lane >> 2;
    const int ecol = (lane & 3) * 2;
#pragma unroll
    for (int mt = 0; mt < 2; mt++) {
        const int r0 = m0 + wm * 32 + mt * 16 + erow;
#pragma unroll
        for (int nt = 0; nt < 8; nt++) {
            const int cc = n0 + wn * 64 + nt * 8 + ecol;
            *(float2*)&C[(size_t)r0 * 1024 + cc] = make_float2(acc[mt][nt][0], acc[mt][nt][1]);
            *(float2*)&C[(size_t)(r0 + 8) * 1024 + cc] = make_float2(acc[mt][nt][2], acc[mt][nt][3]);
        }
    }
}

// =====================================================================
// branch 1: fused HMMA flash attention (triple-split bf16, fp32 softmax)
// 128 threads; warp w owns q-rows [w*16, w*16+16); 64-key tiles.
// =====================================================================
#define FL_SMEM (3 * 64 * 200 * 2)    // Qs, Ks, Vs: 64 rows x 200 bf16 each

__global__ void __launch_bounds__(128) flash_hmma(const float* __restrict__ q,
                                                  const float* __restrict__ k,
                                                  const float* __restrict__ v,
                                                  float* __restrict__ out) {
    extern __shared__ __nv_bfloat16 fsm[];
    const int h = blockIdx.y, m0 = blockIdx.x * 64;
    const int tid = threadIdx.x, warp = tid >> 5, lane = tid & 31;
    const uint32_t smb = smem_u32(fsm);
    const uint32_t Qb = smb, Kb = smb + 25600, Vb = smb + 51200;
    const int lrow = lane & 15, lcol = (lane >> 4) << 3;
    const float QSCALE = 0.125f * LOG2E;

    // load+split Q (scale folded in): pattern [hi, lo, hi] over d
    for (int idx = tid; idx < 4096; idx += 128) {
        int r = idx >> 6, d = idx & 63;
        float val = q[(size_t)(m0 + r) * HD + h * 64 + d] * QSCALE;
        __nv_bfloat16 hi = __float2bfloat16(val);
        __nv_bfloat16 lo = __float2bfloat16(val - __bfloat162float(hi));
        __nv_bfloat16* Qr = fsm + r * 200;
        Qr[d] = hi; Qr[64 + d] = lo; Qr[128 + d] = hi;
    }

    float m_lo = -1e30f, m_hi = -1e30f, l_lo = 0.f, l_hi = 0.f;
    float O[8][4];
#pragma unroll
    for (int nt = 0; nt < 8; nt++)
#pragma unroll
        for (int t = 0; t < 4; t++) O[nt][t] = 0.f;

    for (int n0 = 0; n0 <= m0; n0 += 64) {
        __syncthreads();
        // load+split K (pattern [hi,hi,lo] over d) and V transposed ([hi,hi,lo] over keys)
        for (int idx = tid; idx < 4096; idx += 128) {
            int j = idx >> 6, d = idx & 63;
            float kv = k[(size_t)(n0 + j) * HD + h * 64 + d];
            __nv_bfloat16 khi = __float2bfloat16(kv);
            __nv_bfloat16 klo = __float2bfloat16(kv - __bfloat162float(khi));
            __nv_bfloat16* Kr = fsm + 12800 + j * 200;
            Kr[d] = khi; Kr[64 + d] = khi; Kr[128 + d] = klo;
            float vv = v[(size_t)(n0 + j) * HD + h * 64 + d];
            __nv_bfloat16 vhi = __float2bfloat16(vv);
            __nv_bfloat16 vlo = __float2bfloat16(vv - __bfloat162float(vhi));
            __nv_bfloat16* Vc = fsm + 25600 + d * 200;
            Vc[j] = vhi; Vc[64 + j] = vhi; Vc[128 + j] = vlo;
        }
        __syncthreads();

        // S = Q' K'^T (exp2 domain), K3 = 192
        float s[8][4];
#pragma unroll
        for (int nt = 0; nt < 8; nt++)
#pragma unroll
            for (int t = 0; t < 4; t++) s[nt][t] = 0.f;
#pragma unroll
        for (int ks = 0; ks < 12; ks++) {
            const uint32_t coff = (ks * 16 + lcol) * 2;
            uint32_t a[4], b[8][2];
            ldmx4(a[0], a[1], a[2], a[3], Qb + (uint32_t)(warp * 16 + lrow) * 400 + coff);
#pragma unroll
            for (int bp = 0; bp < 4; bp++) {
                uint32_t r0, r1, r2, r3;
                ldmx4(r0, r1, r2, r3, Kb + (uint32_t)(bp * 16 + lrow) * 400 + coff);
                b[bp * 2][0] = r0; b[bp * 2][1] = r2;
                b[bp * 2 + 1][0] = r1; b[bp * 2 + 1][1] = r3;
            }
#pragma unroll
            for (int nt = 0; nt < 8; nt++) mma_bf16(s[nt], a, b[nt]);
        }

        // causal mask (diagonal tile only)
        if (n0 == m0) {
            const int rl = m0 + warp * 16 + (lane >> 2);
            const int cb = n0 + (lane & 3) * 2;
#pragma unroll
            for (int nt = 0; nt < 8; nt++) {
                int c0 = cb + nt * 8, c1 = c0 + 1;
                if (c0 > rl) s[nt][0] = -1e30f;
                if (c1 > rl) s[nt][1] = -1e30f;
                if (c0 > rl + 8) s[nt][2] = -1e30f;
                if (c1 > rl + 8) s[nt][3] = -1e30f;
            }
        }

        // online softmax (rows shared within lane quads)
        float rmx_lo = -1e30f, rmx_hi = -1e30f;
#pragma unroll
        for (int nt = 0; nt < 8; nt++) {
            rmx_lo = fmaxf(rmx_lo, fmaxf(s[nt][0], s[nt][1]));
            rmx_hi = fmaxf(rmx_hi, fmaxf(s[nt][2], s[nt][3]));
        }
#pragma unroll
        for (int o = 1; o < 4; o <<= 1) {
            rmx_lo = fmaxf(rmx_lo, __shfl_xor_sync(0xffffffffu, rmx_lo, o));
            rmx_hi = fmaxf(rmx_hi, __shfl_xor_sync(0xffffffffu, rmx_hi, o));
        }
        float mn_lo = fmaxf(m_lo, rmx_lo), mn_hi = fmaxf(m_hi, rmx_hi);
        float corr_lo = exp2f(m_lo - mn_lo), corr_hi = exp2f(m_hi - mn_hi);
        m_lo = mn_lo; m_hi = mn_hi;
        float rs_lo = 0.f, rs_hi = 0.f;
#pragma unroll
        for (int nt = 0; nt < 8; nt++) {
            s[nt][0] = exp2f(s[nt][0] - mn_lo); rs_lo += s[nt][0];
            s[nt][1] = exp2f(s[nt][1] - mn_lo); rs_lo += s[nt][1];
            s[nt][2] = exp2f(s[nt][2] - mn_hi); rs_hi += s[nt][2];
            s[nt][3] = exp2f(s[nt][3] - mn_hi); rs_hi += s[nt][3];
        }
#pragma unroll
        for (int o = 1; o < 4; o <<= 1) {
            rs_lo += __shfl_xor_sync(0xffffffffu, rs_lo, o);
            rs_hi += __shfl_xor_sync(0xffffffffu, rs_hi, o);
        }
        l_lo = l_lo * corr_lo + rs_lo;
        l_hi = l_hi * corr_hi + rs_hi;
#pragma unroll
        for (int nt = 0; nt < 8; nt++) {
            O[nt][0] *= corr_lo; O[nt][1] *= corr_lo;
            O[nt][2] *= corr_hi; O[nt][3] *= corr_hi;
        }

        // build P hi/lo A-fragments (C-frag -> A-frag identity)
        uint32_t phi[4][4], plo[4][4];
#pragma unroll
        for (int kk = 0; kk < 4; kk++) {
            const int n0t = 2 * kk, n1t = 2 * kk + 1;
            __nv_bfloat16 h00 = __float2bfloat16(s[n0t][0]);
            __nv_bfloat16 h01 = __float2bfloat16(s[n0t][1]);
            __nv_bfloat16 h02 = __float2bfloat16(s[n0t][2]);
            __nv_bfloat16 h03 = __float2bfloat16(s[n0t][3]);
            __nv_bfloat16 h10 = __float2bfloat16(s[n1t][0]);
            __nv_bfloat16 h11 = __float2bfloat16(s[n1t][1]);
            __nv_bfloat16 h12 = __float2bfloat16(s[n1t][2]);
            __nv_bfloat16 h13 = __float2bfloat16(s[n1t][3]);
            phi[kk][0] = pack2(h00, h01);
            phi[kk][1] = pack2(h02, h03);
            phi[kk][2] = pack2(h10, h11);
            phi[kk][3] = pack2(h12, h13);
            plo[kk][0] = pack2(__float2bfloat16(s[n0t][0] - __bfloat162float(h00)),
                               __float2bfloat16(s[n0t][1] - __bfloat162float(h01)));
            plo[kk][1] = pack2(__float2bfloat16(s[n0t][2] - __bfloat162float(h02)),
                               __float2bfloat16(s[n0t][3] - __bfloat162float(h03)));
            plo[kk][2] = pack2(__float2bfloat16(s[n1t][0] - __bfloat162float(h10)),
                               __float2bfloat16(s[n1t][1] - __bfloat162float(h11)));
            plo[kk][3] = pack2(__float2bfloat16(s[n1t][2] - __bfloat162float(h12)),
                               __float2bfloat16(s[n1t][3] - __bfloat162float(h13)));
        }

        // O += P' V'  (key-split pattern [Phi, Plo, Phi] x [Vhi, Vhi, Vlo])
#pragma unroll
        for (int ks = 0; ks < 12; ks++) {
            const uint32_t* a = (ks < 4) ? phi[ks] : (ks < 8) ? plo[ks - 4] : phi[ks - 8];
            const uint32_t coff = (ks * 16 + lcol) * 2;
            uint32_t b[8][2];
#pragma unroll
            for (int bp = 0; bp < 4; bp++) {
                uint32_t r0, r1, r2, r3;
                ldmx4(r0, r1, r2, r3, Vb + (uint32_t)(bp * 16 + lrow) * 400 + coff);
                b[bp * 2][0] = r0; b[bp * 2][1] = r2;
                b[bp * 2 + 1][0] = r1; b[bp * 2 + 1][1] = r3;
            }
#pragma unroll
            for (int nt = 0; nt < 8; nt++) mma_bf16(O[nt], a, b[nt]);
        }
    }

    const float inv_lo = 1.f / l_lo, inv_hi = 1.f / l_hi;
    const int rl = m0 + warp * 16 + (lane >> 2);
#pragma unroll
    for (int nt = 0; nt < 8; nt++) {
        const int col = h * 64 + nt * 8 + (lane & 3) * 2;
        *(float2*)&out[(size_t)rl * HD + col] = make_float2(O[nt][0] * inv_lo, O[nt][1] * inv_lo);
        *(float2*)&out[(size_t)(rl + 8) * HD + col] = make_float2(O[nt][2] * inv_hi, O[nt][3] * inv_hi);
    }
}

// =====================================================================
// fp32 -> bf16 triple split.  APAT: [hi,lo,hi]; else [hi,hi,lo]
// =====================================================================
template<bool APAT>
__global__ void conv3(const float* __restrict__ S, __nv_bfloat16* __restrict__ D, int K) {
    const int idx = blockIdx.x * 256 + threadIdx.x;
    const int m = idx / K, k = idx - m * K;
    float x = S[idx];
    __nv_bfloat16 hi = __float2bfloat16(x);
    __nv_bfloat16 lo = __float2bfloat16(x - __bfloat162float(hi));
    const size_t ro = (size_t)m * 3 * K;
    D[ro + k] = hi;
    D[ro + K + k] = APAT ? lo : hi;
    D[ro + 2 * K + k] = APAT ? hi : lo;
}

// transpose + split (B pattern, contiguous blocks): S KxN -> D N x 3K
__global__ void conv3T(const float* __restrict__ S, __nv_bfloat16* __restrict__ D,
                       int K, int N) {
    __shared__ float t[32][33];
    const int k0 = blockIdx.x * 32, n0 = blockIdx.y * 32;
    const int tx = threadIdx.x & 31, ty = threadIdx.x >> 5;
    for (int i = ty; i < 32; i += 8) t[i][tx] = S[(size_t)(k0 + i) * N + n0 + tx];
    __syncthreads();
    const int K3 = 3 * K;
    for (int i = ty; i < 32; i += 8) {
        const int n = n0 + i, k = k0 + tx;
        float x = t[tx][i];
        __nv_bfloat16 hi = __float2bfloat16(x);
        __nv_bfloat16 lo = __float2bfloat16(x - __bfloat162float(hi));
        D[(size_t)n * K3 + k] = hi;
        D[(size_t)n * K3 + K + k] = hi;
        D[(size_t)n * K3 + 2 * K + k] = lo;
    }
}

// transpose + split, GROUPED per 64-key: group g cols [g*192 .. g*192+192)
// = [hi(64), hi(64), lo(64)] of keys g*64..g*64+63
__global__ void conv3Tg(const float* __restrict__ S, __nv_bfloat16* __restrict__ D,
                        int K, int N) {
    __shared__ float t[32][33];
    const int k0 = blockIdx.x * 32, n0 = blockIdx.y * 32;
    const int tx = threadIdx.x & 31, ty = threadIdx.x >> 5;
    for (int i = ty; i < 32; i += 8) t[i][tx] = S[(size_t)(k0 + i) * N + n0 + tx];
    __syncthreads();
    const int K3 = 3 * K;
    for (int i = ty; i < 32; i += 8) {
        const int n = n0 + i, k = k0 + tx;
        const int g = k >> 6, j = k & 63;
        float x = t[tx][i];
        __nv_bfloat16 hi = __float2bfloat16(x);
        __nv_bfloat16 lo = __float2bfloat16(x - __bfloat162float(hi));
        __nv_bfloat16* base = D + (size_t)n * K3 + g * 192;
        base[j] = hi;
        base[64 + j] = hi;
        base[128 + j] = lo;
    }
}

// ---------------- branch 2: prefix scan ------------------------------
__global__ void __launch_bounds__(256) krrp(const float* __restrict__ r,
                                            const float* __restrict__ rv,
                                            float* __restrict__ out) {
    __shared__ float w[2048];
    __shared__ float rl[2048];
    __shared__ float red[256];
    const int h = blockIdx.x, tid = threadIdx.x;
    const float Cc = 0.125f * LOG2E;
    float vloc[8], lm = -1e30f;
#pragma unroll
    for (int i = 0; i < 8; i++) {
        float vv = r[h * 2048 + tid * 8 + i] * Cc;
        vloc[i] = vv;
        lm = fmaxf(lm, vv);
    }
    red[tid] = lm; __syncthreads();
    for (int s = 128; s; s >>= 1) { if (tid < s) red[tid] = fmaxf(red[tid], red[tid + s]); __syncthreads(); }
    float M = red[0];
    __syncthreads();
    float run = 0.f, pre[8];
#pragma unroll
    for (int i = 0; i < 8; i++) {
        float e = exp2f(vloc[i] - M);
        w[tid * 8 + i] = e;
        run += e;
        pre[i] = run;
    }
    red[tid] = run; __syncthreads();
    for (int s = 1; s < 256; s <<= 1) {
        float t = (tid >= s) ? red[tid - s] : 0.f;
        __syncthreads();
        red[tid] += t;
        __syncthreads();
    }
    float excl = red[tid] - run;
#pragma unroll
    for (int i = 0; i < 8; i++) rl[tid * 8 + i] = 1.f / (excl + pre[i]);
    __syncthreads();
    if (tid < 64) {
        float acc = 0.f;
        const float* rp = rv + h * 64 + tid;
        float* op = out + h * 64 + tid;
#pragma unroll 4
        for (int t = 0; t < 2048; t++) {
            acc += w[t] * rp[(size_t)t * 1024];
            op[(size_t)t * 1024] = acc * rl[t];
        }
    }
}

// ---------------- branch 3 probabilities -> grouped split bf16 -------
__global__ void __launch_bounds__(256) kjp3(const float* __restrict__ sc,
                                            __nv_bfloat16* __restrict__ P3) {
    __shared__ float sk[2048];
    __shared__ float se[2048];
    __shared__ float red[256];
    const int qq = blockIdx.x, tid = threadIdx.x;
    for (int t = tid; t < 2048; t += 256) sk[t] = sc[t];
    __syncthreads();
    const float sq = sk[qq] * LOG2E;
    float lm = -1e30f;
    for (int t = tid; t <= qq; t += 256) lm = fmaxf(lm, sq * sk[t]);
    red[tid] = lm; __syncthreads();
    for (int s = 128; s; s >>= 1) { if (tid < s) red[tid] = fmaxf(red[tid], red[tid + s]); __syncthreads(); }
    float M = red[0];
    __syncthreads();
    float ls = 0.f;
    for (int t = tid; t <= qq; t += 256) {
        float e = exp2f(sq * sk[t] - M);
        se[t] = e;
        ls += e;
    }
    red[tid] = ls; __syncthreads();
    for (int s = 128; s; s >>= 1) { if (tid < s) red[tid] += red[tid + s]; __syncthreads(); }
    const float rinv = 1.f / red[0];
    __nv_bfloat16* Prow = P3 + (size_t)qq * 6144;
    for (int t = tid; t < 2048; t += 256) {
        float p = (t <= qq) ? se[t] * rinv : 0.f;
        __nv_bfloat16 hi = __float2bfloat16(p);
        __nv_bfloat16 lo = __float2bfloat16(p - __bfloat162float(hi));
        const int g = t >> 6, j = t & 63;
        __nv_bfloat16* base = Prow + g * 192;
        base[j] = hi;        // [Phi, Plo, Phi] per group
        base[64 + j] = lo;
        base[128 + j] = hi;
    }
}

// ---------------- r[h,t] ----------------------------------------------
__global__ void kr(const float* __restrict__ x, const float* __restrict__ wr,
                   float* __restrict__ r) {
    const int h = blockIdx.y;
    const int t = blockIdx.x * 128 + threadIdx.x;
    const float* wp = wr + (size_t)h * EE * TT + t;
    const float* xp = x + (size_t)t * EE;
    float acc = 0.f;
#pragma unroll 8
    for (int e = 0; e < EE; e++) acc += xp[e] * wp[(size_t)e * TT];
    r[h * TT + t] = acc;
}

// ---------------- scores ----------------------------------------------
__global__ void kscores(const float* __restrict__ x, const float* __restrict__ eb,
                        float* __restrict__ sc) {
    const int t = blockIdx.x;
    const float* xp = x + (size_t)t * EE;
    const float* ep = eb + (size_t)t * EE;
    float a = 0.f;
    for (int e = threadIdx.x; e < EE; e += 256) a += xp[e] * ep[e];
#pragma unroll
    for (int o = 16; o > 0; o >>= 1) a += __shfl_xor_sync(0xffffffffu, a, o);
    __shared__ float red[8];
    if ((threadIdx.x & 31) == 0) red[threadIdx.x >> 5] = a;
    __syncthreads();
    if (threadIdx.x == 0) {
        float s = 0.f;
#pragma unroll
        for (int w = 0; w < 8; w++) s += red[w];
        sc[t] = s * (1.f / 32.f);
    }
}

// ---------------- gated combine -> split bf16 (A pattern) -------------
__global__ void kcombine3(const float* __restrict__ o1, const float* __restrict__ o2,
                          const float* __restrict__ o3, const float* __restrict__ gate,
                          __nv_bfloat16* __restrict__ comb3) {
    const int idx = blockIdx.x * 256 + threadIdx.x;
    const int c = idx & (HD - 1);
    const int h = c >> 6;
    float g0 = gate[h * 3 + 0], g1 = gate[h * 3 + 1], g2 = gate[h * 3 + 2];
    float mx = fmaxf(g0, fmaxf(g1, g2));
    float e0 = __expf(g0 - mx), e1 = __expf(g1 - mx), e2 = __expf(g2 - mx);
    float inv = 1.f / (e0 + e1 + e2);
    float val = (e0 * o1[idx] + e1 * o2[idx] + e2 * o3[idx]) * inv;
    __nv_bfloat16 hi = __float2bfloat16(val);
    __nv_bfloat16 lo = __float2bfloat16(val - __bfloat162float(hi));
    const int m = idx >> 10, k = idx & 1023;
    __nv_bfloat16* row = comb3 + (size_t)m * 3072;
    row[k] = hi;
    row[1024 + k] = lo;
    row[2048 + k] = hi;
}

// ---------------- launch ------------------------------------------------
extern "C" void kernel_launch(void* const* d_in, const int* in_sizes, int n_in,
                              void* d_out, int out_size) {
    const float* x    = (const float*)d_in[0];
    const float* wq   = (const float*)d_in[1];
    const float* wk   = (const float*)d_in[2];
    const float* wv   = (const float*)d_in[3];
    const float* wr   = (const float*)d_in[4];
    const float* wvr  = (const float*)d_in[5];
    const float* wj   = (const float*)d_in[6];
    const float* gate = (const float*)d_in[7];
    const float* wo   = (const float*)d_in[8];
    float* out = (float*)d_out;

    float *q, *k, *v, *rv, *echo, *eb, *r, *sc, *o1, *o2, *o3;
    __nv_bfloat16 *x3, *wq3, *wk3, *wv3, *wvr3, *wj3, *wo3, *wjT3, *echoA3, *echoT3, *P3, *comb3;
    cudaGetSymbolAddress((void**)&q, g_q);
    cudaGetSymbolAddress((void**)&k, g_k);
    cudaGetSymbolAddress((void**)&v, g_v);
    cudaGetSymbolAddress((void**)&rv, g_rv);
    cudaGetSymbolAddress((void**)&echo, g_echo);
    cudaGetSymbolAddress((void**)&eb, g_eb);
    cudaGetSymbolAddress((void**)&r, g_r);
    cudaGetSymbolAddress((void**)&sc, g_sc);
    cudaGetSymbolAddress((void**)&o1, g_o1);
    cudaGetSymbolAddress((void**)&o2, g_o2);
    cudaGetSymbolAddress((void**)&o3, g_o3);
    cudaGetSymbolAddress((void**)&x3, g_x3);
    cudaGetSymbolAddress((void**)&wq3, g_wq3);
    cudaGetSymbolAddress((void**)&wk3, g_wk3);
    cudaGetSymbolAddress((void**)&wv3, g_wv3);
    cudaGetSymbolAddress((void**)&wvr3, g_wvr3);
    cudaGetSymbolAddress((void**)&wj3, g_wj3);
    cudaGetSymbolAddress((void**)&wo3, g_wo3);
    cudaGetSymbolAddress((void**)&wjT3, g_wjT3);
    cudaGetSymbolAddress((void**)&echoA3, g_echoA3);
    cudaGetSymbolAddress((void**)&echoT3, g_echoT3);
    cudaGetSymbolAddress((void**)&P3, g_P3);
    cudaGetSymbolAddress((void**)&comb3, g_comb3);

    cudaFuncSetAttribute(hmma_gemm<false>, cudaFuncAttributeMaxDynamicSharedMemorySize, HMMA_SMEM);
    cudaFuncSetAttribute(hmma_gemm<true>, cudaFuncAttributeMaxDynamicSharedMemorySize, HMMA_SMEM);
    cudaFuncSetAttribute(flash_hmma, cudaFuncAttributeMaxDynamicSharedMemorySize, FL_SMEM);

    dim3 mgrid(8, 16);
    const int W = 1024 * 1024 / 256;
    const int X = 2048 * 1024 / 256;

    conv3<false><<<W, 256>>>(wq, wq3, 1024);
    conv3<false><<<W, 256>>>(wk, wk3, 1024);
    conv3<false><<<W, 256>>>(wv, wv3, 1024);
    conv3<false><<<W, 256>>>(wvr, wvr3, 1024);
    conv3<false><<<W, 256>>>(wj, wj3, 1024);
    conv3<false><<<W, 256>>>(wo, wo3, 1024);
    conv3T<<<dim3(32, 32), 256>>>(wj, wjT3, 1024, 1024);
    conv3<true><<<X, 256>>>(x, x3, 1024);

    hmma_gemm<false><<<mgrid, 256, HMMA_SMEM>>>(x3, wq3, q, 3072);
    hmma_gemm<false><<<mgrid, 256, HMMA_SMEM>>>(x3, wk3, k, 3072);
    hmma_gemm<false><<<mgrid, 256, HMMA_SMEM>>>(x3, wv3, v, 3072);
    hmma_gemm<false><<<mgrid, 256, HMMA_SMEM>>>(x3, wvr3, rv, 3072);
    hmma_gemm<false><<<mgrid, 256, HMMA_SMEM>>>(x3, wj3, echo, 3072);

    conv3<true><<<X, 256>>>(echo, echoA3, 1024);
    conv3Tg<<<dim3(64, 32), 256>>>(echo, echoT3, 2048, 1024);
    hmma_gemm<false><<<mgrid, 256, HMMA_SMEM>>>(echoA3, wjT3, eb, 3072);

    kscores<<<TT, 256>>>(x, eb, sc);
    kr<<<dim3(16, 16), 128>>>(x, wr, r);

    kjp3<<<TT, 256>>>(sc, P3);
    flash_hmma<<<dim3(32, 16), 128, FL_SMEM>>>(q, k, v, o1);
    krrp<<<16, 256>>>(r, rv, o2);
    hmma_gemm<true><<<mgrid, 256, HMMA_SMEM>>>(P3, echoT3, o3, 6144);

    kcombine3<<<(TT * HD) / 256, 256>>>(o1, o2, o3, gate, comb3);
    hmma_gemm<false><<<mgrid, 256, HMMA_SMEM>>>(comb3, wo3, out, 3072);
}

// round 7
// speedup vs baseline: 3.2819x; 1.1856x over previous
#include <cuda_runtime.h>
#include <cuda_bf16.h>
#include <cstdint>

#define TT 2048
#define EE 1024
#define HH 16
#define DD 64
#define HD 1024
#define LOG2E 1.4426950408889634f

// ---------------- fp32 scratch ----------------
__device__ __align__(16) float g_q[TT * HD];
__device__ __align__(16) float g_k[TT * HD];
__device__ __align__(16) float g_v[TT * HD];
__device__ __align__(16) float g_rv[TT * HD];
__device__ __align__(16) float g_echo[TT * EE];
__device__ __align__(16) float g_eb[TT * EE];
__device__ __align__(16) float g_r[HH * TT];
__device__ __align__(16) float g_sc[TT];
__device__ __align__(16) float g_o1[TT * HD];
__device__ __align__(16) float g_o2[TT * HD];
__device__ __align__(16) float g_o3[TT * EE];

// ---------------- bf16 triple-split scratch ----------------
__device__ __align__(16) __nv_bfloat16 g_x3[TT * 3072];
__device__ __align__(16) __nv_bfloat16 g_w6[6144 * 3072];       // [wq|wk|wv|wvr|wj|wo]
__device__ __align__(16) __nv_bfloat16 g_wjT3[1024 * 3072];
__device__ __align__(16) __nv_bfloat16 g_echoA3[TT * 3072];
__device__ __align__(16) __nv_bfloat16 g_echoT3[1024 * 6144];   // grouped per 64-key
__device__ __align__(16) __nv_bfloat16 g_P3[TT * 6144];         // grouped per 64-key
__device__ __align__(16) __nv_bfloat16 g_comb3[TT * 3072];

struct Src6 { const float* s[6]; };
struct Out5 { float* p[5]; };

// ============================ PTX helpers ============================
__device__ __forceinline__ uint32_t smem_u32(const void* p) {
    uint32_t a;
    asm("{ .reg .u64 t; cvta.to.shared.u64 t, %1; cvt.u32.u64 %0, t; }" : "=r"(a) : "l"(p));
    return a;
}
__device__ __forceinline__ void cp_async16(uint32_t s, const void* g) {
    asm volatile("cp.async.cg.shared.global [%0], [%1], 16;" :: "r"(s), "l"(g));
}
__device__ __forceinline__ void cp_commit() { asm volatile("cp.async.commit_group;"); }
template<int N> __device__ __forceinline__ void cp_wait() {
    asm volatile("cp.async.wait_group %0;" :: "n"(N) : "memory");
}
__device__ __forceinline__ void ldmx4(uint32_t& r0, uint32_t& r1, uint32_t& r2, uint32_t& r3,
                                      uint32_t addr) {
    asm volatile("ldmatrix.sync.aligned.m8n8.x4.shared.b16 {%0,%1,%2,%3}, [%4];"
                 : "=r"(r0), "=r"(r1), "=r"(r2), "=r"(r3) : "r"(addr));
}
__device__ __forceinline__ void mma_bf16(float* d, const uint32_t* a, const uint32_t* b) {
    asm volatile("mma.sync.aligned.m16n8k16.row.col.f32.bf16.bf16.f32 "
                 "{%0,%1,%2,%3}, {%4,%5,%6,%7}, {%8,%9}, {%0,%1,%2,%3};"
                 : "+f"(d[0]), "+f"(d[1]), "+f"(d[2]), "+f"(d[3])
                 : "r"(a[0]), "r"(a[1]), "r"(a[2]), "r"(a[3]), "r"(b[0]), "r"(b[1]));
}
__device__ __forceinline__ uint32_t pack2(__nv_bfloat16 a, __nv_bfloat16 b) {
    __nv_bfloat162 t(a, b);
    return *reinterpret_cast<uint32_t*>(&t);
}

#define HSTAGE_ELE 10240
#define HMMA_SMEM (4 * HSTAGE_ELE * 2)

// =====================================================================
// Shared HMMA mainloop body (A tile @ m0, B tile rows n0 of NxK3 buffer)
// =====================================================================
template<bool CAUSAL>
__device__ __forceinline__ void hmma_body(const __nv_bfloat16* __restrict__ A,
                                          const __nv_bfloat16* __restrict__ B,
                                          float acc[2][8][4],
                                          int m0, int n0, int K3,
                                          __nv_bfloat16* sm) {
    const int tid = threadIdx.x;
    const int kcols = CAUSAL ? ((m0 + 128) * 3 < K3 ? (m0 + 128) * 3 : K3) : K3;
    const int nchunk = kcols >> 5;
    const int warp = tid >> 5, lane = tid & 31;
    const int wm = warp & 3, wn = warp >> 2;
    const uint32_t smb = smem_u32(sm);

    auto load_stage = [&](int cc, int s) {
        const uint32_t ab = smb + s * (HSTAGE_ELE * 2);
        const uint32_t bb = ab + 10240;
        const int k0 = cc * 32;
#pragma unroll
        for (int i = 0; i < 2; i++) {
            int c = tid * 2 + i;
            int row = c >> 2, cg = c & 3;
            cp_async16(ab + row * 80 + cg * 16, A + (size_t)(m0 + row) * K3 + k0 + cg * 8);
            cp_async16(bb + row * 80 + cg * 16, B + (size_t)(n0 + row) * K3 + k0 + cg * 8);
        }
        cp_commit();
    };

    load_stage(0, 0);
    if (1 < nchunk) load_stage(1, 1); else cp_commit();
    if (2 < nchunk) load_stage(2, 2); else cp_commit();

    const int lrow = lane & 15;
    const int lcol = (lane >> 4) << 3;

    for (int c = 0; c < nchunk; c++) {
        cp_wait<2>();
        __syncthreads();
        if (c + 3 < nchunk) load_stage(c + 3, (c + 3) & 3); else cp_commit();

        const uint32_t ab = smb + (c & 3) * (HSTAGE_ELE * 2);
        const uint32_t bb = ab + 10240;
#pragma unroll
        for (int ks = 0; ks < 2; ks++) {
            const uint32_t coff = (ks * 16 + lcol) * 2;
            uint32_t a[2][4], b[8][2];
#pragma unroll
            for (int mt = 0; mt < 2; mt++)
                ldmx4(a[mt][0], a[mt][1], a[mt][2], a[mt][3],
                      ab + (uint32_t)(wm * 32 + mt * 16 + lrow) * 80 + coff);
#pragma unroll
            for (int bp = 0; bp < 4; bp++) {
                uint32_t r0, r1, r2, r3;
                ldmx4(r0, r1, r2, r3,
                      bb + (uint32_t)(wn * 64 + bp * 16 + lrow) * 80 + coff);
                b[bp * 2][0] = r0; b[bp * 2][1] = r2;
                b[bp * 2 + 1][0] = r1; b[bp * 2 + 1][1] = r3;
            }
#pragma unroll
            for (int mt = 0; mt < 2; mt++)
#pragma unroll
                for (int nt = 0; nt < 8; nt++) mma_bf16(acc[mt][nt], a[mt], b[nt]);
        }
        __syncthreads();
    }
}

__device__ __forceinline__ void hmma_epi(float acc[2][8][4], float* C, int m0, int ncol0) {
    const int lane = threadIdx.x & 31, warp = threadIdx.x >> 5;
    const int wm = warp & 3, wn = warp >> 2;
    const int erow = lane >> 2, ecol = (lane & 3) * 2;
#pragma unroll
    for (int mt = 0; mt < 2; mt++) {
        const int r0 = m0 + wm * 32 + mt * 16 + erow;
#pragma unroll
        for (int nt = 0; nt < 8; nt++) {
            const int cc = ncol0 + wn * 64 + nt * 8 + ecol;
            *(float2*)&C[(size_t)r0 * 1024 + cc] = make_float2(acc[mt][nt][0], acc[mt][nt][1]);
            *(float2*)&C[(size_t)(r0 + 8) * 1024 + cc] = make_float2(acc[mt][nt][2], acc[mt][nt][3]);
        }
    }
}

template<bool CAUSAL>
__global__ void __launch_bounds__(256, 2) hmma_gemm(const __nv_bfloat16* __restrict__ A,
                                                    const __nv_bfloat16* __restrict__ B,
                                                    float* __restrict__ C, int K3) {
    extern __shared__ __nv_bfloat16 sm[];
    float acc[2][8][4];
#pragma unroll
    for (int i = 0; i < 2; i++)
#pragma unroll
        for (int j = 0; j < 8; j++)
#pragma unroll
            for (int t = 0; t < 4; t++) acc[i][j][t] = 0.f;
    const int m0 = blockIdx.y * 128, n0 = blockIdx.x * 128;
    hmma_body<CAUSAL>(A, B, acc, m0, n0, K3, sm);
    hmma_epi(acc, C, m0, n0);
}

// batched projection: B has 5120 rows; output buffer chosen by n-block
__global__ void __launch_bounds__(256, 2) hmma_gemm5(const __nv_bfloat16* __restrict__ A,
                                                     const __nv_bfloat16* __restrict__ B,
                                                     Out5 outs, int K3) {
    extern __shared__ __nv_bfloat16 sm[];
    float acc[2][8][4];
#pragma unroll
    for (int i = 0; i < 2; i++)
#pragma unroll
        for (int j = 0; j < 8; j++)
#pragma unroll
            for (int t = 0; t < 4; t++) acc[i][j][t] = 0.f;
    const int m0 = blockIdx.y * 128, n0 = blockIdx.x * 128;
    hmma_body<false>(A, B, acc, m0, n0, K3, sm);
    hmma_epi(acc, outs.p[blockIdx.x >> 3], m0, (blockIdx.x & 7) * 128);
}

// =====================================================================
// branch 1: fused HMMA flash attention
// =====================================================================
#define FL_SMEM (3 * 64 * 200 * 2)

__global__ void __launch_bounds__(128) flash_hmma(const float* __restrict__ q,
                                                  const float* __restrict__ k,
                                                  const float* __restrict__ v,
                                                  float* __restrict__ out) {
    extern __shared__ __nv_bfloat16 fsm[];
    const int h = blockIdx.y, m0 = blockIdx.x * 64;
    const int tid = threadIdx.x, warp = tid >> 5, lane = tid & 31;
    const uint32_t smb = smem_u32(fsm);
    const uint32_t Qb = smb, Kb = smb + 25600, Vb = smb + 51200;
    const int lrow = lane & 15, lcol = (lane >> 4) << 3;
    const float QSCALE = 0.125f * LOG2E;

    for (int idx = tid; idx < 4096; idx += 128) {
        int r = idx >> 6, d = idx & 63;
        float val = q[(size_t)(m0 + r) * HD + h * 64 + d] * QSCALE;
        __nv_bfloat16 hi = __float2bfloat16(val);
        __nv_bfloat16 lo = __float2bfloat16(val - __bfloat162float(hi));
        __nv_bfloat16* Qr = fsm + r * 200;
        Qr[d] = hi; Qr[64 + d] = lo; Qr[128 + d] = hi;
    }

    float m_lo = -1e30f, m_hi = -1e30f, l_lo = 0.f, l_hi = 0.f;
    float O[8][4];
#pragma unroll
    for (int nt = 0; nt < 8; nt++)
#pragma unroll
        for (int t = 0; t < 4; t++) O[nt][t] = 0.f;

    for (int n0 = 0; n0 <= m0; n0 += 64) {
        __syncthreads();
        for (int idx = tid; idx < 4096; idx += 128) {
            int j = idx >> 6, d = idx & 63;
            float kv = k[(size_t)(n0 + j) * HD + h * 64 + d];
            __nv_bfloat16 khi = __float2bfloat16(kv);
            __nv_bfloat16 klo = __float2bfloat16(kv - __bfloat162float(khi));
            __nv_bfloat16* Kr = fsm + 12800 + j * 200;
            Kr[d] = khi; Kr[64 + d] = khi; Kr[128 + d] = klo;
            float vv = v[(size_t)(n0 + j) * HD + h * 64 + d];
            __nv_bfloat16 vhi = __float2bfloat16(vv);
            __nv_bfloat16 vlo = __float2bfloat16(vv - __bfloat162float(vhi));
            __nv_bfloat16* Vc = fsm + 25600 + d * 200;
            Vc[j] = vhi; Vc[64 + j] = vhi; Vc[128 + j] = vlo;
        }
        __syncthreads();

        float s[8][4];
#pragma unroll
        for (int nt = 0; nt < 8; nt++)
#pragma unroll
            for (int t = 0; t < 4; t++) s[nt][t] = 0.f;
#pragma unroll
        for (int ks = 0; ks < 12; ks++) {
            const uint32_t coff = (ks * 16 + lcol) * 2;
            uint32_t a[4], b[8][2];
            ldmx4(a[0], a[1], a[2], a[3], Qb + (uint32_t)(warp * 16 + lrow) * 400 + coff);
#pragma unroll
            for (int bp = 0; bp < 4; bp++) {
                uint32_t r0, r1, r2, r3;
                ldmx4(r0, r1, r2, r3, Kb + (uint32_t)(bp * 16 + lrow) * 400 + coff);
                b[bp * 2][0] = r0; b[bp * 2][1] = r2;
                b[bp * 2 + 1][0] = r1; b[bp * 2 + 1][1] = r3;
            }
#pragma unroll
            for (int nt = 0; nt < 8; nt++) mma_bf16(s[nt], a, b[nt]);
        }

        if (n0 == m0) {
            const int rl = m0 + warp * 16 + (lane >> 2);
            const int cb = n0 + (lane & 3) * 2;
#pragma unroll
            for (int nt = 0; nt < 8; nt++) {
                int c0 = cb + nt * 8, c1 = c0 + 1;
                if (c0 > rl) s[nt][0] = -1e30f;
                if (c1 > rl) s[nt][1] = -1e30f;
                if (c0 > rl + 8) s[nt][2] = -1e30f;
                if (c1 > rl + 8) s[nt][3] = -1e30f;
            }
        }

        float rmx_lo = -1e30f, rmx_hi = -1e30f;
#pragma unroll
        for (int nt = 0; nt < 8; nt++) {
            rmx_lo = fmaxf(rmx_lo, fmaxf(s[nt][0], s[nt][1]));
            rmx_hi = fmaxf(rmx_hi, fmaxf(s[nt][2], s[nt][3]));
        }
#pragma unroll
        for (int o = 1; o < 4; o <<= 1) {
            rmx_lo = fmaxf(rmx_lo, __shfl_xor_sync(0xffffffffu, rmx_lo, o));
            rmx_hi = fmaxf(rmx_hi, __shfl_xor_sync(0xffffffffu, rmx_hi, o));
        }
        float mn_lo = fmaxf(m_lo, rmx_lo), mn_hi = fmaxf(m_hi, rmx_hi);
        float corr_lo = exp2f(m_lo - mn_lo), corr_hi = exp2f(m_hi - mn_hi);
        m_lo = mn_lo; m_hi = mn_hi;
        float rs_lo = 0.f, rs_hi = 0.f;
#pragma unroll
        for (int nt = 0; nt < 8; nt++) {
            s[nt][0] = exp2f(s[nt][0] - mn_lo); rs_lo += s[nt][0];
            s[nt][1] = exp2f(s[nt][1] - mn_lo); rs_lo += s[nt][1];
            s[nt][2] = exp2f(s[nt][2] - mn_hi); rs_hi += s[nt][2];
            s[nt][3] = exp2f(s[nt][3] - mn_hi); rs_hi += s[nt][3];
        }
#pragma unroll
        for (int o = 1; o < 4; o <<= 1) {
            rs_lo += __shfl_xor_sync(0xffffffffu, rs_lo, o);
            rs_hi += __shfl_xor_sync(0xffffffffu, rs_hi, o);
        }
        l_lo = l_lo * corr_lo + rs_lo;
        l_hi = l_hi * corr_hi + rs_hi;
#pragma unroll
        for (int nt = 0; nt < 8; nt++) {
            O[nt][0] *= corr_lo; O[nt][1] *= corr_lo;
            O[nt][2] *= corr_hi; O[nt][3] *= corr_hi;
        }

        uint32_t phi[4][4], plo[4][4];
#pragma unroll
        for (int kk = 0; kk < 4; kk++) {
            const int n0t = 2 * kk, n1t = 2 * kk + 1;
            __nv_bfloat16 h00 = __float2bfloat16(s[n0t][0]);
            __nv_bfloat16 h01 = __float2bfloat16(s[n0t][1]);
            __nv_bfloat16 h02 = __float2bfloat16(s[n0t][2]);
            __nv_bfloat16 h03 = __float2bfloat16(s[n0t][3]);
            __nv_bfloat16 h10 = __float2bfloat16(s[n1t][0]);
            __nv_bfloat16 h11 = __float2bfloat16(s[n1t][1]);
            __nv_bfloat16 h12 = __float2bfloat16(s[n1t][2]);
            __nv_bfloat16 h13 = __float2bfloat16(s[n1t][3]);
            phi[kk][0] = pack2(h00, h01);
            phi[kk][1] = pack2(h02, h03);
            phi[kk][2] = pack2(h10, h11);
            phi[kk][3] = pack2(h12, h13);
            plo[kk][0] = pack2(__float2bfloat16(s[n0t][0] - __bfloat162float(h00)),
                               __float2bfloat16(s[n0t][1] - __bfloat162float(h01)));
            plo[kk][1] = pack2(__float2bfloat16(s[n0t][2] - __bfloat162float(h02)),
                               __float2bfloat16(s[n0t][3] - __bfloat162float(h03)));
            plo[kk][2] = pack2(__float2bfloat16(s[n1t][0] - __bfloat162float(h10)),
                               __float2bfloat16(s[n1t][1] - __bfloat162float(h11)));
            plo[kk][3] = pack2(__float2bfloat16(s[n1t][2] - __bfloat162float(h12)),
                               __float2bfloat16(s[n1t][3] - __bfloat162float(h13)));
        }

#pragma unroll
        for (int ks = 0; ks < 12; ks++) {
            const uint32_t* a = (ks < 4) ? phi[ks] : (ks < 8) ? plo[ks - 4] : phi[ks - 8];
            const uint32_t coff = (ks * 16 + lcol) * 2;
            uint32_t b[8][2];
#pragma unroll
            for (int bp = 0; bp < 4; bp++) {
                uint32_t r0, r1, r2, r3;
                ldmx4(r0, r1, r2, r3, Vb + (uint32_t)(bp * 16 + lrow) * 400 + coff);
                b[bp * 2][0] = r0; b[bp * 2][1] = r2;
                b[bp * 2 + 1][0] = r1; b[bp * 2 + 1][1] = r3;
            }
#pragma unroll
            for (int nt = 0; nt < 8; nt++) mma_bf16(O[nt], a, b[nt]);
        }
    }

    const float inv_lo = 1.f / l_lo, inv_hi = 1.f / l_hi;
    const int rl = m0 + warp * 16 + (lane >> 2);
#pragma unroll
    for (int nt = 0; nt < 8; nt++) {
        const int col = h * 64 + nt * 8 + (lane & 3) * 2;
        *(float2*)&out[(size_t)rl * HD + col] = make_float2(O[nt][0] * inv_lo, O[nt][1] * inv_lo);
        *(float2*)&out[(size_t)(rl + 8) * HD + col] = make_float2(O[nt][2] * inv_hi, O[nt][3] * inv_hi);
    }
}

// =====================================================================
// conversions
// =====================================================================
// fused 6-weight split (B pattern [hi,hi,lo]) into g_w6
__global__ void conv3w6(Src6 src, __nv_bfloat16* __restrict__ D) {
    const int w = blockIdx.y;
    const int idx = blockIdx.x * 256 + threadIdx.x;
    const int m = idx >> 10, k = idx & 1023;
    float x = src.s[w][idx];
    __nv_bfloat16 hi = __float2bfloat16(x);
    __nv_bfloat16 lo = __float2bfloat16(x - __bfloat162float(hi));
    __nv_bfloat16* row = D + (size_t)(w * 1024 + m) * 3072;
    row[k] = hi;
    row[1024 + k] = hi;
    row[2048 + k] = lo;
}

template<bool APAT>
__global__ void conv3(const float* __restrict__ S, __nv_bfloat16* __restrict__ D, int K) {
    const int idx = blockIdx.x * 256 + threadIdx.x;
    const int m = idx / K, k = idx - m * K;
    float x = S[idx];
    __nv_bfloat16 hi = __float2bfloat16(x);
    __nv_bfloat16 lo = __float2bfloat16(x - __bfloat162float(hi));
    const size_t ro = (size_t)m * 3 * K;
    D[ro + k] = hi;
    D[ro + K + k] = APAT ? lo : hi;
    D[ro + 2 * K + k] = APAT ? hi : lo;
}

__global__ void conv3T(const float* __restrict__ S, __nv_bfloat16* __restrict__ D,
                       int K, int N) {
    __shared__ float t[32][33];
    const int k0 = blockIdx.x * 32, n0 = blockIdx.y * 32;
    const int tx = threadIdx.x & 31, ty = threadIdx.x >> 5;
    for (int i = ty; i < 32; i += 8) t[i][tx] = S[(size_t)(k0 + i) * N + n0 + tx];
    __syncthreads();
    const int K3 = 3 * K;
    for (int i = ty; i < 32; i += 8) {
        const int n = n0 + i, k = k0 + tx;
        float x = t[tx][i];
        __nv_bfloat16 hi = __float2bfloat16(x);
        __nv_bfloat16 lo = __float2bfloat16(x - __bfloat162float(hi));
        D[(size_t)n * K3 + k] = hi;
        D[(size_t)n * K3 + K + k] = hi;
        D[(size_t)n * K3 + 2 * K + k] = lo;
    }
}

__global__ void conv3Tg(const float* __restrict__ S, __nv_bfloat16* __restrict__ D,
                        int K, int N) {
    __shared__ float t[32][33];
    const int k0 = blockIdx.x * 32, n0 = blockIdx.y * 32;
    const int tx = threadIdx.x & 31, ty = threadIdx.x >> 5;
    for (int i = ty; i < 32; i += 8) t[i][tx] = S[(size_t)(k0 + i) * N + n0 + tx];
    __syncthreads();
    const int K3 = 3 * K;
    for (int i = ty; i < 32; i += 8) {
        const int n = n0 + i, k = k0 + tx;
        const int g = k >> 6, j = k & 63;
        float x = t[tx][i];
        __nv_bfloat16 hi = __float2bfloat16(x);
        __nv_bfloat16 lo = __float2bfloat16(x - __bfloat162float(hi));
        __nv_bfloat16* base = D + (size_t)n * K3 + g * 192;
        base[j] = hi;
        base[64 + j] = hi;
        base[128 + j] = lo;
    }
}

// ---------------- branch 2: two-pass blocked scan ---------------------
__global__ void __launch_bounds__(256) krrp(const float* __restrict__ r,
                                            const float* __restrict__ rv,
                                            float* __restrict__ out) {
    __shared__ float w[2048];
    __shared__ float rl[2048];
    __shared__ float red[256];
    __shared__ float Sg[4][64];
    const int h = blockIdx.x, tid = threadIdx.x;
    const float Cc = 0.125f * LOG2E;
    float vloc[8], lm = -1e30f;
#pragma unroll
    for (int i = 0; i < 8; i++) {
        float vv = r[h * 2048 + tid * 8 + i] * Cc;
        vloc[i] = vv;
        lm = fmaxf(lm, vv);
    }
    red[tid] = lm; __syncthreads();
    for (int s = 128; s; s >>= 1) { if (tid < s) red[tid] = fmaxf(red[tid], red[tid + s]); __syncthreads(); }
    float M = red[0];
    __syncthreads();
    float run = 0.f, pre[8];
#pragma unroll
    for (int i = 0; i < 8; i++) {
        float e = exp2f(vloc[i] - M);
        w[tid * 8 + i] = e;
        run += e;
        pre[i] = run;
    }
    red[tid] = run; __syncthreads();
    for (int s = 1; s < 256; s <<= 1) {
        float t = (tid >= s) ? red[tid - s] : 0.f;
        __syncthreads();
        red[tid] += t;
        __syncthreads();
    }
    float excl = red[tid] - run;
#pragma unroll
    for (int i = 0; i < 8; i++) rl[tid * 8 + i] = 1.f / (excl + pre[i]);
    __syncthreads();

    // pass 1: group partial sums
    const int g = tid >> 6, d = tid & 63;
    const int t0 = g * 512, t1 = t0 + 512;
    const float* rp = rv + h * 64 + d;
    float s1 = 0.f;
#pragma unroll 4
    for (int t = t0; t < t1; t++) s1 += w[t] * rp[(size_t)t * 1024];
    Sg[g][d] = s1;
    __syncthreads();
    float base = 0.f;
#pragma unroll
    for (int gg = 0; gg < 3; gg++)
        if (gg < g) base += Sg[gg][d];
    // pass 2: emit
    float acc = base;
    float* op = out + h * 64 + d;
#pragma unroll 4
    for (int t = t0; t < t1; t++) {
        acc += w[t] * rp[(size_t)t * 1024];
        op[(size_t)t * 1024] = acc * rl[t];
    }
}

// ---------------- branch 3 probabilities -> grouped split bf16 -------
__global__ void __launch_bounds__(256) kjp3(const float* __restrict__ sc,
                                            __nv_bfloat16* __restrict__ P3) {
    __shared__ float sk[2048];
    __shared__ float se[2048];
    __shared__ float red[256];
    const int qq = blockIdx.x, tid = threadIdx.x;
    for (int t = tid; t < 2048; t += 256) sk[t] = sc[t];
    __syncthreads();
    const float sq = sk[qq] * LOG2E;
    float lm = -1e30f;
    for (int t = tid; t <= qq; t += 256) lm = fmaxf(lm, sq * sk[t]);
    red[tid] = lm; __syncthreads();
    for (int s = 128; s; s >>= 1) { if (tid < s) red[tid] = fmaxf(red[tid], red[tid + s]); __syncthreads(); }
    float M = red[0];
    __syncthreads();
    float ls = 0.f;
    for (int t = tid; t <= qq; t += 256) {
        float e = exp2f(sq * sk[t] - M);
        se[t] = e;
        ls += e;
    }
    red[tid] = ls; __syncthreads();
    for (int s = 128; s; s >>= 1) { if (tid < s) red[tid] += red[tid + s]; __syncthreads(); }
    const float rinv = 1.f / red[0];
    __nv_bfloat16* Prow = P3 + (size_t)qq * 6144;
    for (int t = tid; t < 2048; t += 256) {
        float p = (t <= qq) ? se[t] * rinv : 0.f;
        __nv_bfloat16 hi = __float2bfloat16(p);
        __nv_bfloat16 lo = __float2bfloat16(p - __bfloat162float(hi));
        const int g = t >> 6, j = t & 63;
        __nv_bfloat16* base = Prow + g * 192;
        base[j] = hi;
        base[64 + j] = lo;
        base[128 + j] = hi;
    }
}

// ---------------- r[h,t] ----------------------------------------------
__global__ void kr(const float* __restrict__ x, const float* __restrict__ wr,
                   float* __restrict__ r) {
    const int h = blockIdx.y;
    const int t = blockIdx.x * 128 + threadIdx.x;
    const float* wp = wr + (size_t)h * EE * TT + t;
    const float* xp = x + (size_t)t * EE;
    float acc = 0.f;
#pragma unroll 8
    for (int e = 0; e < EE; e++) acc += xp[e] * wp[(size_t)e * TT];
    r[h * TT + t] = acc;
}

// ---------------- scores ----------------------------------------------
__global__ void kscores(const float* __restrict__ x, const float* __restrict__ eb,
                        float* __restrict__ sc) {
    const int t = blockIdx.x;
    const float* xp = x + (size_t)t * EE;
    const float* ep = eb + (size_t)t * EE;
    float a = 0.f;
    for (int e = threadIdx.x; e < EE; e += 256) a += xp[e] * ep[e];
#pragma unroll
    for (int o = 16; o > 0; o >>= 1) a += __shfl_xor_sync(0xffffffffu, a, o);
    __shared__ float red[8];
    if ((threadIdx.x & 31) == 0) red[threadIdx.x >> 5] = a;
    __syncthreads();
    if (threadIdx.x == 0) {
        float s = 0.f;
#pragma unroll
        for (int w = 0; w < 8; w++) s += red[w];
        sc[t] = s * (1.f / 32.f);
    }
}

// ---------------- gated combine -> split bf16 (A pattern) -------------
__global__ void kcombine3(const float* __restrict__ o1, const float* __restrict__ o2,
                          const float* __restrict__ o3, const float* __restrict__ gate,
                          __nv_bfloat16* __restrict__ comb3) {
    const int idx = blockIdx.x * 256 + threadIdx.x;
    const int c = idx & (HD - 1);
    const int h = c >> 6;
    float g0 = gate[h * 3 + 0], g1 = gate[h * 3 + 1], g2 = gate[h * 3 + 2];
    float mx = fmaxf(g0, fmaxf(g1, g2));
    float e0 = __expf(g0 - mx), e1 = __expf(g1 - mx), e2 = __expf(g2 - mx);
    float inv = 1.f / (e0 + e1 + e2);
    float val = (e0 * o1[idx] + e1 * o2[idx] + e2 * o3[idx]) * inv;
    __nv_bfloat16 hi = __float2bfloat16(val);
    __nv_bfloat16 lo = __float2bfloat16(val - __bfloat162float(hi));
    const int m = idx >> 10, k = idx & 1023;
    __nv_bfloat16* row = comb3 + (size_t)m * 3072;
    row[k] = hi;
    row[1024 + k] = lo;
    row[2048 + k] = hi;
}

// ---------------- launch ------------------------------------------------
extern "C" void kernel_launch(void* const* d_in, const int* in_sizes, int n_in,
                              void* d_out, int out_size) {
    const float* x    = (const float*)d_in[0];
    const float* wq   = (const float*)d_in[1];
    const float* wk   = (const float*)d_in[2];
    const float* wv   = (const float*)d_in[3];
    const float* wr   = (const float*)d_in[4];
    const float* wvr  = (const float*)d_in[5];
    const float* wj   = (const float*)d_in[6];
    const float* gate = (const float*)d_in[7];
    const float* wo   = (const float*)d_in[8];
    float* out = (float*)d_out;

    float *q, *k, *v, *rv, *echo, *eb, *r, *sc, *o1, *o2, *o3;
    __nv_bfloat16 *x3, *w6, *wjT3, *echoA3, *echoT3, *P3, *comb3;
    cudaGetSymbolAddress((void**)&q, g_q);
    cudaGetSymbolAddress((void**)&k, g_k);
    cudaGetSymbolAddress((void**)&v, g_v);
    cudaGetSymbolAddress((void**)&rv, g_rv);
    cudaGetSymbolAddress((void**)&echo, g_echo);
    cudaGetSymbolAddress((void**)&eb, g_eb);
    cudaGetSymbolAddress((void**)&r, g_r);
    cudaGetSymbolAddress((void**)&sc, g_sc);
    cudaGetSymbolAddress((void**)&o1, g_o1);
    cudaGetSymbolAddress((void**)&o2, g_o2);
    cudaGetSymbolAddress((void**)&o3, g_o3);
    cudaGetSymbolAddress((void**)&x3, g_x3);
    cudaGetSymbolAddress((void**)&w6, g_w6);
    cudaGetSymbolAddress((void**)&wjT3, g_wjT3);
    cudaGetSymbolAddress((void**)&echoA3, g_echoA3);
    cudaGetSymbolAddress((void**)&echoT3, g_echoT3);
    cudaGetSymbolAddress((void**)&P3, g_P3);
    cudaGetSymbolAddress((void**)&comb3, g_comb3);

    cudaFuncSetAttribute(hmma_gemm<false>, cudaFuncAttributeMaxDynamicSharedMemorySize, HMMA_SMEM);
    cudaFuncSetAttribute(hmma_gemm<true>, cudaFuncAttributeMaxDynamicSharedMemorySize, HMMA_SMEM);
    cudaFuncSetAttribute(hmma_gemm5, cudaFuncAttributeMaxDynamicSharedMemorySize, HMMA_SMEM);
    cudaFuncSetAttribute(flash_hmma, cudaFuncAttributeMaxDynamicSharedMemorySize, FL_SMEM);

    dim3 mgrid(8, 16);
    const int X = 2048 * 1024 / 256;

    // fused weight conversion: [wq|wk|wv|wvr|wj|wo] -> g_w6
    Src6 src{{wq, wk, wv, wvr, wj, wo}};
    conv3w6<<<dim3(4096, 6), 256>>>(src, w6);
    conv3T<<<dim3(32, 32), 256>>>(wj, wjT3, 1024, 1024);
    conv3<true><<<X, 256>>>(x, x3, 1024);

    // batched 5-way projection (N = 5120 -> 640 CTAs)
    Out5 outs{{q, k, v, rv, echo}};
    hmma_gemm5<<<dim3(40, 16), 256, HMMA_SMEM>>>(x3, w6, outs, 3072);

    // echo_back = echo @ wj
    conv3<true><<<X, 256>>>(echo, echoA3, 1024);
    conv3Tg<<<dim3(64, 32), 256>>>(echo, echoT3, 2048, 1024);
    hmma_gemm<false><<<mgrid, 256, HMMA_SMEM>>>(echoA3, wjT3, eb, 3072);

    kscores<<<TT, 256>>>(x, eb, sc);
    kr<<<dim3(16, 16), 128>>>(x, wr, r);

    kjp3<<<TT, 256>>>(sc, P3);
    flash_hmma<<<dim3(32, 16), 128, FL_SMEM>>>(q, k, v, o1);
    krrp<<<16, 256>>>(r, rv, o2);
    hmma_gemm<true><<<mgrid, 256, HMMA_SMEM>>>(P3, echoT3, o3, 6144);

    kcombine3<<<(TT * HD) / 256, 256>>>(o1, o2, o3, gate, comb3);
    hmma_gemm<false><<<mgrid, 256, HMMA_SMEM>>>(comb3, w6 + (size_t)5 * 1024 * 3072, out, 3072);
}

// round 8
// speedup vs baseline: 4.0140x; 1.2230x over previous
#include <cuda_runtime.h>
#include <cuda_bf16.h>
#include <cstdint>

#define TT 2048
#define EE 1024
#define HH 16
#define DD 64
#define HD 1024
#define LOG2E 1.4426950408889634f

// ---------------- fp32 scratch ----------------
__device__ __align__(16) float g_q[TT * HD];
__device__ __align__(16) float g_k[TT * HD];
__device__ __align__(16) float g_v[TT * HD];
__device__ __align__(16) float g_rv[TT * HD];
__device__ __align__(16) float g_echo[TT * EE];
__device__ __align__(16) float g_eb[TT * EE];
__device__ __align__(16) float g_r[HH * TT];
__device__ __align__(16) float g_sc[TT];
__device__ __align__(16) float g_o1[TT * HD];
__device__ __align__(16) float g_o2[TT * HD];
__device__ __align__(16) float g_o3[TT * EE];

// ---------------- bf16 triple-split scratch ----------------
__device__ __align__(16) __nv_bfloat16 g_x3[TT * 3072];
__device__ __align__(16) __nv_bfloat16 g_w6[6144 * 3072];
__device__ __align__(16) __nv_bfloat16 g_wjT3[1024 * 3072];
__device__ __align__(16) __nv_bfloat16 g_echoA3[TT * 3072];
__device__ __align__(16) __nv_bfloat16 g_echoT3[1024 * 6144];
__device__ __align__(16) __nv_bfloat16 g_P3[TT * 6144];
__device__ __align__(16) __nv_bfloat16 g_comb3[TT * 3072];

struct Src6 { const float* s[6]; };
struct Out5 { float* p[5]; };

// ============================ PTX helpers ============================
__device__ __forceinline__ uint32_t smem_u32(const void* p) {
    uint32_t a;
    asm("{ .reg .u64 t; cvta.to.shared.u64 t, %1; cvt.u32.u64 %0, t; }" : "=r"(a) : "l"(p));
    return a;
}
__device__ __forceinline__ void cp_async16(uint32_t s, const void* g) {
    asm volatile("cp.async.cg.shared.global [%0], [%1], 16;" :: "r"(s), "l"(g));
}
__device__ __forceinline__ void cp_commit() { asm volatile("cp.async.commit_group;"); }
template<int N> __device__ __forceinline__ void cp_wait() {
    asm volatile("cp.async.wait_group %0;" :: "n"(N) : "memory");
}
__device__ __forceinline__ void ldmx4(uint32_t& r0, uint32_t& r1, uint32_t& r2, uint32_t& r3,
                                      uint32_t addr) {
    asm volatile("ldmatrix.sync.aligned.m8n8.x4.shared.b16 {%0,%1,%2,%3}, [%4];"
                 : "=r"(r0), "=r"(r1), "=r"(r2), "=r"(r3) : "r"(addr));
}
__device__ __forceinline__ void mma_bf16(float* d, const uint32_t* a, const uint32_t* b) {
    asm volatile("mma.sync.aligned.m16n8k16.row.col.f32.bf16.bf16.f32 "
                 "{%0,%1,%2,%3}, {%4,%5,%6,%7}, {%8,%9}, {%0,%1,%2,%3};"
                 : "+f"(d[0]), "+f"(d[1]), "+f"(d[2]), "+f"(d[3])
                 : "r"(a[0]), "r"(a[1]), "r"(a[2]), "r"(a[3]), "r"(b[0]), "r"(b[1]));
}
__device__ __forceinline__ uint32_t pack2(__nv_bfloat16 a, __nv_bfloat16 b) {
    __nv_bfloat162 t(a, b);
    return *reinterpret_cast<uint32_t*>(&t);
}

#define HSTAGE_ELE 10240
#define HMMA_SMEM (4 * HSTAGE_ELE * 2)

// =====================================================================
// Shared HMMA mainloop body
// =====================================================================
template<bool CAUSAL>
__device__ __forceinline__ void hmma_body(const __nv_bfloat16* __restrict__ A,
                                          const __nv_bfloat16* __restrict__ B,
                                          float acc[2][8][4],
                                          int m0, int n0, int K3,
                                          __nv_bfloat16* sm) {
    const int tid = threadIdx.x;
    const int kcols = CAUSAL ? ((m0 + 128) * 3 < K3 ? (m0 + 128) * 3 : K3) : K3;
    const int nchunk = kcols >> 5;
    const int warp = tid >> 5, lane = tid & 31;
    const int wm = warp & 3, wn = warp >> 2;
    const uint32_t smb = smem_u32(sm);

    auto load_stage = [&](int cc, int s) {
        const uint32_t ab = smb + s * (HSTAGE_ELE * 2);
        const uint32_t bb = ab + 10240;
        const int k0 = cc * 32;
#pragma unroll
        for (int i = 0; i < 2; i++) {
            int c = tid * 2 + i;
            int row = c >> 2, cg = c & 3;
            cp_async16(ab + row * 80 + cg * 16, A + (size_t)(m0 + row) * K3 + k0 + cg * 8);
            cp_async16(bb + row * 80 + cg * 16, B + (size_t)(n0 + row) * K3 + k0 + cg * 8);
        }
        cp_commit();
    };

    load_stage(0, 0);
    if (1 < nchunk) load_stage(1, 1); else cp_commit();
    if (2 < nchunk) load_stage(2, 2); else cp_commit();

    const int lrow = lane & 15;
    const int lcol = (lane >> 4) << 3;

    for (int c = 0; c < nchunk; c++) {
        cp_wait<2>();
        __syncthreads();
        if (c + 3 < nchunk) load_stage(c + 3, (c + 3) & 3); else cp_commit();

        const uint32_t ab = smb + (c & 3) * (HSTAGE_ELE * 2);
        const uint32_t bb = ab + 10240;
#pragma unroll
        for (int ks = 0; ks < 2; ks++) {
            const uint32_t coff = (ks * 16 + lcol) * 2;
            uint32_t a[2][4], b[8][2];
#pragma unroll
            for (int mt = 0; mt < 2; mt++)
                ldmx4(a[mt][0], a[mt][1], a[mt][2], a[mt][3],
                      ab + (uint32_t)(wm * 32 + mt * 16 + lrow) * 80 + coff);
#pragma unroll
            for (int bp = 0; bp < 4; bp++) {
                uint32_t r0, r1, r2, r3;
                ldmx4(r0, r1, r2, r3,
                      bb + (uint32_t)(wn * 64 + bp * 16 + lrow) * 80 + coff);
                b[bp * 2][0] = r0; b[bp * 2][1] = r2;
                b[bp * 2 + 1][0] = r1; b[bp * 2 + 1][1] = r3;
            }
#pragma unroll
            for (int mt = 0; mt < 2; mt++)
#pragma unroll
                for (int nt = 0; nt < 8; nt++) mma_bf16(acc[mt][nt], a[mt], b[nt]);
        }
        __syncthreads();
    }
}

__device__ __forceinline__ void hmma_epi(float acc[2][8][4], float* C, int m0, int ncol0) {
    const int lane = threadIdx.x & 31, warp = threadIdx.x >> 5;
    const int wm = warp & 3, wn = warp >> 2;
    const int erow = lane >> 2, ecol = (lane & 3) * 2;
#pragma unroll
    for (int mt = 0; mt < 2; mt++) {
        const int r0 = m0 + wm * 32 + mt * 16 + erow;
#pragma unroll
        for (int nt = 0; nt < 8; nt++) {
            const int cc = ncol0 + wn * 64 + nt * 8 + ecol;
            *(float2*)&C[(size_t)r0 * 1024 + cc] = make_float2(acc[mt][nt][0], acc[mt][nt][1]);
            *(float2*)&C[(size_t)(r0 + 8) * 1024 + cc] = make_float2(acc[mt][nt][2], acc[mt][nt][3]);
        }
    }
}

template<bool CAUSAL>
__global__ void __launch_bounds__(256, 2) hmma_gemm(const __nv_bfloat16* __restrict__ A,
                                                    const __nv_bfloat16* __restrict__ B,
                                                    float* __restrict__ C, int K3) {
    extern __shared__ __nv_bfloat16 sm[];
    float acc[2][8][4];
#pragma unroll
    for (int i = 0; i < 2; i++)
#pragma unroll
        for (int j = 0; j < 8; j++)
#pragma unroll
            for (int t = 0; t < 4; t++) acc[i][j][t] = 0.f;
    const int m0 = blockIdx.y * 128, n0 = blockIdx.x * 128;
    hmma_body<CAUSAL>(A, B, acc, m0, n0, K3, sm);
    hmma_epi(acc, C, m0, n0);
}

__global__ void __launch_bounds__(256, 2) hmma_gemm5(const __nv_bfloat16* __restrict__ A,
                                                     const __nv_bfloat16* __restrict__ B,
                                                     Out5 outs, int K3) {
    extern __shared__ __nv_bfloat16 sm[];
    float acc[2][8][4];
#pragma unroll
    for (int i = 0; i < 2; i++)
#pragma unroll
        for (int j = 0; j < 8; j++)
#pragma unroll
            for (int t = 0; t < 4; t++) acc[i][j][t] = 0.f;
    const int m0 = blockIdx.y * 128, n0 = blockIdx.x * 128;
    hmma_body<false>(A, B, acc, m0, n0, K3, sm);
    hmma_epi(acc, outs.p[blockIdx.x >> 3], m0, (blockIdx.x & 7) * 128);
}

// =====================================================================
// branch 1: fused HMMA flash attention
// =====================================================================
#define FL_SMEM (3 * 64 * 200 * 2)

__global__ void __launch_bounds__(128) flash_hmma(const float* __restrict__ q,
                                                  const float* __restrict__ k,
                                                  const float* __restrict__ v,
                                                  float* __restrict__ out) {
    extern __shared__ __nv_bfloat16 fsm[];
    const int h = blockIdx.y, m0 = blockIdx.x * 64;
    const int tid = threadIdx.x, warp = tid >> 5, lane = tid & 31;
    const uint32_t smb = smem_u32(fsm);
    const uint32_t Qb = smb, Kb = smb + 25600, Vb = smb + 51200;
    const int lrow = lane & 15, lcol = (lane >> 4) << 3;
    const float QSCALE = 0.125f * LOG2E;

    for (int idx = tid; idx < 4096; idx += 128) {
        int r = idx >> 6, d = idx & 63;
        float val = q[(size_t)(m0 + r) * HD + h * 64 + d] * QSCALE;
        __nv_bfloat16 hi = __float2bfloat16(val);
        __nv_bfloat16 lo = __float2bfloat16(val - __bfloat162float(hi));
        __nv_bfloat16* Qr = fsm + r * 200;
        Qr[d] = hi; Qr[64 + d] = lo; Qr[128 + d] = hi;
    }

    float m_lo = -1e30f, m_hi = -1e30f, l_lo = 0.f, l_hi = 0.f;
    float O[8][4];
#pragma unroll
    for (int nt = 0; nt < 8; nt++)
#pragma unroll
        for (int t = 0; t < 4; t++) O[nt][t] = 0.f;

    for (int n0 = 0; n0 <= m0; n0 += 64) {
        __syncthreads();
        for (int idx = tid; idx < 4096; idx += 128) {
            int j = idx >> 6, d = idx & 63;
            float kv = k[(size_t)(n0 + j) * HD + h * 64 + d];
            __nv_bfloat16 khi = __float2bfloat16(kv);
            __nv_bfloat16 klo = __float2bfloat16(kv - __bfloat162float(khi));
            __nv_bfloat16* Kr = fsm + 12800 + j * 200;
            Kr[d] = khi; Kr[64 + d] = khi; Kr[128 + d] = klo;
            float vv = v[(size_t)(n0 + j) * HD + h * 64 + d];
            __nv_bfloat16 vhi = __float2bfloat16(vv);
            __nv_bfloat16 vlo = __float2bfloat16(vv - __bfloat162float(vhi));
            __nv_bfloat16* Vc = fsm + 25600 + d * 200;
            Vc[j] = vhi; Vc[64 + j] = vhi; Vc[128 + j] = vlo;
        }
        __syncthreads();

        float s[8][4];
#pragma unroll
        for (int nt = 0; nt < 8; nt++)
#pragma unroll
            for (int t = 0; t < 4; t++) s[nt][t] = 0.f;
#pragma unroll
        for (int ks = 0; ks < 12; ks++) {
            const uint32_t coff = (ks * 16 + lcol) * 2;
            uint32_t a[4], b[8][2];
            ldmx4(a[0], a[1], a[2], a[3], Qb + (uint32_t)(warp * 16 + lrow) * 400 + coff);
#pragma unroll
            for (int bp = 0; bp < 4; bp++) {
                uint32_t r0, r1, r2, r3;
                ldmx4(r0, r1, r2, r3, Kb + (uint32_t)(bp * 16 + lrow) * 400 + coff);
                b[bp * 2][0] = r0; b[bp * 2][1] = r2;
                b[bp * 2 + 1][0] = r1; b[bp * 2 + 1][1] = r3;
            }
#pragma unroll
            for (int nt = 0; nt < 8; nt++) mma_bf16(s[nt], a, b[nt]);
        }

        if (n0 == m0) {
            const int rl = m0 + warp * 16 + (lane >> 2);
            const int cb = n0 + (lane & 3) * 2;
#pragma unroll
            for (int nt = 0; nt < 8; nt++) {
                int c0 = cb + nt * 8, c1 = c0 + 1;
                if (c0 > rl) s[nt][0] = -1e30f;
                if (c1 > rl) s[nt][1] = -1e30f;
                if (c0 > rl + 8) s[nt][2] = -1e30f;
                if (c1 > rl + 8) s[nt][3] = -1e30f;
            }
        }

        float rmx_lo = -1e30f, rmx_hi = -1e30f;
#pragma unroll
        for (int nt = 0; nt < 8; nt++) {
            rmx_lo = fmaxf(rmx_lo, fmaxf(s[nt][0], s[nt][1]));
            rmx_hi = fmaxf(rmx_hi, fmaxf(s[nt][2], s[nt][3]));
        }
#pragma unroll
        for (int o = 1; o < 4; o <<= 1) {
            rmx_lo = fmaxf(rmx_lo, __shfl_xor_sync(0xffffffffu, rmx_lo, o));
            rmx_hi = fmaxf(rmx_hi, __shfl_xor_sync(0xffffffffu, rmx_hi, o));
        }
        float mn_lo = fmaxf(m_lo, rmx_lo), mn_hi = fmaxf(m_hi, rmx_hi);
        float corr_lo = exp2f(m_lo - mn_lo), corr_hi = exp2f(m_hi - mn_hi);
        m_lo = mn_lo; m_hi = mn_hi;
        float rs_lo = 0.f, rs_hi = 0.f;
#pragma unroll
        for (int nt = 0; nt < 8; nt++) {
            s[nt][0] = exp2f(s[nt][0] - mn_lo); rs_lo += s[nt][0];
            s[nt][1] = exp2f(s[nt][1] - mn_lo); rs_lo += s[nt][1];
            s[nt][2] = exp2f(s[nt][2] - mn_hi); rs_hi += s[nt][2];
            s[nt][3] = exp2f(s[nt][3] - mn_hi); rs_hi += s[nt][3];
        }
#pragma unroll
        for (int o = 1; o < 4; o <<= 1) {
            rs_lo += __shfl_xor_sync(0xffffffffu, rs_lo, o);
            rs_hi += __shfl_xor_sync(0xffffffffu, rs_hi, o);
        }
        l_lo = l_lo * corr_lo + rs_lo;
        l_hi = l_hi * corr_hi + rs_hi;
#pragma unroll
        for (int nt = 0; nt < 8; nt++) {
            O[nt][0] *= corr_lo; O[nt][1] *= corr_lo;
            O[nt][2] *= corr_hi; O[nt][3] *= corr_hi;
        }

        uint32_t phi[4][4], plo[4][4];
#pragma unroll
        for (int kk = 0; kk < 4; kk++) {
            const int n0t = 2 * kk, n1t = 2 * kk + 1;
            __nv_bfloat16 h00 = __float2bfloat16(s[n0t][0]);
            __nv_bfloat16 h01 = __float2bfloat16(s[n0t][1]);
            __nv_bfloat16 h02 = __float2bfloat16(s[n0t][2]);
            __nv_bfloat16 h03 = __float2bfloat16(s[n0t][3]);
            __nv_bfloat16 h10 = __float2bfloat16(s[n1t][0]);
            __nv_bfloat16 h11 = __float2bfloat16(s[n1t][1]);
            __nv_bfloat16 h12 = __float2bfloat16(s[n1t][2]);
            __nv_bfloat16 h13 = __float2bfloat16(s[n1t][3]);
            phi[kk][0] = pack2(h00, h01);
            phi[kk][1] = pack2(h02, h03);
            phi[kk][2] = pack2(h10, h11);
            phi[kk][3] = pack2(h12, h13);
            plo[kk][0] = pack2(__float2bfloat16(s[n0t][0] - __bfloat162float(h00)),
                               __float2bfloat16(s[n0t][1] - __bfloat162float(h01)));
            plo[kk][1] = pack2(__float2bfloat16(s[n0t][2] - __bfloat162float(h02)),
                               __float2bfloat16(s[n0t][3] - __bfloat162float(h03)));
            plo[kk][2] = pack2(__float2bfloat16(s[n1t][0] - __bfloat162float(h10)),
                               __float2bfloat16(s[n1t][1] - __bfloat162float(h11)));
            plo[kk][3] = pack2(__float2bfloat16(s[n1t][2] - __bfloat162float(h12)),
                               __float2bfloat16(s[n1t][3] - __bfloat162float(h13)));
        }

#pragma unroll
        for (int ks = 0; ks < 12; ks++) {
            const uint32_t* a = (ks < 4) ? phi[ks] : (ks < 8) ? plo[ks - 4] : phi[ks - 8];
            const uint32_t coff = (ks * 16 + lcol) * 2;
            uint32_t b[8][2];
#pragma unroll
            for (int bp = 0; bp < 4; bp++) {
                uint32_t r0, r1, r2, r3;
                ldmx4(r0, r1, r2, r3, Vb + (uint32_t)(bp * 16 + lrow) * 400 + coff);
                b[bp * 2][0] = r0; b[bp * 2][1] = r2;
                b[bp * 2 + 1][0] = r1; b[bp * 2 + 1][1] = r3;
            }
#pragma unroll
            for (int nt = 0; nt < 8; nt++) mma_bf16(O[nt], a, b[nt]);
        }
    }

    const float inv_lo = 1.f / l_lo, inv_hi = 1.f / l_hi;
    const int rl = m0 + warp * 16 + (lane >> 2);
#pragma unroll
    for (int nt = 0; nt < 8; nt++) {
        const int col = h * 64 + nt * 8 + (lane & 3) * 2;
        *(float2*)&out[(size_t)rl * HD + col] = make_float2(O[nt][0] * inv_lo, O[nt][1] * inv_lo);
        *(float2*)&out[(size_t)(rl + 8) * HD + col] = make_float2(O[nt][2] * inv_hi, O[nt][3] * inv_hi);
    }
}

// =====================================================================
// conversions
// =====================================================================
__global__ void conv3w6(Src6 src, __nv_bfloat16* __restrict__ D) {
    const int w = blockIdx.y;
    const int idx = blockIdx.x * 256 + threadIdx.x;
    const int m = idx >> 10, k = idx & 1023;
    float x = src.s[w][idx];
    __nv_bfloat16 hi = __float2bfloat16(x);
    __nv_bfloat16 lo = __float2bfloat16(x - __bfloat162float(hi));
    __nv_bfloat16* row = D + (size_t)(w * 1024 + m) * 3072;
    row[k] = hi;
    row[1024 + k] = hi;
    row[2048 + k] = lo;
}

template<bool APAT>
__global__ void conv3(const float* __restrict__ S, __nv_bfloat16* __restrict__ D, int K) {
    const int idx = blockIdx.x * 256 + threadIdx.x;
    const int m = idx / K, k = idx - m * K;
    float x = S[idx];
    __nv_bfloat16 hi = __float2bfloat16(x);
    __nv_bfloat16 lo = __float2bfloat16(x - __bfloat162float(hi));
    const size_t ro = (size_t)m * 3 * K;
    D[ro + k] = hi;
    D[ro + K + k] = APAT ? lo : hi;
    D[ro + 2 * K + k] = APAT ? hi : lo;
}

__global__ void conv3T(const float* __restrict__ S, __nv_bfloat16* __restrict__ D,
                       int K, int N) {
    __shared__ float t[32][33];
    const int k0 = blockIdx.x * 32, n0 = blockIdx.y * 32;
    const int tx = threadIdx.x & 31, ty = threadIdx.x >> 5;
    for (int i = ty; i < 32; i += 8) t[i][tx] = S[(size_t)(k0 + i) * N + n0 + tx];
    __syncthreads();
    const int K3 = 3 * K;
    for (int i = ty; i < 32; i += 8) {
        const int n = n0 + i, k = k0 + tx;
        float x = t[tx][i];
        __nv_bfloat16 hi = __float2bfloat16(x);
        __nv_bfloat16 lo = __float2bfloat16(x - __bfloat162float(hi));
        D[(size_t)n * K3 + k] = hi;
        D[(size_t)n * K3 + K + k] = hi;
        D[(size_t)n * K3 + 2 * K + k] = lo;
    }
}

__global__ void conv3Tg(const float* __restrict__ S, __nv_bfloat16* __restrict__ D,
                        int K, int N) {
    __shared__ float t[32][33];
    const int k0 = blockIdx.x * 32, n0 = blockIdx.y * 32;
    const int tx = threadIdx.x & 31, ty = threadIdx.x >> 5;
    for (int i = ty; i < 32; i += 8) t[i][tx] = S[(size_t)(k0 + i) * N + n0 + tx];
    __syncthreads();
    const int K3 = 3 * K;
    for (int i = ty; i < 32; i += 8) {
        const int n = n0 + i, k = k0 + tx;
        const int g = k >> 6, j = k & 63;
        float x = t[tx][i];
        __nv_bfloat16 hi = __float2bfloat16(x);
        __nv_bfloat16 lo = __float2bfloat16(x - __bfloat162float(hi));
        __nv_bfloat16* base = D + (size_t)n * K3 + g * 192;
        base[j] = hi;
        base[64 + j] = hi;
        base[128 + j] = lo;
    }
}

// ---------------- branch 2: two-pass blocked scan ---------------------
__global__ void __launch_bounds__(256) krrp(const float* __restrict__ r,
                                            const float* __restrict__ rv,
                                            float* __restrict__ out) {
    __shared__ float w[2048];
    __shared__ float rl[2048];
    __shared__ float red[256];
    __shared__ float Sg[4][64];
    const int h = blockIdx.x, tid = threadIdx.x;
    const float Cc = 0.125f * LOG2E;
    float vloc[8], lm = -1e30f;
#pragma unroll
    for (int i = 0; i < 8; i++) {
        float vv = r[h * 2048 + tid * 8 + i] * Cc;
        vloc[i] = vv;
        lm = fmaxf(lm, vv);
    }
    red[tid] = lm; __syncthreads();
    for (int s = 128; s; s >>= 1) { if (tid < s) red[tid] = fmaxf(red[tid], red[tid + s]); __syncthreads(); }
    float M = red[0];
    __syncthreads();
    float run = 0.f, pre[8];
#pragma unroll
    for (int i = 0; i < 8; i++) {
        float e = exp2f(vloc[i] - M);
        w[tid * 8 + i] = e;
        run += e;
        pre[i] = run;
    }
    red[tid] = run; __syncthreads();
    for (int s = 1; s < 256; s <<= 1) {
        float t = (tid >= s) ? red[tid - s] : 0.f;
        __syncthreads();
        red[tid] += t;
        __syncthreads();
    }
    float excl = red[tid] - run;
#pragma unroll
    for (int i = 0; i < 8; i++) rl[tid * 8 + i] = 1.f / (excl + pre[i]);
    __syncthreads();

    const int g = tid >> 6, d = tid & 63;
    const int t0 = g * 512, t1 = t0 + 512;
    const float* rp = rv + h * 64 + d;
    float s1 = 0.f;
#pragma unroll 4
    for (int t = t0; t < t1; t++) s1 += w[t] * rp[(size_t)t * 1024];
    Sg[g][d] = s1;
    __syncthreads();
    float base = 0.f;
#pragma unroll
    for (int gg = 0; gg < 3; gg++)
        if (gg < g) base += Sg[gg][d];
    float acc = base;
    float* op = out + h * 64 + d;
#pragma unroll 4
    for (int t = t0; t < t1; t++) {
        acc += w[t] * rp[(size_t)t * 1024];
        op[(size_t)t * 1024] = acc * rl[t];
    }
}

// ---------------- branch 3 probabilities -> grouped split bf16 -------
__global__ void __launch_bounds__(256) kjp3(const float* __restrict__ sc,
                                            __nv_bfloat16* __restrict__ P3) {
    __shared__ float sk[2048];
    __shared__ float se[2048];
    __shared__ float red[256];
    const int qq = blockIdx.x, tid = threadIdx.x;
    for (int t = tid; t < 2048; t += 256) sk[t] = sc[t];
    __syncthreads();
    const float sq = sk[qq] * LOG2E;
    float lm = -1e30f;
    for (int t = tid; t <= qq; t += 256) lm = fmaxf(lm, sq * sk[t]);
    red[tid] = lm; __syncthreads();
    for (int s = 128; s; s >>= 1) { if (tid < s) red[tid] = fmaxf(red[tid], red[tid + s]); __syncthreads(); }
    float M = red[0];
    __syncthreads();
    float ls = 0.f;
    for (int t = tid; t <= qq; t += 256) {
        float e = exp2f(sq * sk[t] - M);
        se[t] = e;
        ls += e;
    }
    red[tid] = ls; __syncthreads();
    for (int s = 128; s; s >>= 1) { if (tid < s) red[tid] += red[tid + s]; __syncthreads(); }
    const float rinv = 1.f / red[0];
    __nv_bfloat16* Prow = P3 + (size_t)qq * 6144;
    for (int t = tid; t < 2048; t += 256) {
        float p = (t <= qq) ? se[t] * rinv : 0.f;
        __nv_bfloat16 hi = __float2bfloat16(p);
        __nv_bfloat16 lo = __float2bfloat16(p - __bfloat162float(hi));
        const int g = t >> 6, j = t & 63;
        __nv_bfloat16* base = Prow + g * 192;
        base[j] = hi;
        base[64 + j] = lo;
        base[128 + j] = hi;
    }
}

// ---------------- r[h,t] ----------------------------------------------
__global__ void kr(const float* __restrict__ x, const float* __restrict__ wr,
                   float* __restrict__ r) {
    const int h = blockIdx.y;
    const int t = blockIdx.x * 128 + threadIdx.x;
    const float* wp = wr + (size_t)h * EE * TT + t;
    const float* xp = x + (size_t)t * EE;
    float acc = 0.f;
#pragma unroll 8
    for (int e = 0; e < EE; e++) acc += xp[e] * wp[(size_t)e * TT];
    r[h * TT + t] = acc;
}

// ---------------- scores ----------------------------------------------
__global__ void kscores(const float* __restrict__ x, const float* __restrict__ eb,
                        float* __restrict__ sc) {
    const int t = blockIdx.x;
    const float* xp = x + (size_t)t * EE;
    const float* ep = eb + (size_t)t * EE;
    float a = 0.f;
    for (int e = threadIdx.x; e < EE; e += 256) a += xp[e] * ep[e];
#pragma unroll
    for (int o = 16; o > 0; o >>= 1) a += __shfl_xor_sync(0xffffffffu, a, o);
    __shared__ float red[8];
    if ((threadIdx.x & 31) == 0) red[threadIdx.x >> 5] = a;
    __syncthreads();
    if (threadIdx.x == 0) {
        float s = 0.f;
#pragma unroll
        for (int w = 0; w < 8; w++) s += red[w];
        sc[t] = s * (1.f / 32.f);
    }
}

// ---------------- gated combine -> split bf16 (A pattern) -------------
__global__ void kcombine3(const float* __restrict__ o1, const float* __restrict__ o2,
                          const float* __restrict__ o3, const float* __restrict__ gate,
                          __nv_bfloat16* __restrict__ comb3) {
    const int idx = blockIdx.x * 256 + threadIdx.x;
    const int c = idx & (HD - 1);
    const int h = c >> 6;
    float g0 = gate[h * 3 + 0], g1 = gate[h * 3 + 1], g2 = gate[h * 3 + 2];
    float mx = fmaxf(g0, fmaxf(g1, g2));
    float e0 = __expf(g0 - mx), e1 = __expf(g1 - mx), e2 = __expf(g2 - mx);
    float inv = 1.f / (e0 + e1 + e2);
    float val = (e0 * o1[idx] + e1 * o2[idx] + e2 * o3[idx]) * inv;
    __nv_bfloat16 hi = __float2bfloat16(val);
    __nv_bfloat16 lo = __float2bfloat16(val - __bfloat162float(hi));
    const int m = idx >> 10, k = idx & 1023;
    __nv_bfloat16* row = comb3 + (size_t)m * 3072;
    row[k] = hi;
    row[1024 + k] = lo;
    row[2048 + k] = hi;
}

// ---------------- launch: multi-stream fork/join graph -----------------
extern "C" void kernel_launch(void* const* d_in, const int* in_sizes, int n_in,
                              void* d_out, int out_size) {
    const float* x    = (const float*)d_in[0];
    const float* wq   = (const float*)d_in[1];
    const float* wk   = (const float*)d_in[2];
    const float* wv   = (const float*)d_in[3];
    const float* wr   = (const float*)d_in[4];
    const float* wvr  = (const float*)d_in[5];
    const float* wj   = (const float*)d_in[6];
    const float* gate = (const float*)d_in[7];
    const float* wo   = (const float*)d_in[8];
    float* out = (float*)d_out;

    float *q, *k, *v, *rv, *echo, *eb, *r, *sc, *o1, *o2, *o3;
    __nv_bfloat16 *x3, *w6, *wjT3, *echoA3, *echoT3, *P3, *comb3;
    cudaGetSymbolAddress((void**)&q, g_q);
    cudaGetSymbolAddress((void**)&k, g_k);
    cudaGetSymbolAddress((void**)&v, g_v);
    cudaGetSymbolAddress((void**)&rv, g_rv);
    cudaGetSymbolAddress((void**)&echo, g_echo);
    cudaGetSymbolAddress((void**)&eb, g_eb);
    cudaGetSymbolAddress((void**)&r, g_r);
    cudaGetSymbolAddress((void**)&sc, g_sc);
    cudaGetSymbolAddress((void**)&o1, g_o1);
    cudaGetSymbolAddress((void**)&o2, g_o2);
    cudaGetSymbolAddress((void**)&o3, g_o3);
    cudaGetSymbolAddress((void**)&x3, g_x3);
    cudaGetSymbolAddress((void**)&w6, g_w6);
    cudaGetSymbolAddress((void**)&wjT3, g_wjT3);
    cudaGetSymbolAddress((void**)&echoA3, g_echoA3);
    cudaGetSymbolAddress((void**)&echoT3, g_echoT3);
    cudaGetSymbolAddress((void**)&P3, g_P3);
    cudaGetSymbolAddress((void**)&comb3, g_comb3);

    static cudaStream_t sB = nullptr, sC = nullptr;
    static cudaEvent_t evFork, evProj, evO1, evO2;
    if (!sB) {
        cudaStreamCreateWithFlags(&sB, cudaStreamNonBlocking);
        cudaStreamCreateWithFlags(&sC, cudaStreamNonBlocking);
        cudaEventCreateWithFlags(&evFork, cudaEventDisableTiming);
        cudaEventCreateWithFlags(&evProj, cudaEventDisableTiming);
        cudaEventCreateWithFlags(&evO1, cudaEventDisableTiming);
        cudaEventCreateWithFlags(&evO2, cudaEventDisableTiming);
        cudaFuncSetAttribute(hmma_gemm<false>, cudaFuncAttributeMaxDynamicSharedMemorySize, HMMA_SMEM);
        cudaFuncSetAttribute(hmma_gemm<true>, cudaFuncAttributeMaxDynamicSharedMemorySize, HMMA_SMEM);
        cudaFuncSetAttribute(hmma_gemm5, cudaFuncAttributeMaxDynamicSharedMemorySize, HMMA_SMEM);
        cudaFuncSetAttribute(flash_hmma, cudaFuncAttributeMaxDynamicSharedMemorySize, FL_SMEM);
    }

    dim3 mgrid(8, 16);
    const int X = 2048 * 1024 / 256;

    // fork point (stream C starts immediately: kr reads only inputs)
    cudaEventRecord(evFork, 0);
    cudaStreamWaitEvent(sC, evFork, 0);
    kr<<<dim3(16, 16), 128, 0, sC>>>(x, wr, r);

    // main: conversions + batched projection
    Src6 src{{wq, wk, wv, wvr, wj, wo}};
    conv3w6<<<dim3(4096, 6), 256>>>(src, w6);
    conv3T<<<dim3(32, 32), 256>>>(wj, wjT3, 1024, 1024);
    conv3<true><<<X, 256>>>(x, x3, 1024);
    Out5 outs{{q, k, v, rv, echo}};
    hmma_gemm5<<<dim3(40, 16), 256, HMMA_SMEM>>>(x3, w6, outs, 3072);
    cudaEventRecord(evProj, 0);

    // stream B: flash attention (needs q,k,v)
    cudaStreamWaitEvent(sB, evProj, 0);
    flash_hmma<<<dim3(32, 16), 128, FL_SMEM, sB>>>(q, k, v, o1);
    cudaEventRecord(evO1, sB);

    // stream C: krrp (needs rv + r)
    cudaStreamWaitEvent(sC, evProj, 0);
    krrp<<<16, 256, 0, sC>>>(r, rv, o2);
    cudaEventRecord(evO2, sC);

    // main: echo chain
    conv3<true><<<X, 256>>>(echo, echoA3, 1024);
    conv3Tg<<<dim3(64, 32), 256>>>(echo, echoT3, 2048, 1024);
    hmma_gemm<false><<<mgrid, 256, HMMA_SMEM>>>(echoA3, wjT3, eb, 3072);
    kscores<<<TT, 256>>>(x, eb, sc);
    kjp3<<<TT, 256>>>(sc, P3);
    hmma_gemm<true><<<mgrid, 256, HMMA_SMEM>>>(P3, echoT3, o3, 6144);

    // join + combine + output projection
    cudaStreamWaitEvent(0, evO1, 0);
    cudaStreamWaitEvent(0, evO2, 0);
    kcombine3<<<(TT * HD) / 256, 256>>>(o1, o2, o3, gate, comb3);
    hmma_gemm<false><<<mgrid, 256, HMMA_SMEM>>>(comb3, w6 + (size_t)5 * 1024 * 3072, out, 3072);
}

// round 9
// speedup vs baseline: 4.4424x; 1.1067x over previous
#include <cuda_runtime.h>
#include <cuda_bf16.h>
#include <cstdint>

#define TT 2048
#define EE 1024
#define HH 16
#define DD 64
#define HD 1024
#define LOG2E 1.4426950408889634f

// ---------------- fp32 scratch ----------------
__device__ __align__(16) float g_q[TT * HD];
__device__ __align__(16) float g_k[TT * HD];
__device__ __align__(16) float g_v[TT * HD];
__device__ __align__(16) float g_rv[TT * HD];
__device__ __align__(16) float g_echo[TT * EE];
__device__ __align__(16) float g_r[HH * TT];
__device__ __align__(16) float g_sc[TT];
__device__ __align__(16) float g_o1[TT * HD];
__device__ __align__(16) float g_o2[TT * HD];
__device__ __align__(16) float g_o3[TT * EE];

// ---------------- bf16 triple-split scratch ----------------
__device__ __align__(16) __nv_bfloat16 g_x3[TT * 3072];
__device__ __align__(16) __nv_bfloat16 g_w6[6144 * 3072];
__device__ __align__(16) __nv_bfloat16 g_echoT3[1024 * 6144];
__device__ __align__(16) __nv_bfloat16 g_P3[TT * 6144];
__device__ __align__(16) __nv_bfloat16 g_comb3[TT * 3072];

struct Src6 { const float* s[6]; };
struct Out5 { float* p[5]; };

// ============================ PTX helpers ============================
__device__ __forceinline__ uint32_t smem_u32(const void* p) {
    uint32_t a;
    asm("{ .reg .u64 t; cvta.to.shared.u64 t, %1; cvt.u32.u64 %0, t; }" : "=r"(a) : "l"(p));
    return a;
}
__device__ __forceinline__ void cp_async16(uint32_t s, const void* g) {
    asm volatile("cp.async.cg.shared.global [%0], [%1], 16;" :: "r"(s), "l"(g));
}
__device__ __forceinline__ void cp_commit() { asm volatile("cp.async.commit_group;"); }
template<int N> __device__ __forceinline__ void cp_wait() {
    asm volatile("cp.async.wait_group %0;" :: "n"(N) : "memory");
}
__device__ __forceinline__ void ldmx4(uint32_t& r0, uint32_t& r1, uint32_t& r2, uint32_t& r3,
                                      uint32_t addr) {
    asm volatile("ldmatrix.sync.aligned.m8n8.x4.shared.b16 {%0,%1,%2,%3}, [%4];"
                 : "=r"(r0), "=r"(r1), "=r"(r2), "=r"(r3) : "r"(addr));
}
__device__ __forceinline__ void mma_bf16(float* d, const uint32_t* a, const uint32_t* b) {
    asm volatile("mma.sync.aligned.m16n8k16.row.col.f32.bf16.bf16.f32 "
                 "{%0,%1,%2,%3}, {%4,%5,%6,%7}, {%8,%9}, {%0,%1,%2,%3};"
                 : "+f"(d[0]), "+f"(d[1]), "+f"(d[2]), "+f"(d[3])
                 : "r"(a[0]), "r"(a[1]), "r"(a[2]), "r"(a[3]), "r"(b[0]), "r"(b[1]));
}
__device__ __forceinline__ uint32_t pack2(__nv_bfloat16 a, __nv_bfloat16 b) {
    __nv_bfloat162 t(a, b);
    return *reinterpret_cast<uint32_t*>(&t);
}

#define HSTAGE_ELE 10240
#define HMMA_SMEM (4 * HSTAGE_ELE * 2)

// =====================================================================
// Shared HMMA mainloop body
// =====================================================================
template<bool CAUSAL>
__device__ __forceinline__ void hmma_body(const __nv_bfloat16* __restrict__ A,
                                          const __nv_bfloat16* __restrict__ B,
                                          float acc[2][8][4],
                                          int m0, int n0, int K3,
                                          __nv_bfloat16* sm) {
    const int tid = threadIdx.x;
    const int kcols = CAUSAL ? ((m0 + 128) * 3 < K3 ? (m0 + 128) * 3 : K3) : K3;
    const int nchunk = kcols >> 5;
    const int warp = tid >> 5, lane = tid & 31;
    const int wm = warp & 3, wn = warp >> 2;
    const uint32_t smb = smem_u32(sm);

    auto load_stage = [&](int cc, int s) {
        const uint32_t ab = smb + s * (HSTAGE_ELE * 2);
        const uint32_t bb = ab + 10240;
        const int k0 = cc * 32;
#pragma unroll
        for (int i = 0; i < 2; i++) {
            int c = tid * 2 + i;
            int row = c >> 2, cg = c & 3;
            cp_async16(ab + row * 80 + cg * 16, A + (size_t)(m0 + row) * K3 + k0 + cg * 8);
            cp_async16(bb + row * 80 + cg * 16, B + (size_t)(n0 + row) * K3 + k0 + cg * 8);
        }
        cp_commit();
    };

    load_stage(0, 0);
    if (1 < nchunk) load_stage(1, 1); else cp_commit();
    if (2 < nchunk) load_stage(2, 2); else cp_commit();

    const int lrow = lane & 15;
    const int lcol = (lane >> 4) << 3;

    for (int c = 0; c < nchunk; c++) {
        cp_wait<2>();
        __syncthreads();
        if (c + 3 < nchunk) load_stage(c + 3, (c + 3) & 3); else cp_commit();

        const uint32_t ab = smb + (c & 3) * (HSTAGE_ELE * 2);
        const uint32_t bb = ab + 10240;
#pragma unroll
        for (int ks = 0; ks < 2; ks++) {
            const uint32_t coff = (ks * 16 + lcol) * 2;
            uint32_t a[2][4], b[8][2];
#pragma unroll
            for (int mt = 0; mt < 2; mt++)
                ldmx4(a[mt][0], a[mt][1], a[mt][2], a[mt][3],
                      ab + (uint32_t)(wm * 32 + mt * 16 + lrow) * 80 + coff);
#pragma unroll
            for (int bp = 0; bp < 4; bp++) {
                uint32_t r0, r1, r2, r3;
                ldmx4(r0, r1, r2, r3,
                      bb + (uint32_t)(wn * 64 + bp * 16 + lrow) * 80 + coff);
                b[bp * 2][0] = r0; b[bp * 2][1] = r2;
                b[bp * 2 + 1][0] = r1; b[bp * 2 + 1][1] = r3;
            }
#pragma unroll
            for (int mt = 0; mt < 2; mt++)
#pragma unroll
                for (int nt = 0; nt < 8; nt++) mma_bf16(acc[mt][nt], a[mt], b[nt]);
        }
        __syncthreads();
    }
}

__device__ __forceinline__ void hmma_epi(float acc[2][8][4], float* C, int m0, int ncol0) {
    const int lane = threadIdx.x & 31, warp = threadIdx.x >> 5;
    const int wm = warp & 3, wn = warp >> 2;
    const int erow = lane >> 2, ecol = (lane & 3) * 2;
#pragma unroll
    for (int mt = 0; mt < 2; mt++) {
        const int r0 = m0 + wm * 32 + mt * 16 + erow;
#pragma unroll
        for (int nt = 0; nt < 8; nt++) {
            const int cc = ncol0 + wn * 64 + nt * 8 + ecol;
            *(float2*)&C[(size_t)r0 * 1024 + cc] = make_float2(acc[mt][nt][0], acc[mt][nt][1]);
            *(float2*)&C[(size_t)(r0 + 8) * 1024 + cc] = make_float2(acc[mt][nt][2], acc[mt][nt][3]);
        }
    }
}

template<bool CAUSAL>
__global__ void __launch_bounds__(256, 2) hmma_gemm(const __nv_bfloat16* __restrict__ A,
                                                    const __nv_bfloat16* __restrict__ B,
                                                    float* __restrict__ C, int K3) {
    extern __shared__ __nv_bfloat16 sm[];
    float acc[2][8][4];
#pragma unroll
    for (int i = 0; i < 2; i++)
#pragma unroll
        for (int j = 0; j < 8; j++)
#pragma unroll
            for (int t = 0; t < 4; t++) acc[i][j][t] = 0.f;
    const int m0 = blockIdx.y * 128, n0 = blockIdx.x * 128;
    hmma_body<CAUSAL>(A, B, acc, m0, n0, K3, sm);
    hmma_epi(acc, C, m0, n0);
}

__global__ void __launch_bounds__(256, 2) hmma_gemm5(const __nv_bfloat16* __restrict__ A,
                                                     const __nv_bfloat16* __restrict__ B,
                                                     Out5 outs, int K3) {
    extern __shared__ __nv_bfloat16 sm[];
    float acc[2][8][4];
#pragma unroll
    for (int i = 0; i < 2; i++)
#pragma unroll
        for (int j = 0; j < 8; j++)
#pragma unroll
            for (int t = 0; t < 4; t++) acc[i][j][t] = 0.f;
    const int m0 = blockIdx.y * 128, n0 = blockIdx.x * 128;
    hmma_body<false>(A, B, acc, m0, n0, K3, sm);
    hmma_epi(acc, outs.p[blockIdx.x >> 3], m0, (blockIdx.x & 7) * 128);
}

// =====================================================================
// branch 1: fused HMMA flash attention
// =====================================================================
#define FL_SMEM (3 * 64 * 200 * 2)

__global__ void __launch_bounds__(128) flash_hmma(const float* __restrict__ q,
                                                  const float* __restrict__ k,
                                                  const float* __restrict__ v,
                                                  float* __restrict__ out) {
    extern __shared__ __nv_bfloat16 fsm[];
    const int h = blockIdx.y, m0 = blockIdx.x * 64;
    const int tid = threadIdx.x, warp = tid >> 5, lane = tid & 31;
    const uint32_t smb = smem_u32(fsm);
    const uint32_t Qb = smb, Kb = smb + 25600, Vb = smb + 51200;
    const int lrow = lane & 15, lcol = (lane >> 4) << 3;
    const float QSCALE = 0.125f * LOG2E;

    for (int idx = tid; idx < 4096; idx += 128) {
        int r = idx >> 6, d = idx & 63;
        float val = q[(size_t)(m0 + r) * HD + h * 64 + d] * QSCALE;
        __nv_bfloat16 hi = __float2bfloat16(val);
        __nv_bfloat16 lo = __float2bfloat16(val - __bfloat162float(hi));
        __nv_bfloat16* Qr = fsm + r * 200;
        Qr[d] = hi; Qr[64 + d] = lo; Qr[128 + d] = hi;
    }

    float m_lo = -1e30f, m_hi = -1e30f, l_lo = 0.f, l_hi = 0.f;
    float O[8][4];
#pragma unroll
    for (int nt = 0; nt < 8; nt++)
#pragma unroll
        for (int t = 0; t < 4; t++) O[nt][t] = 0.f;

    for (int n0 = 0; n0 <= m0; n0 += 64) {
        __syncthreads();
        for (int idx = tid; idx < 4096; idx += 128) {
            int j = idx >> 6, d = idx & 63;
            float kv = k[(size_t)(n0 + j) * HD + h * 64 + d];
            __nv_bfloat16 khi = __float2bfloat16(kv);
            __nv_bfloat16 klo = __float2bfloat16(kv - __bfloat162float(khi));
            __nv_bfloat16* Kr = fsm + 12800 + j * 200;
            Kr[d] = khi; Kr[64 + d] = khi; Kr[128 + d] = klo;
            float vv = v[(size_t)(n0 + j) * HD + h * 64 + d];
            __nv_bfloat16 vhi = __float2bfloat16(vv);
            __nv_bfloat16 vlo = __float2bfloat16(vv - __bfloat162float(vhi));
            __nv_bfloat16* Vc = fsm + 25600 + d * 200;
            Vc[j] = vhi; Vc[64 + j] = vhi; Vc[128 + j] = vlo;
        }
        __syncthreads();

        float s[8][4];
#pragma unroll
        for (int nt = 0; nt < 8; nt++)
#pragma unroll
            for (int t = 0; t < 4; t++) s[nt][t] = 0.f;
#pragma unroll
        for (int ks = 0; ks < 12; ks++) {
            const uint32_t coff = (ks * 16 + lcol) * 2;
            uint32_t a[4], b[8][2];
            ldmx4(a[0], a[1], a[2], a[3], Qb + (uint32_t)(warp * 16 + lrow) * 400 + coff);
#pragma unroll
            for (int bp = 0; bp < 4; bp++) {
                uint32_t r0, r1, r2, r3;
                ldmx4(r0, r1, r2, r3, Kb + (uint32_t)(bp * 16 + lrow) * 400 + coff);
                b[bp * 2][0] = r0; b[bp * 2][1] = r2;
                b[bp * 2 + 1][0] = r1; b[bp * 2 + 1][1] = r3;
            }
#pragma unroll
            for (int nt = 0; nt < 8; nt++) mma_bf16(s[nt], a, b[nt]);
        }

        if (n0 == m0) {
            const int rl = m0 + warp * 16 + (lane >> 2);
            const int cb = n0 + (lane & 3) * 2;
#pragma unroll
            for (int nt = 0; nt < 8; nt++) {
                int c0 = cb + nt * 8, c1 = c0 + 1;
                if (c0 > rl) s[nt][0] = -1e30f;
                if (c1 > rl) s[nt][1] = -1e30f;
                if (c0 > rl + 8) s[nt][2] = -1e30f;
                if (c1 > rl + 8) s[nt][3] = -1e30f;
            }
        }

        float rmx_lo = -1e30f, rmx_hi = -1e30f;
#pragma unroll
        for (int nt = 0; nt < 8; nt++) {
            rmx_lo = fmaxf(rmx_lo, fmaxf(s[nt][0], s[nt][1]));
            rmx_hi = fmaxf(rmx_hi, fmaxf(s[nt][2], s[nt][3]));
        }
#pragma unroll
        for (int o = 1; o < 4; o <<= 1) {
            rmx_lo = fmaxf(rmx_lo, __shfl_xor_sync(0xffffffffu, rmx_lo, o));
            rmx_hi = fmaxf(rmx_hi, __shfl_xor_sync(0xffffffffu, rmx_hi, o));
        }
        float mn_lo = fmaxf(m_lo, rmx_lo), mn_hi = fmaxf(m_hi, rmx_hi);
        float corr_lo = exp2f(m_lo - mn_lo), corr_hi = exp2f(m_hi - mn_hi);
        m_lo = mn_lo; m_hi = mn_hi;
        float rs_lo = 0.f, rs_hi = 0.f;
#pragma unroll
        for (int nt = 0; nt < 8; nt++) {
            s[nt][0] = exp2f(s[nt][0] - mn_lo); rs_lo += s[nt][0];
            s[nt][1] = exp2f(s[nt][1] - mn_lo); rs_lo += s[nt][1];
            s[nt][2] = exp2f(s[nt][2] - mn_hi); rs_hi += s[nt][2];
            s[nt][3] = exp2f(s[nt][3] - mn_hi); rs_hi += s[nt][3];
        }
#pragma unroll
        for (int o = 1; o < 4; o <<= 1) {
            rs_lo += __shfl_xor_sync(0xffffffffu, rs_lo, o);
            rs_hi += __shfl_xor_sync(0xffffffffu, rs_hi, o);
        }
        l_lo = l_lo * corr_lo + rs_lo;
        l_hi = l_hi * corr_hi + rs_hi;
#pragma unroll
        for (int nt = 0; nt < 8; nt++) {
            O[nt][0] *= corr_lo; O[nt][1] *= corr_lo;
            O[nt][2] *= corr_hi; O[nt][3] *= corr_hi;
        }

        uint32_t phi[4][4], plo[4][4];
#pragma unroll
        for (int kk = 0; kk < 4; kk++) {
            const int n0t = 2 * kk, n1t = 2 * kk + 1;
            __nv_bfloat16 h00 = __float2bfloat16(s[n0t][0]);
            __nv_bfloat16 h01 = __float2bfloat16(s[n0t][1]);
            __nv_bfloat16 h02 = __float2bfloat16(s[n0t][2]);
            __nv_bfloat16 h03 = __float2bfloat16(s[n0t][3]);
            __nv_bfloat16 h10 = __float2bfloat16(s[n1t][0]);
            __nv_bfloat16 h11 = __float2bfloat16(s[n1t][1]);
            __nv_bfloat16 h12 = __float2bfloat16(s[n1t][2]);
            __nv_bfloat16 h13 = __float2bfloat16(s[n1t][3]);
            phi[kk][0] = pack2(h00, h01);
            phi[kk][1] = pack2(h02, h03);
            phi[kk][2] = pack2(h10, h11);
            phi[kk][3] = pack2(h12, h13);
            plo[kk][0] = pack2(__float2bfloat16(s[n0t][0] - __bfloat162float(h00)),
                               __float2bfloat16(s[n0t][1] - __bfloat162float(h01)));
            plo[kk][1] = pack2(__float2bfloat16(s[n0t][2] - __bfloat162float(h02)),
                               __float2bfloat16(s[n0t][3] - __bfloat162float(h03)));
            plo[kk][2] = pack2(__float2bfloat16(s[n1t][0] - __bfloat162float(h10)),
                               __float2bfloat16(s[n1t][1] - __bfloat162float(h11)));
            plo[kk][3] = pack2(__float2bfloat16(s[n1t][2] - __bfloat162float(h12)),
                               __float2bfloat16(s[n1t][3] - __bfloat162float(h13)));
        }

#pragma unroll
        for (int ks = 0; ks < 12; ks++) {
            const uint32_t* a = (ks < 4) ? phi[ks] : (ks < 8) ? plo[ks - 4] : phi[ks - 8];
            const uint32_t coff = (ks * 16 + lcol) * 2;
            uint32_t b[8][2];
#pragma unroll
            for (int bp = 0; bp < 4; bp++) {
                uint32_t r0, r1, r2, r3;
                ldmx4(r0, r1, r2, r3, Vb + (uint32_t)(bp * 16 + lrow) * 400 + coff);
                b[bp * 2][0] = r0; b[bp * 2][1] = r2;
                b[bp * 2 + 1][0] = r1; b[bp * 2 + 1][1] = r3;
            }
#pragma unroll
            for (int nt = 0; nt < 8; nt++) mma_bf16(O[nt], a, b[nt]);
        }
    }

    const float inv_lo = 1.f / l_lo, inv_hi = 1.f / l_hi;
    const int rl = m0 + warp * 16 + (lane >> 2);
#pragma unroll
    for (int nt = 0; nt < 8; nt++) {
        const int col = h * 64 + nt * 8 + (lane & 3) * 2;
        *(float2*)&out[(size_t)rl * HD + col] = make_float2(O[nt][0] * inv_lo, O[nt][1] * inv_lo);
        *(float2*)&out[(size_t)(rl + 8) * HD + col] = make_float2(O[nt][2] * inv_hi, O[nt][3] * inv_hi);
    }
}

// =====================================================================
// conversions
// =====================================================================
__global__ void conv3w6(Src6 src, __nv_bfloat16* __restrict__ D) {
    const int w = blockIdx.y;
    const int idx = blockIdx.x * 256 + threadIdx.x;
    const int m = idx >> 10, k = idx & 1023;
    float x = src.s[w][idx];
    __nv_bfloat16 hi = __float2bfloat16(x);
    __nv_bfloat16 lo = __float2bfloat16(x - __bfloat162float(hi));
    __nv_bfloat16* row = D + (size_t)(w * 1024 + m) * 3072;
    row[k] = hi;
    row[1024 + k] = hi;
    row[2048 + k] = lo;
}

template<bool APAT>
__global__ void conv3(const float* __restrict__ S, __nv_bfloat16* __restrict__ D, int K) {
    const int idx = blockIdx.x * 256 + threadIdx.x;
    const int m = idx / K, k = idx - m * K;
    float x = S[idx];
    __nv_bfloat16 hi = __float2bfloat16(x);
    __nv_bfloat16 lo = __float2bfloat16(x - __bfloat162float(hi));
    const size_t ro = (size_t)m * 3 * K;
    D[ro + k] = hi;
    D[ro + K + k] = APAT ? lo : hi;
    D[ro + 2 * K + k] = APAT ? hi : lo;
}

__global__ void conv3Tg(const float* __restrict__ S, __nv_bfloat16* __restrict__ D,
                        int K, int N) {
    __shared__ float t[32][33];
    const int k0 = blockIdx.x * 32, n0 = blockIdx.y * 32;
    const int tx = threadIdx.x & 31, ty = threadIdx.x >> 5;
    for (int i = ty; i < 32; i += 8) t[i][tx] = S[(size_t)(k0 + i) * N + n0 + tx];
    __syncthreads();
    const int K3 = 3 * K;
    for (int i = ty; i < 32; i += 8) {
        const int n = n0 + i, k = k0 + tx;
        const int g = k >> 6, j = k & 63;
        float x = t[tx][i];
        __nv_bfloat16 hi = __float2bfloat16(x);
        __nv_bfloat16 lo = __float2bfloat16(x - __bfloat162float(hi));
        __nv_bfloat16* base = D + (size_t)n * K3 + g * 192;
        base[j] = hi;
        base[64 + j] = hi;
        base[128 + j] = lo;
    }
}

// ---------------- branch 2: two-pass blocked scan ---------------------
__global__ void __launch_bounds__(256) krrp(const float* __restrict__ r,
                                            const float* __restrict__ rv,
                                            float* __restrict__ out) {
    __shared__ float w[2048];
    __shared__ float rl[2048];
    __shared__ float red[256];
    __shared__ float Sg[4][64];
    const int h = blockIdx.x, tid = threadIdx.x;
    const float Cc = 0.125f * LOG2E;
    float vloc[8], lm = -1e30f;
#pragma unroll
    for (int i = 0; i < 8; i++) {
        float vv = r[h * 2048 + tid * 8 + i] * Cc;
        vloc[i] = vv;
        lm = fmaxf(lm, vv);
    }
    red[tid] = lm; __syncthreads();
    for (int s = 128; s; s >>= 1) { if (tid < s) red[tid] = fmaxf(red[tid], red[tid + s]); __syncthreads(); }
    float M = red[0];
    __syncthreads();
    float run = 0.f, pre[8];
#pragma unroll
    for (int i = 0; i < 8; i++) {
        float e = exp2f(vloc[i] - M);
        w[tid * 8 + i] = e;
        run += e;
        pre[i] = run;
    }
    red[tid] = run; __syncthreads();
    for (int s = 1; s < 256; s <<= 1) {
        float t = (tid >= s) ? red[tid - s] : 0.f;
        __syncthreads();
        red[tid] += t;
        __syncthreads();
    }
    float excl = red[tid] - run;
#pragma unroll
    for (int i = 0; i < 8; i++) rl[tid * 8 + i] = 1.f / (excl + pre[i]);
    __syncthreads();

    const int g = tid >> 6, d = tid & 63;
    const int t0 = g * 512, t1 = t0 + 512;
    const float* rp = rv + h * 64 + d;
    float s1 = 0.f;
#pragma unroll 4
    for (int t = t0; t < t1; t++) s1 += w[t] * rp[(size_t)t * 1024];
    Sg[g][d] = s1;
    __syncthreads();
    float base = 0.f;
#pragma unroll
    for (int gg = 0; gg < 3; gg++)
        if (gg < g) base += Sg[gg][d];
    float acc = base;
    float* op = out + h * 64 + d;
#pragma unroll 4
    for (int t = t0; t < t1; t++) {
        acc += w[t] * rp[(size_t)t * 1024];
        op[(size_t)t * 1024] = acc * rl[t];
    }
}

// ---------------- branch 3 probabilities -> grouped split bf16 -------
__global__ void __launch_bounds__(256) kjp3(const float* __restrict__ sc,
                                            __nv_bfloat16* __restrict__ P3) {
    __shared__ float sk[2048];
    __shared__ float se[2048];
    __shared__ float red[256];
    const int qq = blockIdx.x, tid = threadIdx.x;
    for (int t = tid; t < 2048; t += 256) sk[t] = sc[t];
    __syncthreads();
    const float sq = sk[qq] * LOG2E;
    float lm = -1e30f;
    for (int t = tid; t <= qq; t += 256) lm = fmaxf(lm, sq * sk[t]);
    red[tid] = lm; __syncthreads();
    for (int s = 128; s; s >>= 1) { if (tid < s) red[tid] = fmaxf(red[tid], red[tid + s]); __syncthreads(); }
    float M = red[0];
    __syncthreads();
    float ls = 0.f;
    for (int t = tid; t <= qq; t += 256) {
        float e = exp2f(sq * sk[t] - M);
        se[t] = e;
        ls += e;
    }
    red[tid] = ls; __syncthreads();
    for (int s = 128; s; s >>= 1) { if (tid < s) red[tid] += red[tid + s]; __syncthreads(); }
    const float rinv = 1.f / red[0];
    __nv_bfloat16* Prow = P3 + (size_t)qq * 6144;
    for (int t = tid; t < 2048; t += 256) {
        float p = (t <= qq) ? se[t] * rinv : 0.f;
        __nv_bfloat16 hi = __float2bfloat16(p);
        __nv_bfloat16 lo = __float2bfloat16(p - __bfloat162float(hi));
        const int g = t >> 6, j = t & 63;
        __nv_bfloat16* base = Prow + g * 192;
        base[j] = hi;
        base[64 + j] = lo;
        base[128 + j] = hi;
    }
}

// ---------------- r[h,t] ----------------------------------------------
__global__ void kr(const float* __restrict__ x, const float* __restrict__ wr,
                   float* __restrict__ r) {
    const int h = blockIdx.y;
    const int t = blockIdx.x * 128 + threadIdx.x;
    const float* wp = wr + (size_t)h * EE * TT + t;
    const float* xp = x + (size_t)t * EE;
    float acc = 0.f;
#pragma unroll 8
    for (int e = 0; e < EE; e++) acc += xp[e] * wp[(size_t)e * TT];
    r[h * TT + t] = acc;
}

// ---------------- scores[t] = ||echo[t]||^2 / 32 ----------------------
// (x . (echo @ wj))[t] = x wj^T wj x^T = ||echo[t]||^2  — gemm_eb eliminated
__global__ void kscores2(const float* __restrict__ echo, float* __restrict__ sc) {
    const int t = blockIdx.x * 8 + (threadIdx.x >> 5);
    const int lane = threadIdx.x & 31;
    const float* ep = echo + (size_t)t * EE;
    float a = 0.f;
#pragma unroll 4
    for (int e = lane * 4; e < EE; e += 128) {
        float4 v = *(const float4*)(ep + e);
        a += v.x * v.x + v.y * v.y + v.z * v.z + v.w * v.w;
    }
#pragma unroll
    for (int o = 16; o > 0; o >>= 1) a += __shfl_xor_sync(0xffffffffu, a, o);
    if (lane == 0) sc[t] = a * (1.f / 32.f);
}

// ---------------- gated combine -> split bf16 (A pattern) -------------
__global__ void kcombine3(const float* __restrict__ o1, const float* __restrict__ o2,
                          const float* __restrict__ o3, const float* __restrict__ gate,
                          __nv_bfloat16* __restrict__ comb3) {
    const int idx = blockIdx.x * 256 + threadIdx.x;
    const int c = idx & (HD - 1);
    const int h = c >> 6;
    float g0 = gate[h * 3 + 0], g1 = gate[h * 3 + 1], g2 = gate[h * 3 + 2];
    float mx = fmaxf(g0, fmaxf(g1, g2));
    float e0 = __expf(g0 - mx), e1 = __expf(g1 - mx), e2 = __expf(g2 - mx);
    float inv = 1.f / (e0 + e1 + e2);
    float val = (e0 * o1[idx] + e1 * o2[idx] + e2 * o3[idx]) * inv;
    __nv_bfloat16 hi = __float2bfloat16(val);
    __nv_bfloat16 lo = __float2bfloat16(val - __bfloat162float(hi));
    const int m = idx >> 10, k = idx & 1023;
    __nv_bfloat16* row = comb3 + (size_t)m * 3072;
    row[k] = hi;
    row[1024 + k] = lo;
    row[2048 + k] = hi;
}

// ---------------- launch: multi-stream fork/join graph -----------------
extern "C" void kernel_launch(void* const* d_in, const int* in_sizes, int n_in,
                              void* d_out, int out_size) {
    const float* x    = (const float*)d_in[0];
    const float* wq   = (const float*)d_in[1];
    const float* wk   = (const float*)d_in[2];
    const float* wv   = (const float*)d_in[3];
    const float* wr   = (const float*)d_in[4];
    const float* wvr  = (const float*)d_in[5];
    const float* wj   = (const float*)d_in[6];
    const float* gate = (const float*)d_in[7];
    const float* wo   = (const float*)d_in[8];
    float* out = (float*)d_out;

    float *q, *k, *v, *rv, *echo, *r, *sc, *o1, *o2, *o3;
    __nv_bfloat16 *x3, *w6, *echoT3, *P3, *comb3;
    cudaGetSymbolAddress((void**)&q, g_q);
    cudaGetSymbolAddress((void**)&k, g_k);
    cudaGetSymbolAddress((void**)&v, g_v);
    cudaGetSymbolAddress((void**)&rv, g_rv);
    cudaGetSymbolAddress((void**)&echo, g_echo);
    cudaGetSymbolAddress((void**)&r, g_r);
    cudaGetSymbolAddress((void**)&sc, g_sc);
    cudaGetSymbolAddress((void**)&o1, g_o1);
    cudaGetSymbolAddress((void**)&o2, g_o2);
    cudaGetSymbolAddress((void**)&o3, g_o3);
    cudaGetSymbolAddress((void**)&x3, g_x3);
    cudaGetSymbolAddress((void**)&w6, g_w6);
    cudaGetSymbolAddress((void**)&echoT3, g_echoT3);
    cudaGetSymbolAddress((void**)&P3, g_P3);
    cudaGetSymbolAddress((void**)&comb3, g_comb3);

    static cudaStream_t sB = nullptr, sC = nullptr;
    static cudaEvent_t evFork, evProj, evO1, evO2, evT;
    if (!sB) {
        cudaStreamCreateWithFlags(&sB, cudaStreamNonBlocking);
        cudaStreamCreateWithFlags(&sC, cudaStreamNonBlocking);
        cudaEventCreateWithFlags(&evFork, cudaEventDisableTiming);
        cudaEventCreateWithFlags(&evProj, cudaEventDisableTiming);
        cudaEventCreateWithFlags(&evO1, cudaEventDisableTiming);
        cudaEventCreateWithFlags(&evO2, cudaEventDisableTiming);
        cudaEventCreateWithFlags(&evT, cudaEventDisableTiming);
        cudaFuncSetAttribute(hmma_gemm<false>, cudaFuncAttributeMaxDynamicSharedMemorySize, HMMA_SMEM);
        cudaFuncSetAttribute(hmma_gemm<true>, cudaFuncAttributeMaxDynamicSharedMemorySize, HMMA_SMEM);
        cudaFuncSetAttribute(hmma_gemm5, cudaFuncAttributeMaxDynamicSharedMemorySize, HMMA_SMEM);
        cudaFuncSetAttribute(flash_hmma, cudaFuncAttributeMaxDynamicSharedMemorySize, FL_SMEM);
    }

    dim3 mgrid(8, 16);
    const int X = 2048 * 1024 / 256;

    // fork: stream C starts kr immediately (reads only inputs)
    cudaEventRecord(evFork, 0);
    cudaStreamWaitEvent(sC, evFork, 0);
    kr<<<dim3(16, 16), 128, 0, sC>>>(x, wr, r);

    // main: conversions + batched projection
    Src6 src{{wq, wk, wv, wvr, wj, wo}};
    conv3w6<<<dim3(4096, 6), 256>>>(src, w6);
    conv3<true><<<X, 256>>>(x, x3, 1024);
    Out5 outs{{q, k, v, rv, echo}};
    hmma_gemm5<<<dim3(40, 16), 256, HMMA_SMEM>>>(x3, w6, outs, 3072);
    cudaEventRecord(evProj, 0);

    // stream B: echo transpose-split, then flash attention
    cudaStreamWaitEvent(sB, evProj, 0);
    conv3Tg<<<dim3(64, 32), 256, 0, sB>>>(echo, echoT3, 2048, 1024);
    cudaEventRecord(evT, sB);
    flash_hmma<<<dim3(32, 16), 128, FL_SMEM, sB>>>(q, k, v, o1);
    cudaEventRecord(evO1, sB);

    // stream C: krrp (needs rv + r)
    cudaStreamWaitEvent(sC, evProj, 0);
    krrp<<<16, 256, 0, sC>>>(r, rv, o2);
    cudaEventRecord(evO2, sC);

    // main: janus chain (no gemm_eb — scores = ||echo||^2/32)
    kscores2<<<TT / 8, 256>>>(echo, sc);
    kjp3<<<TT, 256>>>(sc, P3);
    cudaStreamWaitEvent(0, evT, 0);
    hmma_gemm<true><<<mgrid, 256, HMMA_SMEM>>>(P3, echoT3, o3, 6144);

    // join + combine + output projection
    cudaStreamWaitEvent(0, evO1, 0);
    cudaStreamWaitEvent(0, evO2, 0);
    kcombine3<<<(TT * HD) / 256, 256>>>(o1, o2, o3, gate, comb3);
    hmma_gemm<false><<<mgrid, 256, HMMA_SMEM>>>(comb3, w6 + (size_t)5 * 1024 * 3072, out, 3072);
}

// round 10
// speedup vs baseline: 5.4263x; 1.2215x over previous
#include <cuda_runtime.h>
#include <cuda_bf16.h>
#include <cstdint>

#define TT 2048
#define EE 1024
#define HH 16
#define DD 64
#define HD 1024
#define LOG2E 1.4426950408889634f

// ---------------- fp32 scratch ----------------
__device__ __align__(16) float g_q[TT * HD];
__device__ __align__(16) float g_k[TT * HD];
__device__ __align__(16) float g_v[TT * HD];
__device__ __align__(16) float g_rv[TT * HD];
__device__ __align__(16) float g_echo[TT * EE];
__device__ __align__(16) float g_r[HH * TT];
__device__ __align__(16) float g_sc[TT];
__device__ __align__(16) float g_o1[TT * HD];
__device__ __align__(16) float g_o2[TT * HD];
__device__ __align__(16) float g_o3[TT * EE];

// ---------------- bf16 triple-split scratch ----------------
__device__ __align__(16) __nv_bfloat16 g_x3[TT * 3072];
__device__ __align__(16) __nv_bfloat16 g_w6[6144 * 3072];
__device__ __align__(16) __nv_bfloat16 g_echoT3[1024 * 6144];
__device__ __align__(16) __nv_bfloat16 g_P3[TT * 6144];
__device__ __align__(16) __nv_bfloat16 g_comb3[TT * 3072];

struct Src6 { const float* s[6]; };
struct Out5 { float* p[5]; };

// ============================ PTX helpers ============================
__device__ __forceinline__ uint32_t smem_u32(const void* p) {
    uint32_t a;
    asm("{ .reg .u64 t; cvta.to.shared.u64 t, %1; cvt.u32.u64 %0, t; }" : "=r"(a) : "l"(p));
    return a;
}
__device__ __forceinline__ void cp_async16(uint32_t s, const void* g) {
    asm volatile("cp.async.cg.shared.global [%0], [%1], 16;" :: "r"(s), "l"(g));
}
__device__ __forceinline__ void cp_commit() { asm volatile("cp.async.commit_group;"); }
template<int N> __device__ __forceinline__ void cp_wait() {
    asm volatile("cp.async.wait_group %0;" :: "n"(N) : "memory");
}
__device__ __forceinline__ void ldmx4(uint32_t& r0, uint32_t& r1, uint32_t& r2, uint32_t& r3,
                                      uint32_t addr) {
    asm volatile("ldmatrix.sync.aligned.m8n8.x4.shared.b16 {%0,%1,%2,%3}, [%4];"
                 : "=r"(r0), "=r"(r1), "=r"(r2), "=r"(r3) : "r"(addr));
}
__device__ __forceinline__ void mma_bf16(float* d, const uint32_t* a, const uint32_t* b) {
    asm volatile("mma.sync.aligned.m16n8k16.row.col.f32.bf16.bf16.f32 "
                 "{%0,%1,%2,%3}, {%4,%5,%6,%7}, {%8,%9}, {%0,%1,%2,%3};"
                 : "+f"(d[0]), "+f"(d[1]), "+f"(d[2]), "+f"(d[3])
                 : "r"(a[0]), "r"(a[1]), "r"(a[2]), "r"(a[3]), "r"(b[0]), "r"(b[1]));
}
__device__ __forceinline__ uint32_t pack2(__nv_bfloat16 a, __nv_bfloat16 b) {
    __nv_bfloat162 t(a, b);
    return *reinterpret_cast<uint32_t*>(&t);
}

// BK=64, 2-stage: rows padded to 72 elements (144B) -> ldsm conflict-free
#define HROW 144
#define HOPER (128 * HROW)          // bytes per operand per stage (18432)
#define HSTAGE (2 * HOPER)          // 36864
#define HMMA_SMEM (2 * HSTAGE)      // 73728

// =====================================================================
// Shared HMMA mainloop body (BK=64, 2-stage cp.async)
// =====================================================================
template<bool CAUSAL>
__device__ __forceinline__ void hmma_body(const __nv_bfloat16* __restrict__ A,
                                          const __nv_bfloat16* __restrict__ B,
                                          float acc[2][8][4],
                                          int m0, int n0, int K3,
                                          __nv_bfloat16* sm) {
    const int tid = threadIdx.x;
    const int kcols = CAUSAL ? ((m0 + 128) * 3 < K3 ? (m0 + 128) * 3 : K3) : K3;
    const int nchunk = kcols >> 6;
    const int warp = tid >> 5, lane = tid & 31;
    const int wm = warp & 3, wn = warp >> 2;
    const uint32_t smb = smem_u32(sm);

    auto load_stage = [&](int cc, int s) {
        const uint32_t ab = smb + s * HSTAGE;
        const uint32_t bb = ab + HOPER;
        const int k0 = cc * 64;
#pragma unroll
        for (int i = 0; i < 4; i++) {
            int idx = tid + i * 256;           // 0..1023
            int row = idx >> 3, cg = idx & 7;
            cp_async16(ab + row * HROW + cg * 16, A + (size_t)(m0 + row) * K3 + k0 + cg * 8);
            cp_async16(bb + row * HROW + cg * 16, B + (size_t)(n0 + row) * K3 + k0 + cg * 8);
        }
        cp_commit();
    };

    load_stage(0, 0);
    load_stage(1, 1);

    const int lrow = lane & 15;
    const int lcol = (lane >> 4) << 3;

    for (int c = 0; c < nchunk; c++) {
        cp_wait<1>();
        __syncthreads();
        const uint32_t ab = smb + (c & 1) * HSTAGE;
        const uint32_t bb = ab + HOPER;
#pragma unroll
        for (int ks = 0; ks < 4; ks++) {
            const uint32_t coff = (ks * 16 + lcol) * 2;
            uint32_t a[2][4], b[8][2];
#pragma unroll
            for (int mt = 0; mt < 2; mt++)
                ldmx4(a[mt][0], a[mt][1], a[mt][2], a[mt][3],
                      ab + (uint32_t)(wm * 32 + mt * 16 + lrow) * HROW + coff);
#pragma unroll
            for (int bp = 0; bp < 4; bp++) {
                uint32_t r0, r1, r2, r3;
                ldmx4(r0, r1, r2, r3,
                      bb + (uint32_t)(wn * 64 + bp * 16 + lrow) * HROW + coff);
                b[bp * 2][0] = r0; b[bp * 2][1] = r2;
                b[bp * 2 + 1][0] = r1; b[bp * 2 + 1][1] = r3;
            }
#pragma unroll
            for (int mt = 0; mt < 2; mt++)
#pragma unroll
                for (int nt = 0; nt < 8; nt++) mma_bf16(acc[mt][nt], a[mt], b[nt]);
        }
        __syncthreads();
        if (c + 2 < nchunk) load_stage(c + 2, c & 1);
    }
}

__device__ __forceinline__ void hmma_epi(float acc[2][8][4], float* C, int m0, int ncol0) {
    const int lane = threadIdx.x & 31, warp = threadIdx.x >> 5;
    const int wm = warp & 3, wn = warp >> 2;
    const int erow = lane >> 2, ecol = (lane & 3) * 2;
#pragma unroll
    for (int mt = 0; mt < 2; mt++) {
        const int r0 = m0 + wm * 32 + mt * 16 + erow;
#pragma unroll
        for (int nt = 0; nt < 8; nt++) {
            const int cc = ncol0 + wn * 64 + nt * 8 + ecol;
            *(float2*)&C[(size_t)r0 * 1024 + cc] = make_float2(acc[mt][nt][0], acc[mt][nt][1]);
            *(float2*)&C[(size_t)(r0 + 8) * 1024 + cc] = make_float2(acc[mt][nt][2], acc[mt][nt][3]);
        }
    }
}

template<bool CAUSAL>
__global__ void __launch_bounds__(256, 2) hmma_gemm(const __nv_bfloat16* __restrict__ A,
                                                    const __nv_bfloat16* __restrict__ B,
                                                    float* __restrict__ C, int K3) {
    extern __shared__ __nv_bfloat16 sm[];
    float acc[2][8][4];
#pragma unroll
    for (int i = 0; i < 2; i++)
#pragma unroll
        for (int j = 0; j < 8; j++)
#pragma unroll
            for (int t = 0; t < 4; t++) acc[i][j][t] = 0.f;
    const int m0 = blockIdx.y * 128, n0 = blockIdx.x * 128;
    hmma_body<CAUSAL>(A, B, acc, m0, n0, K3, sm);
    hmma_epi(acc, C, m0, n0);
}

__global__ void __launch_bounds__(256, 2) hmma_gemm5(const __nv_bfloat16* __restrict__ A,
                                                     const __nv_bfloat16* __restrict__ B,
                                                     Out5 outs, int K3) {
    extern __shared__ __nv_bfloat16 sm[];
    float acc[2][8][4];
#pragma unroll
    for (int i = 0; i < 2; i++)
#pragma unroll
        for (int j = 0; j < 8; j++)
#pragma unroll
            for (int t = 0; t < 4; t++) acc[i][j][t] = 0.f;
    const int m0 = blockIdx.y * 128, n0 = blockIdx.x * 128;
    hmma_body<false>(A, B, acc, m0, n0, K3, sm);
    hmma_epi(acc, outs.p[blockIdx.x >> 3], m0, (blockIdx.x & 7) * 128);
}

// =====================================================================
// branch 1: fused HMMA flash attention
// =====================================================================
#define FL_SMEM (3 * 64 * 200 * 2)

__global__ void __launch_bounds__(128) flash_hmma(const float* __restrict__ q,
                                                  const float* __restrict__ k,
                                                  const float* __restrict__ v,
                                                  float* __restrict__ out) {
    extern __shared__ __nv_bfloat16 fsm[];
    const int h = blockIdx.y, m0 = blockIdx.x * 64;
    const int tid = threadIdx.x, warp = tid >> 5, lane = tid & 31;
    const uint32_t smb = smem_u32(fsm);
    const uint32_t Qb = smb, Kb = smb + 25600, Vb = smb + 51200;
    const int lrow = lane & 15, lcol = (lane >> 4) << 3;
    const float QSCALE = 0.125f * LOG2E;

    for (int idx = tid; idx < 4096; idx += 128) {
        int r = idx >> 6, d = idx & 63;
        float val = q[(size_t)(m0 + r) * HD + h * 64 + d] * QSCALE;
        __nv_bfloat16 hi = __float2bfloat16(val);
        __nv_bfloat16 lo = __float2bfloat16(val - __bfloat162float(hi));
        __nv_bfloat16* Qr = fsm + r * 200;
        Qr[d] = hi; Qr[64 + d] = lo; Qr[128 + d] = hi;
    }

    float m_lo = -1e30f, m_hi = -1e30f, l_lo = 0.f, l_hi = 0.f;
    float O[8][4];
#pragma unroll
    for (int nt = 0; nt < 8; nt++)
#pragma unroll
        for (int t = 0; t < 4; t++) O[nt][t] = 0.f;

    for (int n0 = 0; n0 <= m0; n0 += 64) {
        __syncthreads();
        for (int idx = tid; idx < 4096; idx += 128) {
            int j = idx >> 6, d = idx & 63;
            float kv = k[(size_t)(n0 + j) * HD + h * 64 + d];
            __nv_bfloat16 khi = __float2bfloat16(kv);
            __nv_bfloat16 klo = __float2bfloat16(kv - __bfloat162float(khi));
            __nv_bfloat16* Kr = fsm + 12800 + j * 200;
            Kr[d] = khi; Kr[64 + d] = khi; Kr[128 + d] = klo;
            float vv = v[(size_t)(n0 + j) * HD + h * 64 + d];
            __nv_bfloat16 vhi = __float2bfloat16(vv);
            __nv_bfloat16 vlo = __float2bfloat16(vv - __bfloat162float(vhi));
            __nv_bfloat16* Vc = fsm + 25600 + d * 200;
            Vc[j] = vhi; Vc[64 + j] = vhi; Vc[128 + j] = vlo;
        }
        __syncthreads();

        float s[8][4];
#pragma unroll
        for (int nt = 0; nt < 8; nt++)
#pragma unroll
            for (int t = 0; t < 4; t++) s[nt][t] = 0.f;
#pragma unroll
        for (int ks = 0; ks < 12; ks++) {
            const uint32_t coff = (ks * 16 + lcol) * 2;
            uint32_t a[4], b[8][2];
            ldmx4(a[0], a[1], a[2], a[3], Qb + (uint32_t)(warp * 16 + lrow) * 400 + coff);
#pragma unroll
            for (int bp = 0; bp < 4; bp++) {
                uint32_t r0, r1, r2, r3;
                ldmx4(r0, r1, r2, r3, Kb + (uint32_t)(bp * 16 + lrow) * 400 + coff);
                b[bp * 2][0] = r0; b[bp * 2][1] = r2;
                b[bp * 2 + 1][0] = r1; b[bp * 2 + 1][1] = r3;
            }
#pragma unroll
            for (int nt = 0; nt < 8; nt++) mma_bf16(s[nt], a, b[nt]);
        }

        if (n0 == m0) {
            const int rl = m0 + warp * 16 + (lane >> 2);
            const int cb = n0 + (lane & 3) * 2;
#pragma unroll
            for (int nt = 0; nt < 8; nt++) {
                int c0 = cb + nt * 8, c1 = c0 + 1;
                if (c0 > rl) s[nt][0] = -1e30f;
                if (c1 > rl) s[nt][1] = -1e30f;
                if (c0 > rl + 8) s[nt][2] = -1e30f;
                if (c1 > rl + 8) s[nt][3] = -1e30f;
            }
        }

        float rmx_lo = -1e30f, rmx_hi = -1e30f;
#pragma unroll
        for (int nt = 0; nt < 8; nt++) {
            rmx_lo = fmaxf(rmx_lo, fmaxf(s[nt][0], s[nt][1]));
            rmx_hi = fmaxf(rmx_hi, fmaxf(s[nt][2], s[nt][3]));
        }
#pragma unroll
        for (int o = 1; o < 4; o <<= 1) {
            rmx_lo = fmaxf(rmx_lo, __shfl_xor_sync(0xffffffffu, rmx_lo, o));
            rmx_hi = fmaxf(rmx_hi, __shfl_xor_sync(0xffffffffu, rmx_hi, o));
        }
        float mn_lo = fmaxf(m_lo, rmx_lo), mn_hi = fmaxf(m_hi, rmx_hi);
        float corr_lo = exp2f(m_lo - mn_lo), corr_hi = exp2f(m_hi - mn_hi);
        m_lo = mn_lo; m_hi = mn_hi;
        float rs_lo = 0.f, rs_hi = 0.f;
#pragma unroll
        for (int nt = 0; nt < 8; nt++) {
            s[nt][0] = exp2f(s[nt][0] - mn_lo); rs_lo += s[nt][0];
            s[nt][1] = exp2f(s[nt][1] - mn_lo); rs_lo += s[nt][1];
            s[nt][2] = exp2f(s[nt][2] - mn_hi); rs_hi += s[nt][2];
            s[nt][3] = exp2f(s[nt][3] - mn_hi); rs_hi += s[nt][3];
        }
#pragma unroll
        for (int o = 1; o < 4; o <<= 1) {
            rs_lo += __shfl_xor_sync(0xffffffffu, rs_lo, o);
            rs_hi += __shfl_xor_sync(0xffffffffu, rs_hi, o);
        }
        l_lo = l_lo * corr_lo + rs_lo;
        l_hi = l_hi * corr_hi + rs_hi;
#pragma unroll
        for (int nt = 0; nt < 8; nt++) {
            O[nt][0] *= corr_lo; O[nt][1] *= corr_lo;
            O[nt][2] *= corr_hi; O[nt][3] *= corr_hi;
        }

        uint32_t phi[4][4], plo[4][4];
#pragma unroll
        for (int kk = 0; kk < 4; kk++) {
            const int n0t = 2 * kk, n1t = 2 * kk + 1;
            __nv_bfloat16 h00 = __float2bfloat16(s[n0t][0]);
            __nv_bfloat16 h01 = __float2bfloat16(s[n0t][1]);
            __nv_bfloat16 h02 = __float2bfloat16(s[n0t][2]);
            __nv_bfloat16 h03 = __float2bfloat16(s[n0t][3]);
            __nv_bfloat16 h10 = __float2bfloat16(s[n1t][0]);
            __nv_bfloat16 h11 = __float2bfloat16(s[n1t][1]);
            __nv_bfloat16 h12 = __float2bfloat16(s[n1t][2]);
            __nv_bfloat16 h13 = __float2bfloat16(s[n1t][3]);
            phi[kk][0] = pack2(h00, h01);
            phi[kk][1] = pack2(h02, h03);
            phi[kk][2] = pack2(h10, h11);
            phi[kk][3] = pack2(h12, h13);
            plo[kk][0] = pack2(__float2bfloat16(s[n0t][0] - __bfloat162float(h00)),
                               __float2bfloat16(s[n0t][1] - __bfloat162float(h01)));
            plo[kk][1] = pack2(__float2bfloat16(s[n0t][2] - __bfloat162float(h02)),
                               __float2bfloat16(s[n0t][3] - __bfloat162float(h03)));
            plo[kk][2] = pack2(__float2bfloat16(s[n1t][0] - __bfloat162float(h10)),
                               __float2bfloat16(s[n1t][1] - __bfloat162float(h11)));
            plo[kk][3] = pack2(__float2bfloat16(s[n1t][2] - __bfloat162float(h12)),
                               __float2bfloat16(s[n1t][3] - __bfloat162float(h13)));
        }

#pragma unroll
        for (int ks = 0; ks < 12; ks++) {
            const uint32_t* a = (ks < 4) ? phi[ks] : (ks < 8) ? plo[ks - 4] : phi[ks - 8];
            const uint32_t coff = (ks * 16 + lcol) * 2;
            uint32_t b[8][2];
#pragma unroll
            for (int bp = 0; bp < 4; bp++) {
                uint32_t r0, r1, r2, r3;
                ldmx4(r0, r1, r2, r3, Vb + (uint32_t)(bp * 16 + lrow) * 400 + coff);
                b[bp * 2][0] = r0; b[bp * 2][1] = r2;
                b[bp * 2 + 1][0] = r1; b[bp * 2 + 1][1] = r3;
            }
#pragma unroll
            for (int nt = 0; nt < 8; nt++) mma_bf16(O[nt], a, b[nt]);
        }
    }

    const float inv_lo = 1.f / l_lo, inv_hi = 1.f / l_hi;
    const int rl = m0 + warp * 16 + (lane >> 2);
#pragma unroll
    for (int nt = 0; nt < 8; nt++) {
        const int col = h * 64 + nt * 8 + (lane & 3) * 2;
        *(float2*)&out[(size_t)rl * HD + col] = make_float2(O[nt][0] * inv_lo, O[nt][1] * inv_lo);
        *(float2*)&out[(size_t)(rl + 8) * HD + col] = make_float2(O[nt][2] * inv_hi, O[nt][3] * inv_hi);
    }
}

// =====================================================================
// conversions
// =====================================================================
__global__ void conv3w6(Src6 src, __nv_bfloat16* __restrict__ D) {
    const int w = blockIdx.y;
    const int idx = blockIdx.x * 256 + threadIdx.x;
    const int m = idx >> 10, k = idx & 1023;
    float x = src.s[w][idx];
    __nv_bfloat16 hi = __float2bfloat16(x);
    __nv_bfloat16 lo = __float2bfloat16(x - __bfloat162float(hi));
    __nv_bfloat16* row = D + (size_t)(w * 1024 + m) * 3072;
    row[k] = hi;
    row[1024 + k] = hi;
    row[2048 + k] = lo;
}

template<bool APAT>
__global__ void conv3(const float* __restrict__ S, __nv_bfloat16* __restrict__ D, int K) {
    const int idx = blockIdx.x * 256 + threadIdx.x;
    const int m = idx / K, k = idx - m * K;
    float x = S[idx];
    __nv_bfloat16 hi = __float2bfloat16(x);
    __nv_bfloat16 lo = __float2bfloat16(x - __bfloat162float(hi));
    const size_t ro = (size_t)m * 3 * K;
    D[ro + k] = hi;
    D[ro + K + k] = APAT ? lo : hi;
    D[ro + 2 * K + k] = APAT ? hi : lo;
}

__global__ void conv3Tg(const float* __restrict__ S, __nv_bfloat16* __restrict__ D,
                        int K, int N) {
    __shared__ float t[32][33];
    const int k0 = blockIdx.x * 32, n0 = blockIdx.y * 32;
    const int tx = threadIdx.x & 31, ty = threadIdx.x >> 5;
    for (int i = ty; i < 32; i += 8) t[i][tx] = S[(size_t)(k0 + i) * N + n0 + tx];
    __syncthreads();
    const int K3 = 3 * K;
    for (int i = ty; i < 32; i += 8) {
        const int n = n0 + i, k = k0 + tx;
        const int g = k >> 6, j = k & 63;
        float x = t[tx][i];
        __nv_bfloat16 hi = __float2bfloat16(x);
        __nv_bfloat16 lo = __float2bfloat16(x - __bfloat162float(hi));
        __nv_bfloat16* base = D + (size_t)n * K3 + g * 192;
        base[j] = hi;
        base[64 + j] = hi;
        base[128 + j] = lo;
    }
}

// ---------------- branch 2: two-pass blocked scan ---------------------
__global__ void __launch_bounds__(256) krrp(const float* __restrict__ r,
                                            const float* __restrict__ rv,
                                            float* __restrict__ out) {
    __shared__ float w[2048];
    __shared__ float rl[2048];
    __shared__ float red[256];
    __shared__ float Sg[4][64];
    const int h = blockIdx.x, tid = threadIdx.x;
    const float Cc = 0.125f * LOG2E;
    float vloc[8], lm = -1e30f;
#pragma unroll
    for (int i = 0; i < 8; i++) {
        float vv = r[h * 2048 + tid * 8 + i] * Cc;
        vloc[i] = vv;
        lm = fmaxf(lm, vv);
    }
    red[tid] = lm; __syncthreads();
    for (int s = 128; s; s >>= 1) { if (tid < s) red[tid] = fmaxf(red[tid], red[tid + s]); __syncthreads(); }
    float M = red[0];
    __syncthreads();
    float run = 0.f, pre[8];
#pragma unroll
    for (int i = 0; i < 8; i++) {
        float e = exp2f(vloc[i] - M);
        w[tid * 8 + i] = e;
        run += e;
        pre[i] = run;
    }
    red[tid] = run; __syncthreads();
    for (int s = 1; s < 256; s <<= 1) {
        float t = (tid >= s) ? red[tid - s] : 0.f;
        __syncthreads();
        red[tid] += t;
        __syncthreads();
    }
    float excl = red[tid] - run;
#pragma unroll
    for (int i = 0; i < 8; i++) rl[tid * 8 + i] = 1.f / (excl + pre[i]);
    __syncthreads();

    const int g = tid >> 6, d = tid & 63;
    const int t0 = g * 512, t1 = t0 + 512;
    const float* rp = rv + h * 64 + d;
    float s1 = 0.f;
#pragma unroll 4
    for (int t = t0; t < t1; t++) s1 += w[t] * rp[(size_t)t * 1024];
    Sg[g][d] = s1;
    __syncthreads();
    float base = 0.f;
#pragma unroll
    for (int gg = 0; gg < 3; gg++)
        if (gg < g) base += Sg[gg][d];
    float acc = base;
    float* op = out + h * 64 + d;
#pragma unroll 4
    for (int t = t0; t < t1; t++) {
        acc += w[t] * rp[(size_t)t * 1024];
        op[(size_t)t * 1024] = acc * rl[t];
    }
}

// ---------------- branch 3 probabilities -> grouped split bf16 -------
__global__ void __launch_bounds__(256) kjp3(const float* __restrict__ sc,
                                            __nv_bfloat16* __restrict__ P3) {
    __shared__ float sk[2048];
    __shared__ float se[2048];
    __shared__ float red[256];
    const int qq = blockIdx.x, tid = threadIdx.x;
    for (int t = tid; t < 2048; t += 256) sk[t] = sc[t];
    __syncthreads();
    const float sq = sk[qq] * LOG2E;
    float lm = -1e30f;
    for (int t = tid; t <= qq; t += 256) lm = fmaxf(lm, sq * sk[t]);
    red[tid] = lm; __syncthreads();
    for (int s = 128; s; s >>= 1) { if (tid < s) red[tid] = fmaxf(red[tid], red[tid + s]); __syncthreads(); }
    float M = red[0];
    __syncthreads();
    float ls = 0.f;
    for (int t = tid; t <= qq; t += 256) {
        float e = exp2f(sq * sk[t] - M);
        se[t] = e;
        ls += e;
    }
    red[tid] = ls; __syncthreads();
    for (int s = 128; s; s >>= 1) { if (tid < s) red[tid] += red[tid + s]; __syncthreads(); }
    const float rinv = 1.f / red[0];
    __nv_bfloat16* Prow = P3 + (size_t)qq * 6144;
    for (int t = tid; t < 2048; t += 256) {
        float p = (t <= qq) ? se[t] * rinv : 0.f;
        __nv_bfloat16 hi = __float2bfloat16(p);
        __nv_bfloat16 lo = __float2bfloat16(p - __bfloat162float(hi));
        const int g = t >> 6, j = t & 63;
        __nv_bfloat16* base = Prow + g * 192;
        base[j] = hi;
        base[64 + j] = lo;
        base[128 + j] = hi;
    }
}

// ---------------- r[h,t] ----------------------------------------------
__global__ void kr(const float* __restrict__ x, const float* __restrict__ wr,
                   float* __restrict__ r) {
    const int h = blockIdx.y;
    const int t = blockIdx.x * 128 + threadIdx.x;
    const float* wp = wr + (size_t)h * EE * TT + t;
    const float* xp = x + (size_t)t * EE;
    float acc = 0.f;
#pragma unroll 8
    for (int e = 0; e < EE; e++) acc += xp[e] * wp[(size_t)e * TT];
    r[h * TT + t] = acc;
}

// ---------------- scores[t] = ||echo[t]||^2 / 32 ----------------------
__global__ void kscores2(const float* __restrict__ echo, float* __restrict__ sc) {
    const int t = blockIdx.x * 8 + (threadIdx.x >> 5);
    const int lane = threadIdx.x & 31;
    const float* ep = echo + (size_t)t * EE;
    float a = 0.f;
#pragma unroll 4
    for (int e = lane * 4; e < EE; e += 128) {
        float4 v = *(const float4*)(ep + e);
        a += v.x * v.x + v.y * v.y + v.z * v.z + v.w * v.w;
    }
#pragma unroll
    for (int o = 16; o > 0; o >>= 1) a += __shfl_xor_sync(0xffffffffu, a, o);
    if (lane == 0) sc[t] = a * (1.f / 32.f);
}

// ---------------- gated combine -> split bf16 (A pattern) -------------
__global__ void kcombine3(const float* __restrict__ o1, const float* __restrict__ o2,
                          const float* __restrict__ o3, const float* __restrict__ gate,
                          __nv_bfloat16* __restrict__ comb3) {
    const int idx = blockIdx.x * 256 + threadIdx.x;
    const int c = idx & (HD - 1);
    const int h = c >> 6;
    float g0 = gate[h * 3 + 0], g1 = gate[h * 3 + 1], g2 = gate[h * 3 + 2];
    float mx = fmaxf(g0, fmaxf(g1, g2));
    float e0 = __expf(g0 - mx), e1 = __expf(g1 - mx), e2 = __expf(g2 - mx);
    float inv = 1.f / (e0 + e1 + e2);
    float val = (e0 * o1[idx] + e1 * o2[idx] + e2 * o3[idx]) * inv;
    __nv_bfloat16 hi = __float2bfloat16(val);
    __nv_bfloat16 lo = __float2bfloat16(val - __bfloat162float(hi));
    const int m = idx >> 10, k = idx & 1023;
    __nv_bfloat16* row = comb3 + (size_t)m * 3072;
    row[k] = hi;
    row[1024 + k] = lo;
    row[2048 + k] = hi;
}

// ---------------- launch: multi-stream fork/join graph -----------------
extern "C" void kernel_launch(void* const* d_in, const int* in_sizes, int n_in,
                              void* d_out, int out_size) {
    const float* x    = (const float*)d_in[0];
    const float* wq   = (const float*)d_in[1];
    const float* wk   = (const float*)d_in[2];
    const float* wv   = (const float*)d_in[3];
    const float* wr   = (const float*)d_in[4];
    const float* wvr  = (const float*)d_in[5];
    const float* wj   = (const float*)d_in[6];
    const float* gate = (const float*)d_in[7];
    const float* wo   = (const float*)d_in[8];
    float* out = (float*)d_out;

    float *q, *k, *v, *rv, *echo, *r, *sc, *o1, *o2, *o3;
    __nv_bfloat16 *x3, *w6, *echoT3, *P3, *comb3;
    cudaGetSymbolAddress((void**)&q, g_q);
    cudaGetSymbolAddress((void**)&k, g_k);
    cudaGetSymbolAddress((void**)&v, g_v);
    cudaGetSymbolAddress((void**)&rv, g_rv);
    cudaGetSymbolAddress((void**)&echo, g_echo);
    cudaGetSymbolAddress((void**)&r, g_r);
    cudaGetSymbolAddress((void**)&sc, g_sc);
    cudaGetSymbolAddress((void**)&o1, g_o1);
    cudaGetSymbolAddress((void**)&o2, g_o2);
    cudaGetSymbolAddress((void**)&o3, g_o3);
    cudaGetSymbolAddress((void**)&x3, g_x3);
    cudaGetSymbolAddress((void**)&w6, g_w6);
    cudaGetSymbolAddress((void**)&echoT3, g_echoT3);
    cudaGetSymbolAddress((void**)&P3, g_P3);
    cudaGetSymbolAddress((void**)&comb3, g_comb3);

    static cudaStream_t sB = nullptr, sC = nullptr;
    static cudaEvent_t evFork, evProj, evO1, evO2, evT;
    if (!sB) {
        cudaStreamCreateWithFlags(&sB, cudaStreamNonBlocking);
        cudaStreamCreateWithFlags(&sC, cudaStreamNonBlocking);
        cudaEventCreateWithFlags(&evFork, cudaEventDisableTiming);
        cudaEventCreateWithFlags(&evProj, cudaEventDisableTiming);
        cudaEventCreateWithFlags(&evO1, cudaEventDisableTiming);
        cudaEventCreateWithFlags(&evO2, cudaEventDisableTiming);
        cudaEventCreateWithFlags(&evT, cudaEventDisableTiming);
        cudaFuncSetAttribute(hmma_gemm<false>, cudaFuncAttributeMaxDynamicSharedMemorySize, HMMA_SMEM);
        cudaFuncSetAttribute(hmma_gemm<true>, cudaFuncAttributeMaxDynamicSharedMemorySize, HMMA_SMEM);
        cudaFuncSetAttribute(hmma_gemm5, cudaFuncAttributeMaxDynamicSharedMemorySize, HMMA_SMEM);
        cudaFuncSetAttribute(flash_hmma, cudaFuncAttributeMaxDynamicSharedMemorySize, FL_SMEM);
    }

    dim3 mgrid(8, 16);
    const int X = 2048 * 1024 / 256;

    // fork: stream C starts kr immediately (reads only inputs)
    cudaEventRecord(evFork, 0);
    cudaStreamWaitEvent(sC, evFork, 0);
    kr<<<dim3(16, 16), 128, 0, sC>>>(x, wr, r);

    // main: conversions + batched projection
    Src6 src{{wq, wk, wv, wvr, wj, wo}};
    conv3w6<<<dim3(4096, 6), 256>>>(src, w6);
    conv3<true><<<X, 256>>>(x, x3, 1024);
    Out5 outs{{q, k, v, rv, echo}};
    hmma_gemm5<<<dim3(40, 16), 256, HMMA_SMEM>>>(x3, w6, outs, 3072);
    cudaEventRecord(evProj, 0);

    // stream B: echo transpose-split, then flash attention
    cudaStreamWaitEvent(sB, evProj, 0);
    conv3Tg<<<dim3(64, 32), 256, 0, sB>>>(echo, echoT3, 2048, 1024);
    cudaEventRecord(evT, sB);
    flash_hmma<<<dim3(32, 16), 128, FL_SMEM, sB>>>(q, k, v, o1);
    cudaEventRecord(evO1, sB);

    // stream C: krrp (needs rv + r)
    cudaStreamWaitEvent(sC, evProj, 0);
    krrp<<<16, 256, 0, sC>>>(r, rv, o2);
    cudaEventRecord(evO2, sC);

    // main: janus chain (scores = ||echo||^2/32)
    kscores2<<<TT / 8, 256>>>(echo, sc);
    kjp3<<<TT, 256>>>(sc, P3);
    cudaStreamWaitEvent(0, evT, 0);
    hmma_gemm<true><<<mgrid, 256, HMMA_SMEM>>>(P3, echoT3, o3, 6144);

    // join + combine + output projection
    cudaStreamWaitEvent(0, evO1, 0);
    cudaStreamWaitEvent(0, evO2, 0);
    kcombine3<<<(TT * HD) / 256, 256>>>(o1, o2, o3, gate, comb3);
    hmma_gemm<false><<<mgrid, 256, HMMA_SMEM>>>(comb3, w6 + (size_t)5 * 1024 * 3072, out, 3072);
}

// round 11
// speedup vs baseline: 5.8672x; 1.0812x over previous
#include <cuda_runtime.h>
#include <cuda_bf16.h>
#include <cstdint>

#define TT 2048
#define EE 1024
#define HH 16
#define DD 64
#define HD 1024
#define LOG2E 1.4426950408889634f

// ---------------- fp32 scratch ----------------
__device__ __align__(16) float g_q[TT * HD];
__device__ __align__(16) float g_k[TT * HD];
__device__ __align__(16) float g_v[TT * HD];
__device__ __align__(16) float g_rv[TT * HD];
__device__ __align__(16) float g_echo[TT * EE];
__device__ __align__(16) float g_r[HH * TT];
__device__ __align__(16) float g_sc[TT];
__device__ __align__(16) float g_o1[TT * HD];
__device__ __align__(16) float g_o2[TT * HD];
__device__ __align__(16) float g_o3a[TT * EE];
__device__ __align__(16) float g_o3b[TT * EE];
__device__ __align__(16) float g_f0[TT * EE];
__device__ __align__(16) float g_f1[TT * EE];

// ---------------- bf16 triple-split scratch ----------------
__device__ __align__(16) __nv_bfloat16 g_x3[TT * 3072];
__device__ __align__(16) __nv_bfloat16 g_w6[6144 * 3072];
__device__ __align__(16) __nv_bfloat16 g_echoT3[1024 * 6144];
__device__ __align__(16) __nv_bfloat16 g_P3[TT * 6144];
__device__ __align__(16) __nv_bfloat16 g_comb3[TT * 3072];

struct Src6 { const float* s[6]; };
struct Out5 { float* p[5]; };

// ============================ PTX helpers ============================
__device__ __forceinline__ uint32_t smem_u32(const void* p) {
    uint32_t a;
    asm("{ .reg .u64 t; cvta.to.shared.u64 t, %1; cvt.u32.u64 %0, t; }" : "=r"(a) : "l"(p));
    return a;
}
__device__ __forceinline__ void cp_async16(uint32_t s, const void* g) {
    asm volatile("cp.async.cg.shared.global [%0], [%1], 16;" :: "r"(s), "l"(g));
}
__device__ __forceinline__ void cp_commit() { asm volatile("cp.async.commit_group;"); }
template<int N> __device__ __forceinline__ void cp_wait() {
    asm volatile("cp.async.wait_group %0;" :: "n"(N) : "memory");
}
__device__ __forceinline__ void ldmx4(uint32_t& r0, uint32_t& r1, uint32_t& r2, uint32_t& r3,
                                      uint32_t addr) {
    asm volatile("ldmatrix.sync.aligned.m8n8.x4.shared.b16 {%0,%1,%2,%3}, [%4];"
                 : "=r"(r0), "=r"(r1), "=r"(r2), "=r"(r3) : "r"(addr));
}
__device__ __forceinline__ void mma_bf16(float* d, const uint32_t* a, const uint32_t* b) {
    asm volatile("mma.sync.aligned.m16n8k16.row.col.f32.bf16.bf16.f32 "
                 "{%0,%1,%2,%3}, {%4,%5,%6,%7}, {%8,%9}, {%0,%1,%2,%3};"
                 : "+f"(d[0]), "+f"(d[1]), "+f"(d[2]), "+f"(d[3])
                 : "r"(a[0]), "r"(a[1]), "r"(a[2]), "r"(a[3]), "r"(b[0]), "r"(b[1]));
}
__device__ __forceinline__ uint32_t pack2(__nv_bfloat16 a, __nv_bfloat16 b) {
    __nv_bfloat162 t(a, b);
    return *reinterpret_cast<uint32_t*>(&t);
}

// BK=64, 2-stage: rows padded to 72 elements (144B) -> ldsm conflict-free
#define HROW 144
#define HOPER (128 * HROW)
#define HSTAGE (2 * HOPER)
#define HMMA_SMEM (2 * HSTAGE)

// =====================================================================
// Shared HMMA mainloop body (BK=64, 2-stage cp.async), k-range [kbeg, kbeg+klen)
// =====================================================================
__device__ __forceinline__ void hmma_body(const __nv_bfloat16* __restrict__ A,
                                          const __nv_bfloat16* __restrict__ B,
                                          float acc[2][8][4],
                                          int m0, int n0, int K3,
                                          int kbeg, int klen,
                                          __nv_bfloat16* sm) {
    const int tid = threadIdx.x;
    const int nchunk = klen >> 6;
    const int warp = tid >> 5, lane = tid & 31;
    const int wm = warp & 3, wn = warp >> 2;
    const uint32_t smb = smem_u32(sm);

    auto load_stage = [&](int cc, int s) {
        const uint32_t ab = smb + s * HSTAGE;
        const uint32_t bb = ab + HOPER;
        const int k0 = kbeg + cc * 64;
#pragma unroll
        for (int i = 0; i < 4; i++) {
            int idx = tid + i * 256;
            int row = idx >> 3, cg = idx & 7;
            cp_async16(ab + row * HROW + cg * 16, A + (size_t)(m0 + row) * K3 + k0 + cg * 8);
            cp_async16(bb + row * HROW + cg * 16, B + (size_t)(n0 + row) * K3 + k0 + cg * 8);
        }
        cp_commit();
    };

    load_stage(0, 0);
    load_stage(1, 1);

    const int lrow = lane & 15;
    const int lcol = (lane >> 4) << 3;

    for (int c = 0; c < nchunk; c++) {
        cp_wait<1>();
        __syncthreads();
        const uint32_t ab = smb + (c & 1) * HSTAGE;
        const uint32_t bb = ab + HOPER;
#pragma unroll
        for (int ks = 0; ks < 4; ks++) {
            const uint32_t coff = (ks * 16 + lcol) * 2;
            uint32_t a[2][4], b[8][2];
#pragma unroll
            for (int mt = 0; mt < 2; mt++)
                ldmx4(a[mt][0], a[mt][1], a[mt][2], a[mt][3],
                      ab + (uint32_t)(wm * 32 + mt * 16 + lrow) * HROW + coff);
#pragma unroll
            for (int bp = 0; bp < 4; bp++) {
                uint32_t r0, r1, r2, r3;
                ldmx4(r0, r1, r2, r3,
                      bb + (uint32_t)(wn * 64 + bp * 16 + lrow) * HROW + coff);
                b[bp * 2][0] = r0; b[bp * 2][1] = r2;
                b[bp * 2 + 1][0] = r1; b[bp * 2 + 1][1] = r3;
            }
#pragma unroll
            for (int mt = 0; mt < 2; mt++)
#pragma unroll
                for (int nt = 0; nt < 8; nt++) mma_bf16(acc[mt][nt], a[mt], b[nt]);
        }
        __syncthreads();
        if (c + 2 < nchunk) load_stage(c + 2, c & 1);
    }
}

__device__ __forceinline__ void hmma_epi(float acc[2][8][4], float* C, int m0, int ncol0) {
    const int lane = threadIdx.x & 31, warp = threadIdx.x >> 5;
    const int wm = warp & 3, wn = warp >> 2;
    const int erow = lane >> 2, ecol = (lane & 3) * 2;
#pragma unroll
    for (int mt = 0; mt < 2; mt++) {
        const int r0 = m0 + wm * 32 + mt * 16 + erow;
#pragma unroll
        for (int nt = 0; nt < 8; nt++) {
            const int cc = ncol0 + wn * 64 + nt * 8 + ecol;
            *(float2*)&C[(size_t)r0 * 1024 + cc] = make_float2(acc[mt][nt][0], acc[mt][nt][1]);
            *(float2*)&C[(size_t)(r0 + 8) * 1024 + cc] = make_float2(acc[mt][nt][2], acc[mt][nt][3]);
        }
    }
}

// split-K (z in {0,1}) GEMM; CAUSAL uses grouped-192 layout k-skip
template<bool CAUSAL>
__global__ void __launch_bounds__(256, 2) hmma_gemmz(const __nv_bfloat16* __restrict__ A,
                                                     const __nv_bfloat16* __restrict__ B,
                                                     float* __restrict__ C0,
                                                     float* __restrict__ C1, int K3) {
    extern __shared__ __nv_bfloat16 sm[];
    float acc[2][8][4];
#pragma unroll
    for (int i = 0; i < 2; i++)
#pragma unroll
        for (int j = 0; j < 8; j++)
#pragma unroll
            for (int t = 0; t < 4; t++) acc[i][j][t] = 0.f;
    const int m0 = blockIdx.y * 128, n0 = blockIdx.x * 128;
    const int kc = CAUSAL ? ((m0 + 128) * 3 < K3 ? (m0 + 128) * 3 : K3) : K3;
    const int half = kc >> 1;   // multiple of 64 (kc is 384k or 3072)
    hmma_body(A, B, acc, m0, n0, K3, blockIdx.z * half, half, sm);
    hmma_epi(acc, blockIdx.z ? C1 : C0, m0, n0);
}

__global__ void __launch_bounds__(256, 2) hmma_gemm5(const __nv_bfloat16* __restrict__ A,
                                                     const __nv_bfloat16* __restrict__ B,
                                                     Out5 outs, int K3) {
    extern __shared__ __nv_bfloat16 sm[];
    float acc[2][8][4];
#pragma unroll
    for (int i = 0; i < 2; i++)
#pragma unroll
        for (int j = 0; j < 8; j++)
#pragma unroll
            for (int t = 0; t < 4; t++) acc[i][j][t] = 0.f;
    const int m0 = blockIdx.y * 128, n0 = blockIdx.x * 128;
    hmma_body(A, B, acc, m0, n0, K3, 0, K3, sm);
    hmma_epi(acc, outs.p[blockIdx.x >> 3], m0, (blockIdx.x & 7) * 128);
}

// =====================================================================
// branch 1: fused HMMA flash attention, Q tile = 128 rows, 256 threads
// =====================================================================
#define FL2_SMEM ((128 + 64 + 64) * 200 * 2)   // 102400 B

__global__ void __launch_bounds__(256) flash_hmma2(const float* __restrict__ q,
                                                   const float* __restrict__ k,
                                                   const float* __restrict__ v,
                                                   float* __restrict__ out) {
    extern __shared__ __nv_bfloat16 fsm[];
    const int h = blockIdx.y, m0 = blockIdx.x * 128;
    const int tid = threadIdx.x, warp = tid >> 5, lane = tid & 31;
    const uint32_t smb = smem_u32(fsm);
    const uint32_t Qb = smb;                       // 128 rows x 200
    const uint32_t Kb = smb + 128 * 400;           // 64 rows x 200
    const uint32_t Vb = Kb + 64 * 400;             // 64 d-cols x 200
    const int lrow = lane & 15, lcol = (lane >> 4) << 3;
    const float QSCALE = 0.125f * LOG2E;

    // load+split Q ([hi, lo, hi] over d, scale folded)
    for (int idx = tid; idx < 8192; idx += 256) {
        int r = idx >> 6, d = idx & 63;
        float val = q[(size_t)(m0 + r) * HD + h * 64 + d] * QSCALE;
        __nv_bfloat16 hi = __float2bfloat16(val);
        __nv_bfloat16 lo = __float2bfloat16(val - __bfloat162float(hi));
        __nv_bfloat16* Qr = fsm + r * 200;
        Qr[d] = hi; Qr[64 + d] = lo; Qr[128 + d] = hi;
    }

    float m_lo = -1e30f, m_hi = -1e30f, l_lo = 0.f, l_hi = 0.f;
    float O[8][4];
#pragma unroll
    for (int nt = 0; nt < 8; nt++)
#pragma unroll
        for (int t = 0; t < 4; t++) O[nt][t] = 0.f;

    for (int n0 = 0; n0 <= m0 + 64; n0 += 64) {
        __syncthreads();
        for (int idx = tid; idx < 4096; idx += 256) {
            int j = idx >> 6, d = idx & 63;
            float kv = k[(size_t)(n0 + j) * HD + h * 64 + d];
            __nv_bfloat16 khi = __float2bfloat16(kv);
            __nv_bfloat16 klo = __float2bfloat16(kv - __bfloat162float(khi));
            __nv_bfloat16* Kr = fsm + 128 * 200 + j * 200;
            Kr[d] = khi; Kr[64 + d] = khi; Kr[128 + d] = klo;
            float vv = v[(size_t)(n0 + j) * HD + h * 64 + d];
            __nv_bfloat16 vhi = __float2bfloat16(vv);
            __nv_bfloat16 vlo = __float2bfloat16(vv - __bfloat162float(vhi));
            __nv_bfloat16* Vc = fsm + (128 + 64) * 200 + d * 200;
            Vc[j] = vhi; Vc[64 + j] = vhi; Vc[128 + j] = vlo;
        }
        __syncthreads();

        float s[8][4];
#pragma unroll
        for (int nt = 0; nt < 8; nt++)
#pragma unroll
            for (int t = 0; t < 4; t++) s[nt][t] = 0.f;
#pragma unroll
        for (int ks = 0; ks < 12; ks++) {
            const uint32_t coff = (ks * 16 + lcol) * 2;
            uint32_t a[4], b[8][2];
            ldmx4(a[0], a[1], a[2], a[3], Qb + (uint32_t)(warp * 16 + lrow) * 400 + coff);
#pragma unroll
            for (int bp = 0; bp < 4; bp++) {
                uint32_t r0, r1, r2, r3;
                ldmx4(r0, r1, r2, r3, Kb + (uint32_t)(bp * 16 + lrow) * 400 + coff);
                b[bp * 2][0] = r0; b[bp * 2][1] = r2;
                b[bp * 2 + 1][0] = r1; b[bp * 2 + 1][1] = r3;
            }
#pragma unroll
            for (int nt = 0; nt < 8; nt++) mma_bf16(s[nt], a, b[nt]);
        }

        // causal mask: only needed once keys can exceed rows
        if (n0 >= m0) {
            const int rl = m0 + warp * 16 + (lane >> 2);
            const int cb = n0 + (lane & 3) * 2;
#pragma unroll
            for (int nt = 0; nt < 8; nt++) {
                int c0 = cb + nt * 8, c1 = c0 + 1;
                if (c0 > rl) s[nt][0] = -1e30f;
                if (c1 > rl) s[nt][1] = -1e30f;
                if (c0 > rl + 8) s[nt][2] = -1e30f;
                if (c1 > rl + 8) s[nt][3] = -1e30f;
            }
        }

        float rmx_lo = -1e30f, rmx_hi = -1e30f;
#pragma unroll
        for (int nt = 0; nt < 8; nt++) {
            rmx_lo = fmaxf(rmx_lo, fmaxf(s[nt][0], s[nt][1]));
            rmx_hi = fmaxf(rmx_hi, fmaxf(s[nt][2], s[nt][3]));
        }
#pragma unroll
        for (int o = 1; o < 4; o <<= 1) {
            rmx_lo = fmaxf(rmx_lo, __shfl_xor_sync(0xffffffffu, rmx_lo, o));
            rmx_hi = fmaxf(rmx_hi, __shfl_xor_sync(0xffffffffu, rmx_hi, o));
        }
        float mn_lo = fmaxf(m_lo, rmx_lo), mn_hi = fmaxf(m_hi, rmx_hi);
        float corr_lo = exp2f(m_lo - mn_lo), corr_hi = exp2f(m_hi - mn_hi);
        m_lo = mn_lo; m_hi = mn_hi;
        float rs_lo = 0.f, rs_hi = 0.f;
#pragma unroll
        for (int nt = 0; nt < 8; nt++) {
            s[nt][0] = exp2f(s[nt][0] - mn_lo); rs_lo += s[nt][0];
            s[nt][1] = exp2f(s[nt][1] - mn_lo); rs_lo += s[nt][1];
            s[nt][2] = exp2f(s[nt][2] - mn_hi); rs_hi += s[nt][2];
            s[nt][3] = exp2f(s[nt][3] - mn_hi); rs_hi += s[nt][3];
        }
#pragma unroll
        for (int o = 1; o < 4; o <<= 1) {
            rs_lo += __shfl_xor_sync(0xffffffffu, rs_lo, o);
            rs_hi += __shfl_xor_sync(0xffffffffu, rs_hi, o);
        }
        l_lo = l_lo * corr_lo + rs_lo;
        l_hi = l_hi * corr_hi + rs_hi;
#pragma unroll
        for (int nt = 0; nt < 8; nt++) {
            O[nt][0] *= corr_lo; O[nt][1] *= corr_lo;
            O[nt][2] *= corr_hi; O[nt][3] *= corr_hi;
        }

        uint32_t phi[4][4], plo[4][4];
#pragma unroll
        for (int kk = 0; kk < 4; kk++) {
            const int n0t = 2 * kk, n1t = 2 * kk + 1;
            __nv_bfloat16 h00 = __float2bfloat16(s[n0t][0]);
            __nv_bfloat16 h01 = __float2bfloat16(s[n0t][1]);
            __nv_bfloat16 h02 = __float2bfloat16(s[n0t][2]);
            __nv_bfloat16 h03 = __float2bfloat16(s[n0t][3]);
            __nv_bfloat16 h10 = __float2bfloat16(s[n1t][0]);
            __nv_bfloat16 h11 = __float2bfloat16(s[n1t][1]);
            __nv_bfloat16 h12 = __float2bfloat16(s[n1t][2]);
            __nv_bfloat16 h13 = __float2bfloat16(s[n1t][3]);
            phi[kk][0] = pack2(h00, h01);
            phi[kk][1] = pack2(h02, h03);
            phi[kk][2] = pack2(h10, h11);
            phi[kk][3] = pack2(h12, h13);
            plo[kk][0] = pack2(__float2bfloat16(s[n0t][0] - __bfloat162float(h00)),
                               __float2bfloat16(s[n0t][1] - __bfloat162float(h01)));
            plo[kk][1] = pack2(__float2bfloat16(s[n0t][2] - __bfloat162float(h02)),
                               __float2bfloat16(s[n0t][3] - __bfloat162float(h03)));
            plo[kk][2] = pack2(__float2bfloat16(s[n1t][0] - __bfloat162float(h10)),
                               __float2bfloat16(s[n1t][1] - __bfloat162float(h11)));
            plo[kk][3] = pack2(__float2bfloat16(s[n1t][2] - __bfloat162float(h12)),
                               __float2bfloat16(s[n1t][3] - __bfloat162float(h13)));
        }

#pragma unroll
        for (int ks = 0; ks < 12; ks++) {
            const uint32_t* a = (ks < 4) ? phi[ks] : (ks < 8) ? plo[ks - 4] : phi[ks - 8];
            const uint32_t coff = (ks * 16 + lcol) * 2;
            uint32_t b[8][2];
#pragma unroll
            for (int bp = 0; bp < 4; bp++) {
                uint32_t r0, r1, r2, r3;
                ldmx4(r0, r1, r2, r3, Vb + (uint32_t)(bp * 16 + lrow) * 400 + coff);
                b[bp * 2][0] = r0; b[bp * 2][1] = r2;
                b[bp * 2 + 1][0] = r1; b[bp * 2 + 1][1] = r3;
            }
#pragma unroll
            for (int nt = 0; nt < 8; nt++) mma_bf16(O[nt], a, b[nt]);
        }
    }

    const float inv_lo = 1.f / l_lo, inv_hi = 1.f / l_hi;
    const int rl = m0 + warp * 16 + (lane >> 2);
#pragma unroll
    for (int nt = 0; nt < 8; nt++) {
        const int col = h * 64 + nt * 8 + (lane & 3) * 2;
        *(float2*)&out[(size_t)rl * HD + col] = make_float2(O[nt][0] * inv_lo, O[nt][1] * inv_lo);
        *(float2*)&out[(size_t)(rl + 8) * HD + col] = make_float2(O[nt][2] * inv_hi, O[nt][3] * inv_hi);
    }
}

// =====================================================================
// conversions
// =====================================================================
__global__ void conv3w6(Src6 src, __nv_bfloat16* __restrict__ D) {
    const int w = blockIdx.y;
    const int idx = blockIdx.x * 256 + threadIdx.x;
    const int m = idx >> 10, k = idx & 1023;
    float x = src.s[w][idx];
    __nv_bfloat16 hi = __float2bfloat16(x);
    __nv_bfloat16 lo = __float2bfloat16(x - __bfloat162float(hi));
    __nv_bfloat16* row = D + (size_t)(w * 1024 + m) * 3072;
    row[k] = hi;
    row[1024 + k] = hi;
    row[2048 + k] = lo;
}

template<bool APAT>
__global__ void conv3(const float* __restrict__ S, __nv_bfloat16* __restrict__ D, int K) {
    const int idx = blockIdx.x * 256 + threadIdx.x;
    const int m = idx / K, k = idx - m * K;
    float x = S[idx];
    __nv_bfloat16 hi = __float2bfloat16(x);
    __nv_bfloat16 lo = __float2bfloat16(x - __bfloat162float(hi));
    const size_t ro = (size_t)m * 3 * K;
    D[ro + k] = hi;
    D[ro + K + k] = APAT ? lo : hi;
    D[ro + 2 * K + k] = APAT ? hi : lo;
}

__global__ void conv3Tg(const float* __restrict__ S, __nv_bfloat16* __restrict__ D,
                        int K, int N) {
    __shared__ float t[32][33];
    const int k0 = blockIdx.x * 32, n0 = blockIdx.y * 32;
    const int tx = threadIdx.x & 31, ty = threadIdx.x >> 5;
    for (int i = ty; i < 32; i += 8) t[i][tx] = S[(size_t)(k0 + i) * N + n0 + tx];
    __syncthreads();
    const int K3 = 3 * K;
    for (int i = ty; i < 32; i += 8) {
        const int n = n0 + i, k = k0 + tx;
        const int g = k >> 6, j = k & 63;
        float x = t[tx][i];
        __nv_bfloat16 hi = __float2bfloat16(x);
        __nv_bfloat16 lo = __float2bfloat16(x - __bfloat162float(hi));
        __nv_bfloat16* base = D + (size_t)n * K3 + g * 192;
        base[j] = hi;
        base[64 + j] = hi;
        base[128 + j] = lo;
    }
}

// ---------------- branch 2: two-pass blocked scan ---------------------
__global__ void __launch_bounds__(256) krrp(const float* __restrict__ r,
                                            const float* __restrict__ rv,
                                            float* __restrict__ out) {
    __shared__ float w[2048];
    __shared__ float rl[2048];
    __shared__ float red[256];
    __shared__ float Sg[4][64];
    const int h = blockIdx.x, tid = threadIdx.x;
    const float Cc = 0.125f * LOG2E;
    float vloc[8], lm = -1e30f;
#pragma unroll
    for (int i = 0; i < 8; i++) {
        float vv = r[h * 2048 + tid * 8 + i] * Cc;
        vloc[i] = vv;
        lm = fmaxf(lm, vv);
    }
    red[tid] = lm; __syncthreads();
    for (int s = 128; s; s >>= 1) { if (tid < s) red[tid] = fmaxf(red[tid], red[tid + s]); __syncthreads(); }
    float M = red[0];
    __syncthreads();
    float run = 0.f, pre[8];
#pragma unroll
    for (int i = 0; i < 8; i++) {
        float e = exp2f(vloc[i] - M);
        w[tid * 8 + i] = e;
        run += e;
        pre[i] = run;
    }
    red[tid] = run; __syncthreads();
    for (int s = 1; s < 256; s <<= 1) {
        float t = (tid >= s) ? red[tid - s] : 0.f;
        __syncthreads();
        red[tid] += t;
        __syncthreads();
    }
    float excl = red[tid] - run;
#pragma unroll
    for (int i = 0; i < 8; i++) rl[tid * 8 + i] = 1.f / (excl + pre[i]);
    __syncthreads();

    const int g = tid >> 6, d = tid & 63;
    const int t0 = g * 512, t1 = t0 + 512;
    const float* rp = rv + h * 64 + d;
    float s1 = 0.f;
#pragma unroll 4
    for (int t = t0; t < t1; t++) s1 += w[t] * rp[(size_t)t * 1024];
    Sg[g][d] = s1;
    __syncthreads();
    float base = 0.f;
#pragma unroll
    for (int gg = 0; gg < 3; gg++)
        if (gg < g) base += Sg[gg][d];
    float acc = base;
    float* op = out + h * 64 + d;
#pragma unroll 4
    for (int t = t0; t < t1; t++) {
        acc += w[t] * rp[(size_t)t * 1024];
        op[(size_t)t * 1024] = acc * rl[t];
    }
}

// ---------------- branch 3 probabilities -> grouped split bf16 -------
__global__ void __launch_bounds__(256) kjp3(const float* __restrict__ sc,
                                            __nv_bfloat16* __restrict__ P3) {
    __shared__ float sk[2048];
    __shared__ float se[2048];
    __shared__ float red[256];
    const int qq = blockIdx.x, tid = threadIdx.x;
    for (int t = tid; t < 2048; t += 256) sk[t] = sc[t];
    __syncthreads();
    const float sq = sk[qq] * LOG2E;
    float lm = -1e30f;
    for (int t = tid; t <= qq; t += 256) lm = fmaxf(lm, sq * sk[t]);
    red[tid] = lm; __syncthreads();
    for (int s = 128; s; s >>= 1) { if (tid < s) red[tid] = fmaxf(red[tid], red[tid + s]); __syncthreads(); }
    float M = red[0];
    __syncthreads();
    float ls = 0.f;
    for (int t = tid; t <= qq; t += 256) {
        float e = exp2f(sq * sk[t] - M);
        se[t] = e;
        ls += e;
    }
    red[tid] = ls; __syncthreads();
    for (int s = 128; s; s >>= 1) { if (tid < s) red[tid] += red[tid + s]; __syncthreads(); }
    const float rinv = 1.f / red[0];
    __nv_bfloat16* Prow = P3 + (size_t)qq * 6144;
    for (int t = tid; t < 2048; t += 256) {
        float p = (t <= qq) ? se[t] * rinv : 0.f;
        __nv_bfloat16 hi = __float2bfloat16(p);
        __nv_bfloat16 lo = __float2bfloat16(p - __bfloat162float(hi));
        const int g = t >> 6, j = t & 63;
        __nv_bfloat16* base = Prow + g * 192;
        base[j] = hi;
        base[64 + j] = lo;
        base[128 + j] = hi;
    }
}

// ---------------- r[h,t] ----------------------------------------------
__global__ void kr(const float* __restrict__ x, const float* __restrict__ wr,
                   float* __restrict__ r) {
    const int h = blockIdx.y;
    const int t = blockIdx.x * 128 + threadIdx.x;
    const float* wp = wr + (size_t)h * EE * TT + t;
    const float* xp = x + (size_t)t * EE;
    float acc = 0.f;
#pragma unroll 8
    for (int e = 0; e < EE; e++) acc += xp[e] * wp[(size_t)e * TT];
    r[h * TT + t] = acc;
}

// ---------------- scores[t] = ||echo[t]||^2 / 32 ----------------------
__global__ void kscores2(const float* __restrict__ echo, float* __restrict__ sc) {
    const int t = blockIdx.x * 8 + (threadIdx.x >> 5);
    const int lane = threadIdx.x & 31;
    const float* ep = echo + (size_t)t * EE;
    float a = 0.f;
#pragma unroll 4
    for (int e = lane * 4; e < EE; e += 128) {
        float4 v = *(const float4*)(ep + e);
        a += v.x * v.x + v.y * v.y + v.z * v.z + v.w * v.w;
    }
#pragma unroll
    for (int o = 16; o > 0; o >>= 1) a += __shfl_xor_sync(0xffffffffu, a, o);
    if (lane == 0) sc[t] = a * (1.f / 32.f);
}

// ---------------- gated combine (o3 = a + b) -> split bf16 ------------
__global__ void kcombine3(const float* __restrict__ o1, const float* __restrict__ o2,
                          const float* __restrict__ o3a, const float* __restrict__ o3b,
                          const float* __restrict__ gate,
                          __nv_bfloat16* __restrict__ comb3) {
    const int idx = blockIdx.x * 256 + threadIdx.x;
    const int c = idx & (HD - 1);
    const int h = c >> 6;
    float g0 = gate[h * 3 + 0], g1 = gate[h * 3 + 1], g2 = gate[h * 3 + 2];
    float mx = fmaxf(g0, fmaxf(g1, g2));
    float e0 = __expf(g0 - mx), e1 = __expf(g1 - mx), e2 = __expf(g2 - mx);
    float inv = 1.f / (e0 + e1 + e2);
    float val = (e0 * o1[idx] + e1 * o2[idx] + e2 * (o3a[idx] + o3b[idx])) * inv;
    __nv_bfloat16 hi = __float2bfloat16(val);
    __nv_bfloat16 lo = __float2bfloat16(val - __bfloat162float(hi));
    const int m = idx >> 10, k = idx & 1023;
    __nv_bfloat16* row = comb3 + (size_t)m * 3072;
    row[k] = hi;
    row[1024 + k] = lo;
    row[2048 + k] = hi;
}

// ---------------- final add: out = f0 + f1 -----------------------------
__global__ void kadd(const float* __restrict__ a, const float* __restrict__ b,
                     float* __restrict__ out) {
    const int idx = blockIdx.x * 256 + threadIdx.x;
    out[idx] = a[idx] + b[idx];
}

// ---------------- launch: multi-stream fork/join graph -----------------
extern "C" void kernel_launch(void* const* d_in, const int* in_sizes, int n_in,
                              void* d_out, int out_size) {
    const float* x    = (const float*)d_in[0];
    const float* wq   = (const float*)d_in[1];
    const float* wk   = (const float*)d_in[2];
    const float* wv   = (const float*)d_in[3];
    const float* wr   = (const float*)d_in[4];
    const float* wvr  = (const float*)d_in[5];
    const float* wj   = (const float*)d_in[6];
    const float* gate = (const float*)d_in[7];
    const float* wo   = (const float*)d_in[8];
    float* out = (float*)d_out;

    float *q, *k, *v, *rv, *echo, *r, *sc, *o1, *o2, *o3a, *o3b, *f0, *f1;
    __nv_bfloat16 *x3, *w6, *echoT3, *P3, *comb3;
    cudaGetSymbolAddress((void**)&q, g_q);
    cudaGetSymbolAddress((void**)&k, g_k);
    cudaGetSymbolAddress((void**)&v, g_v);
    cudaGetSymbolAddress((void**)&rv, g_rv);
    cudaGetSymbolAddress((void**)&echo, g_echo);
    cudaGetSymbolAddress((void**)&r, g_r);
    cudaGetSymbolAddress((void**)&sc, g_sc);
    cudaGetSymbolAddress((void**)&o1, g_o1);
    cudaGetSymbolAddress((void**)&o2, g_o2);
    cudaGetSymbolAddress((void**)&o3a, g_o3a);
    cudaGetSymbolAddress((void**)&o3b, g_o3b);
    cudaGetSymbolAddress((void**)&f0, g_f0);
    cudaGetSymbolAddress((void**)&f1, g_f1);
    cudaGetSymbolAddress((void**)&x3, g_x3);
    cudaGetSymbolAddress((void**)&w6, g_w6);
    cudaGetSymbolAddress((void**)&echoT3, g_echoT3);
    cudaGetSymbolAddress((void**)&P3, g_P3);
    cudaGetSymbolAddress((void**)&comb3, g_comb3);

    static cudaStream_t sB = nullptr, sC = nullptr;
    static cudaEvent_t evFork, evProj, evO1, evO2, evT;
    if (!sB) {
        cudaStreamCreateWithFlags(&sB, cudaStreamNonBlocking);
        cudaStreamCreateWithFlags(&sC, cudaStreamNonBlocking);
        cudaEventCreateWithFlags(&evFork, cudaEventDisableTiming);
        cudaEventCreateWithFlags(&evProj, cudaEventDisableTiming);
        cudaEventCreateWithFlags(&evO1, cudaEventDisableTiming);
        cudaEventCreateWithFlags(&evO2, cudaEventDisableTiming);
        cudaEventCreateWithFlags(&evT, cudaEventDisableTiming);
        cudaFuncSetAttribute(hmma_gemmz<false>, cudaFuncAttributeMaxDynamicSharedMemorySize, HMMA_SMEM);
        cudaFuncSetAttribute(hmma_gemmz<true>, cudaFuncAttributeMaxDynamicSharedMemorySize, HMMA_SMEM);
        cudaFuncSetAttribute(hmma_gemm5, cudaFuncAttributeMaxDynamicSharedMemorySize, HMMA_SMEM);
        cudaFuncSetAttribute(flash_hmma2, cudaFuncAttributeMaxDynamicSharedMemorySize, FL2_SMEM);
    }

    const int X = 2048 * 1024 / 256;

    // fork: stream C starts kr immediately (reads only inputs)
    cudaEventRecord(evFork, 0);
    cudaStreamWaitEvent(sC, evFork, 0);
    kr<<<dim3(16, 16), 128, 0, sC>>>(x, wr, r);

    // main: conversions + batched projection
    Src6 src{{wq, wk, wv, wvr, wj, wo}};
    conv3w6<<<dim3(4096, 6), 256>>>(src, w6);
    conv3<true><<<X, 256>>>(x, x3, 1024);
    Out5 outs{{q, k, v, rv, echo}};
    hmma_gemm5<<<dim3(40, 16), 256, HMMA_SMEM>>>(x3, w6, outs, 3072);
    cudaEventRecord(evProj, 0);

    // stream B: echo transpose-split, then flash attention (128-row Q tiles)
    cudaStreamWaitEvent(sB, evProj, 0);
    conv3Tg<<<dim3(64, 32), 256, 0, sB>>>(echo, echoT3, 2048, 1024);
    cudaEventRecord(evT, sB);
    flash_hmma2<<<dim3(16, 16), 256, FL2_SMEM, sB>>>(q, k, v, o1);
    cudaEventRecord(evO1, sB);

    // stream C: krrp (needs rv + r)
    cudaStreamWaitEvent(sC, evProj, 0);
    krrp<<<16, 256, 0, sC>>>(r, rv, o2);
    cudaEventRecord(evO2, sC);

    // main: janus chain (scores = ||echo||^2/32), split-K causal GEMM
    kscores2<<<TT / 8, 256>>>(echo, sc);
    kjp3<<<TT, 256>>>(sc, P3);
    cudaStreamWaitEvent(0, evT, 0);
    hmma_gemmz<true><<<dim3(8, 16, 2), 256, HMMA_SMEM>>>(P3, echoT3, o3a, o3b, 6144);

    // join + combine + split-K output projection
    cudaStreamWaitEvent(0, evO1, 0);
    cudaStreamWaitEvent(0, evO2, 0);
    kcombine3<<<(TT * HD) / 256, 256>>>(o1, o2, o3a, o3b, gate, comb3);
    hmma_gemmz<false><<<dim3(8, 16, 2), 256, HMMA_SMEM>>>(comb3, w6 + (size_t)5 * 1024 * 3072,
                                                          f0, f1, 3072);
    kadd<<<(TT * HD) / 256, 256>>>(f0, f1, out);
}